// round 11
// baseline (speedup 1.0000x reference)
#include <cuda_runtime.h>
#include <math.h>

// ---------------- problem constants ----------------
#define Bq  32
#define Dn  10
#define QLn 16
#define DLn 128
#define BD  320
#define Ff  300
#define Hh  256
#define G4  1024
#define Cc  50
#define NFc 50
#define MFc 20
#define NTQ (Bq*QLn)      // 512
#define NTD (BD*DLn)      // 40960

// ---------------- device scratch ----------------
__device__ float g_Xq[NTQ*Ff];
__device__ float g_Xd[(size_t)NTD*Ff];
__device__ float g_xgq[(size_t)NTQ*G4];
__device__ float g_xgd[(size_t)NTD*G4];
__device__ float g_encq[NTQ*Hh];
__device__ float g_encd[(size_t)NTD*Hh];
__device__ float g_pq[NTQ*Cc];
__device__ float g_pdT[(size_t)BD*Cc*DLn];
__device__ float g_s3[(size_t)Bq*NFc*QLn*152 + 16];
__device__ float g_s5[(size_t)Bq*NFc*QLn*252 + 16];
__device__ float g_s7[(size_t)Bq*NFc*QLn*352 + 16];
__device__ float g_f[(size_t)BD*150*QLn*DLn];
__device__ float g_qb[G4];
__device__ float g_db[G4];
__device__ float g_WTq[Ff*G4];     // Wih^T, column-permuted for packed loads
__device__ float g_WTd[Ff*G4];

__device__ __forceinline__ float tha(float x){
    float y; asm("tanh.approx.f32 %0, %1;" : "=f"(y) : "f"(x)); return y;
}
__device__ __forceinline__ float sigf(float x){ return fmaf(tha(0.5f*x), 0.5f, 0.5f); }

__device__ __forceinline__ void mma8(float* c, const unsigned* a, const unsigned* b){
    asm volatile("mma.sync.aligned.m16n8k8.row.col.f32.tf32.tf32.f32 "
        "{%0,%1,%2,%3}, {%4,%5,%6,%7}, {%8,%9}, {%0,%1,%2,%3};"
        : "+f"(c[0]),"+f"(c[1]),"+f"(c[2]),"+f"(c[3])
        : "r"(a[0]),"r"(a[1]),"r"(a[2]),"r"(a[3]), "r"(b[0]),"r"(b[1]));
}
__device__ __forceinline__ unsigned sptr(const void* p){
    return (unsigned)__cvta_generic_to_shared(p);
}
__device__ __forceinline__ void cpa16(unsigned dst, const void* src, bool pred){
    int sz = pred ? 16 : 0;
    asm volatile("cp.async.cg.shared.global [%0], [%1], 16, %2;" :: "r"(dst), "l"(src), "r"(sz));
}
#define CP_COMMIT() asm volatile("cp.async.commit_group;")
#define CP_WAIT0()  asm volatile("cp.async.wait_group 0;")
#define CP_WAIT1()  asm volatile("cp.async.wait_group 1;")
#define CLUSTER_ARRIVE() asm volatile("barrier.cluster.arrive.aligned;" ::: "memory")
#define CLUSTER_WAIT()   asm volatile("barrier.cluster.wait.aligned;" ::: "memory")

// ---------------- bias precombine ----------------
__global__ void bias_sum_k(const float* __restrict__ qb1, const float* __restrict__ qb2,
                           const float* __restrict__ db1, const float* __restrict__ db2)
{
    int t = blockIdx.x*blockDim.x + threadIdx.x;
    if (t < G4){ g_qb[t] = qb1[t]+qb2[t]; g_db[t] = db1[t]+db2[t]; }
}

// ---------------- Wih transpose: smem-tiled, coalesced both sides ----------
// dst[k][np] = src[n][k], np = intra-32 packed permutation of n.
__global__ void wt_k(const float* __restrict__ qW, const float* __restrict__ dW)
{
    __shared__ float t[32][33];
    const float* src = blockIdx.z ? dW : qW;
    float* dst = blockIdx.z ? g_WTd : g_WTq;
    int k0 = blockIdx.x*32, n0 = blockIdx.y*32;
    int tx = threadIdx.x, ty = threadIdx.y;     // block (32,8)
    #pragma unroll
    for (int dy = 0; dy < 32; dy += 8){
        int n = n0 + ty + dy, k = k0 + tx;
        t[ty+dy][tx] = (k < Ff) ? src[(size_t)n*Ff + k] : 0.f;
    }
    __syncthreads();
    #pragma unroll
    for (int dy = 0; dy < 32; dy += 8){
        int k = k0 + ty + dy;
        int n = n0 + tx;
        int np = (n & ~31) | ((n & 7)*4 + ((n >> 3) & 3));
        if (k < Ff) dst[(size_t)k*G4 + np] = t[tx][ty+dy];
    }
}

// ---------------- dual-side 3-stage pipelined tf32 GEMM (!BT only) ----------
// PACKB: B source pre-permuted (WT) -> float4 fragment loads.
struct GS {
    const float* A; const int* idx; const float* Bm; const float* bias;
    float* C; int M; int ldc; int store;   // store 0: C[m*ldc+n]; 1: pdT layout
};
#define GEMM_DSM (6*2560*4)
template<bool GATHER, bool BASYNC, bool PACKB>
__global__ __launch_bounds__(256,2) void gemm_dual(
    GS s1, GS s2, int ysplit, int lda, int ldb, int N, int K)
{
    extern __shared__ float dsm[];
    float* Asm = dsm;            // 3 stages x [128][20]
    float* Bsm = dsm + 3*2560;   // 3 stages x [16][132]
    int tid = threadIdx.x;
    int lane = tid & 31, warp = tid >> 5;
    int wm = warp >> 2, wn = warp & 3;
    bool side2 = ((int)blockIdx.y >= ysplit);
    const float* A_   = side2 ? s2.A    : s1.A;
    const int*   idx_ = side2 ? s2.idx  : s1.idx;
    const float* Bm_  = side2 ? s2.Bm   : s1.Bm;
    const float* bias = side2 ? s2.bias : s1.bias;
    float*       C    = side2 ? s2.C    : s1.C;
    int M    = side2 ? s2.M    : s1.M;
    int ldc  = side2 ? s2.ldc  : s1.ldc;
    int store= side2 ? s2.store: s1.store;
    int by = (int)blockIdx.y - (side2 ? ysplit : 0);
    int m0 = by*128, n0 = blockIdx.x*128;
    int nk = (K + 15) >> 4;
    int r8 = lane>>2, q4 = lane&3;

    int arow = tid >> 1;
    int acp  = (tid & 1) * 8;
    bool mrowok = (m0 + arow) < M;
    const float* Arow;
    { long r = GATHER ? (long)idx_[m0 + (mrowok ? arow : 0)] : (long)(m0 + (mrowok ? arow : 0));
      Arow = A_ + r*(long)lda; }

    int bkr = tid >> 4, bnf = (tid & 15)*8;

    auto issue = [&](int kt, int buf){
        int k0 = kt*16;
        unsigned d = sptr(Asm + buf*2560 + arow*20 + acp);
        cpa16(d,    Arow + k0 + acp,     mrowok && (k0+acp)   < K);
        cpa16(d+16, Arow + k0 + acp + 4, mrowok && (k0+acp+4) < K);
        if (BASYNC){
            const float* src = Bm_ + (size_t)(k0+bkr)*ldb + n0 + bnf;
            unsigned db = sptr(Bsm + buf*2560 + bkr*132 + bnf);
            bool kok = (k0+bkr) < K;
            cpa16(db,    src,   kok && (n0+bnf)   < N);
            cpa16(db+16, src+4, kok && (n0+bnf+4) < N);
        }
        CP_COMMIT();
    };

    float bv[8];
    int nc = (tid&31)*4, kr = tid>>5;
    auto ldgB = [&](int kt){
        int k0 = kt*16;
        #pragma unroll
        for (int h=0;h<2;h++){
            int kk = k0 + kr + h*8;
            #pragma unroll
            for (int j=0;j<4;j++){
                int n = n0 + nc + j;
                bv[h*4+j] = (kk < K && n < N) ? Bm_[(size_t)kk*ldb + n] : 0.f;
            }
        }
    };
    auto stsB = [&](int buf){
        #pragma unroll
        for (int h=0;h<2;h++)
            #pragma unroll
            for (int j=0;j<4;j++) Bsm[buf*2560 + (kr+h*8)*132 + nc+j] = bv[h*4+j];
    };

    float acc[4][4][4] = {};

    issue(0,0);
    if (nk > 1) issue(1,1);
    if (!BASYNC) ldgB(0);

    int buf = 0;
    for (int kt = 0; kt < nk; kt++){
        if (kt >= nk-1) CP_WAIT0(); else CP_WAIT1();
        __syncthreads();
        if (!BASYNC) stsB(buf);
        if (kt+2 < nk) issue(kt+2, buf == 0 ? 2 : buf-1);
        if (!BASYNC){
            if (kt+1 < nk) ldgB(kt+1);
            __syncthreads();
        }
        const float* Ab2 = Asm + buf*2560;
        const float* Bb2 = Bsm + buf*2560;
        #pragma unroll
        for (int kb=0; kb<2; kb++){
            int ko = kb*8;
            unsigned af[4][4], bf[4][2];
            #pragma unroll
            for (int mt=0; mt<4; mt++){
                int rb = wm*64 + mt*16;
                af[mt][0] = __float_as_uint(Ab2[(rb+r8  )*20 + ko+q4  ]);
                af[mt][1] = __float_as_uint(Ab2[(rb+r8+8)*20 + ko+q4  ]);
                af[mt][2] = __float_as_uint(Ab2[(rb+r8  )*20 + ko+q4+4]);
                af[mt][3] = __float_as_uint(Ab2[(rb+r8+8)*20 + ko+q4+4]);
            }
            if (PACKB){
                float4 b0 = *(const float4*)&Bb2[(ko+q4  )*132 + wn*32 + r8*4];
                float4 b1 = *(const float4*)&Bb2[(ko+q4+4)*132 + wn*32 + r8*4];
                bf[0][0]=__float_as_uint(b0.x); bf[1][0]=__float_as_uint(b0.y);
                bf[2][0]=__float_as_uint(b0.z); bf[3][0]=__float_as_uint(b0.w);
                bf[0][1]=__float_as_uint(b1.x); bf[1][1]=__float_as_uint(b1.y);
                bf[2][1]=__float_as_uint(b1.z); bf[3][1]=__float_as_uint(b1.w);
            } else {
                #pragma unroll
                for (int nt=0; nt<4; nt++){
                    int nb = wn*32 + nt*8;
                    bf[nt][0] = __float_as_uint(Bb2[(ko+q4  )*132 + nb+r8]);
                    bf[nt][1] = __float_as_uint(Bb2[(ko+q4+4)*132 + nb+r8]);
                }
            }
            #pragma unroll
            for (int mt=0;mt<4;mt++)
                #pragma unroll
                for (int nt=0;nt<4;nt++)
                    mma8(acc[mt][nt], af[mt], bf[nt]);
        }
        buf = (buf == 2) ? 0 : buf+1;
    }

    #pragma unroll
    for (int mt=0;mt<4;mt++){
        int row = m0 + wm*64 + mt*16 + r8;
        #pragma unroll
        for (int nt=0;nt<4;nt++){
            int col = n0 + wn*32 + nt*8 + q4*2;
            const float* cc = acc[mt][nt];
            #pragma unroll
            for (int j=0;j<2;j++){
                int n = col + j;
                if (n >= N) continue;
                float bb = bias ? bias[n] : 0.f;
                float v0 = cc[j] + bb, v1 = cc[2+j] + bb;
                if (store == 0){
                    if (row < M)   C[(size_t)row*ldc + n] = v0;
                    if (row+8 < M) C[(size_t)(row+8)*ldc + n] = v1;
                } else {
                    int img = row >> 7;
                    C[((size_t)img*Cc + n)*DLn + (row & 127)] = v0;
                    C[((size_t)img*Cc + n)*DLn + ((row+8) & 127)] = v1;
                }
            }
        }
    }
}

// ---------------- persistent LSTM (packed Bs, split-As pipeline) ------------
#define LSTM_BS_W  (256*136)
#define LSTM_AS_W  (32*260)
#define LSTM_XS_W  (32*132)
#define LSTM_SMEM  ((LSTM_BS_W + LSTM_AS_W + LSTM_XS_W)*4)
__global__ __cluster_dims__(8,1,1) __launch_bounds__(256,1) void lstm_persist(
    const float* __restrict__ xgq, const float* __restrict__ Whq, float* __restrict__ encq,
    const float* __restrict__ xgd, const float* __restrict__ Whd, float* __restrict__ encd)
{
    extern __shared__ unsigned smbuf[];
    unsigned* Bs = smbuf;
    float* Bsf = (float*)Bs;
    float* As = (float*)(smbuf + LSTM_BS_W);
    float* xs = As + LSTM_AS_W;
    int tid = threadIdx.x;
    int lane = tid & 31, warp = tid >> 5;
    int r8 = lane >> 2, q4 = lane & 3;
    int wm = warp & 1, wn = warp >> 1;
    int cid = blockIdx.x >> 3, hb = blockIdx.x & 7;
    const float* xg; const float* Whh; float* enc; int T, n0;
    if (cid == 0){ xg = xgq; Whh = Whq; enc = encq; T = QLn; n0 = 0; }
    else        { xg = xgd; Whh = Whd; enc = encd; T = DLn; n0 = (cid-1)*32; }
    int h0 = hb * 32;

    // fill Bs with column permutation: physical p holds logical j
    for (int idx = tid; idx < 128*256; idx += 256){
        int p = idx >> 8, k = idx & 255;
        int p32 = p & 31;
        int j = (p & ~31) | (((p32 & 3) << 3) | (p32 >> 2));   // nt*8 + r8
        int r = ((j & 3) << 8) + h0 + (j >> 2);
        Bs[k*136 + p] = __float_as_uint(Whh[(size_t)r*Hh + k]);
    }

    auto issueXS = [&](int t){
        #pragma unroll
        for (int u = 0; u < 4; u++){
            int ch = tid + 256*u;
            int m  = ch >> 5;
            int g  = (ch >> 3) & 3;
            int o4 = (ch & 7) * 4;
            const float* src = xg + ((size_t)(n0+m)*T + t)*G4 + g*256 + h0 + o4;
            cpa16(sptr(xs + m*132 + g*32 + o4), src, true);
        }
        CP_COMMIT();
    };
    auto issueAS = [&](int t, int ubeg){   // 4 u's = half of k range
        #pragma unroll
        for (int u = ubeg; u < ubeg+4; u++){
            int ch = tid + 256*u;
            int m  = ch & 31;
            int k4 = (ch >> 5) * 4;
            cpa16(sptr(As + m*260 + k4), enc + ((size_t)(n0+m)*T + (t-1))*Hh + k4, true);
        }
        CP_COMMIT();
    };

    issueXS(0);
    float creg[4] = {0.f, 0.f, 0.f, 0.f};
    int rb = wm*16;
    float acc[4][4];

    auto mmahalf = [&](int kbeg){
        #pragma unroll 4
        for (int ko = kbeg; ko < kbeg+128; ko += 8){
            unsigned af[4];
            af[0] = __float_as_uint(As[(rb+r8  )*260 + ko+q4  ]);
            af[1] = __float_as_uint(As[(rb+r8+8)*260 + ko+q4  ]);
            af[2] = __float_as_uint(As[(rb+r8  )*260 + ko+q4+4]);
            af[3] = __float_as_uint(As[(rb+r8+8)*260 + ko+q4+4]);
            float4 b0 = *(const float4*)&Bsf[(ko+q4  )*136 + wn*32 + r8*4];
            float4 b1 = *(const float4*)&Bsf[(ko+q4+4)*136 + wn*32 + r8*4];
            unsigned bf0[2] = {__float_as_uint(b0.x), __float_as_uint(b1.x)};
            unsigned bf1[2] = {__float_as_uint(b0.y), __float_as_uint(b1.y)};
            unsigned bf2[2] = {__float_as_uint(b0.z), __float_as_uint(b1.z)};
            unsigned bf3[2] = {__float_as_uint(b0.w), __float_as_uint(b1.w)};
            mma8(acc[0], af, bf0);
            mma8(acc[1], af, bf1);
            mma8(acc[2], af, bf2);
            mma8(acc[3], af, bf3);
        }
    };

    for (int t = 0; t < T; t++){
        #pragma unroll
        for (int nt = 0; nt < 4; nt++){ acc[nt][0]=0.f; acc[nt][1]=0.f; acc[nt][2]=0.f; acc[nt][3]=0.f; }
        if (t == 0){
            for (int idx = tid; idx < 32*256; idx += 256)
                As[(idx >> 8)*260 + (idx & 255)] = 0.f;
            CP_WAIT0();          // xs(0)
            __syncthreads();
            mmahalf(0); mmahalf(128);
        } else {
            issueAS(t, 0);
            issueAS(t, 4);
            CP_WAIT1();          // xs(t) + AS first half done
            __syncthreads();
            mmahalf(0);
            CP_WAIT0();
            __syncthreads();
            mmahalf(128);
        }

        // shfl epilogue: lane^1 holds the complementary gate pair
        bool odd = (q4 & 1);
        int m  = rb + r8 + (odd ? 8 : 0);
        #pragma unroll
        for (int nt = 0; nt < 4; nt++){
            float a0 = acc[nt][0], a1 = acc[nt][1], a2 = acc[nt][2], a3 = acc[nt][3];
            float e0 = __shfl_xor_sync(0xFFFFFFFFu, a0, 1);
            float e1 = __shfl_xor_sync(0xFFFFFFFFu, a1, 1);
            float e2 = __shfl_xor_sync(0xFFFFFFFFu, a2, 1);
            float e3 = __shfl_xor_sync(0xFFFFFFFFu, a3, 1);
            float g0 = odd ? e2 : a0;
            float g1 = odd ? e3 : a1;
            float g2 = odd ? a2 : e0;
            float g3 = odd ? a3 : e1;
            int hp = wn*8 + nt*2 + (q4 >> 1);
            const float* xr = xs + m*132 + hp;
            float gi = g0 + xr[0];
            float gf = g1 + xr[32];
            float gg = g2 + xr[64];
            float go = g3 + xr[96];
            float cv = sigf(gf)*creg[nt] + sigf(gi)*tha(gg);
            creg[nt] = cv;
            enc[((size_t)(n0+m)*T + t)*Hh + h0 + hp] = sigf(go)*tha(cv);
        }
        __syncthreads();
        if (t+1 < T) issueXS(t+1);
        CLUSTER_ARRIVE();
        CLUSTER_WAIT();
    }
}

// ---------------- conv stage 1 (merged 3 convs via blockIdx.y) ----------------
__global__ void s_k(const float* __restrict__ c1W, const float* __restrict__ c2W,
                    const float* __restrict__ c3W,
                    float* __restrict__ s3, float* __restrict__ s5, float* __restrict__ s7)
{
    int z = blockIdx.y;
    int KW = 3 + 2*z, KP = 152 + 100*z;
    const float* cW = (z==0) ? c1W : (z==1) ? c2W : c3W;
    float* s = (z==0) ? s3 : (z==1) ? s5 : s7;
    long total = (long)Bq*NFc*QLn*KP;
    long i = (long)blockIdx.x*blockDim.x + threadIdx.x;
    if (i >= total) return;
    int kk = (int)(i % KP);
    long r = i / KP;
    int q  = (int)(r % QLn); r /= QLn;
    int o  = (int)(r % NFc);
    int b  = (int)(r / NFc);
    float v = 0.f;
    if (kk < Cc*KW){
        int dd = kk / Cc, c = kk - dd*Cc;
        #pragma unroll
        for (int dq = 0; dq < 3; dq++){
            int qq = q + dq - 1;
            if (qq >= 0 && qq < QLn)
                v += cW[(((size_t)o*51 + c)*3 + dq)*KW + dd] * g_pq[((size_t)b*QLn + qq)*Cc + c];
        }
    }
    s[i] = v;
}

// ---------------- conv stage 2: merged (blockIdx.z), resident-B, 3-stage A ----
#define CONV_DSM ((3*2560 + 50*132)*4)
__global__ __launch_bounds__(256,2) void convgemm_k(
    const float* __restrict__ sA3, const float* __restrict__ sA5, const float* __restrict__ sA7,
    const float* __restrict__ c1W, const float* __restrict__ c1b,
    const float* __restrict__ c2W, const float* __restrict__ c2b,
    const float* __restrict__ c3W, const float* __restrict__ c3b,
    const int* __restrict__ bqtok, const int* __restrict__ bdtok,
    const float* __restrict__ alpha)
{
    int z = blockIdx.z;
    const int KW = 3 + 2*z, KP = 152 + 100*z, PW = KW >> 1, OCB = z*50;
    const int nk = (KP + 15) >> 4;
    const float* sA = (z==0) ? sA3 : (z==1) ? sA5 : sA7;
    const float* cW = (z==0) ? c1W : (z==1) ? c2W : c3W;
    const float* cb = (z==0) ? c1b : (z==1) ? c2b : c3b;
    extern __shared__ float dsm[];
    float* Asm = dsm;              // 3 stages x [128][20]
    float* pdt = dsm + 3*2560;     // [50][132]
    __shared__ float ems[18][136];
    __shared__ float wem[8][21];
    __shared__ int qt[16], dt[128], s_any;
    int tid = threadIdx.x;
    int lane = tid & 31, warp = tid >> 5;
    int wm = warp >> 2, wn = warp & 3;
    int img = blockIdx.y, b = img / Dn;
    int m0 = blockIdx.x*128, obase = m0 >> 4;
    int r8 = lane>>2, q4 = lane&3;

    const float* Pd = &g_pdT[(size_t)img*Cc*DLn];
    int arow = tid >> 1, acp = (tid & 1)*8;
    bool mok = (m0 + arow) < 800;
    const float* Arow = sA + ((size_t)b*800 + (mok ? m0+arow : 0))*KP;

    auto issueA = [&](int kt, int buf){
        int k0 = kt*16;
        unsigned d = sptr(Asm + buf*2560 + arow*20 + acp);
        cpa16(d,    Arow + k0 + acp,     mok && (k0+acp)   < KP);
        cpa16(d+16, Arow + k0 + acp + 4, mok && (k0+acp+4) < KP);
    };

    for (int ch = tid; ch < 1600; ch += 256){
        int row = ch >> 5, off = (ch & 31) * 4;
        cpa16(sptr(pdt + row*132 + off), Pd + row*128 + off, true);
    }
    issueA(0,0); CP_COMMIT();
    issueA(1,1); CP_COMMIT();

    if (tid == 0) s_any = 0;
    if (tid < 16) qt[tid] = bqtok[b*QLn + tid];
    if (tid < 128) dt[tid] = bdtok[(size_t)img*DLn + tid];
    if (tid < 8*3*KW){
        int ol = tid/(3*KW), rr = tid%(3*KW);
        int o = obase + ol;
        wem[ol][rr] = (o < NFc) ? cW[(((size_t)o*51 + 50)*3 + rr/KW)*KW + rr%KW] : 0.f;
    }
    __syncthreads();
    float al = alpha[0];
    for (int e = tid; e < 18*136; e += 256){
        int qi = e/136, dj = e%136;
        int q = qi-1, dl = dj-3;
        float v = 0.f;
        if (q >= 0 && q < QLn && dl >= 0 && dl < DLn && qt[q] == dt[dl]){ v = al; s_any = 1; }
        ems[qi][dj] = v;
    }

    float acc[4][4][4] = {};
    int buf = 0;
    for (int kt = 0; kt < nk; kt++){
        if (kt >= nk-1) CP_WAIT0(); else CP_WAIT1();
        __syncthreads();
        if (kt+2 < nk){ issueA(kt+2, buf == 0 ? 2 : buf-1); CP_COMMIT(); }
        const float* Ab2 = Asm + buf*2560;
        #pragma unroll
        for (int kb=0; kb<2; kb++){
            int ko = kb*8;
            int ka = kt*16 + ko + q4;
            int k2 = ka + 4;
            int dda = ka/Cc, ca = ka - dda*Cc;
            int ddb = k2/Cc, cbb = k2 - ddb*Cc;
            unsigned af[4][4], bf[4][2];
            #pragma unroll
            for (int mt=0; mt<4; mt++){
                int rb = wm*64 + mt*16;
                af[mt][0] = __float_as_uint(Ab2[(rb+r8  )*20 + ko+q4  ]);
                af[mt][1] = __float_as_uint(Ab2[(rb+r8+8)*20 + ko+q4  ]);
                af[mt][2] = __float_as_uint(Ab2[(rb+r8  )*20 + ko+q4+4]);
                af[mt][3] = __float_as_uint(Ab2[(rb+r8+8)*20 + ko+q4+4]);
            }
            #pragma unroll
            for (int nt=0; nt<4; nt++){
                int col = wn*32 + nt*8 + r8;
                int sa = col + dda - PW;
                int sb = col + ddb - PW;
                bf[nt][0] = ((unsigned)sa < 128u) ? __float_as_uint(pdt[ca*132 + sa]) : 0u;
                bf[nt][1] = ((unsigned)sb < 128u) ? __float_as_uint(pdt[cbb*132 + sb]) : 0u;
            }
            #pragma unroll
            for (int mt=0;mt<4;mt++)
                #pragma unroll
                for (int nt=0;nt<4;nt++)
                    mma8(acc[mt][nt], af[mt], bf[nt]);
        }
        buf = (buf == 2) ? 0 : buf+1;
    }

    int any = s_any;
    #pragma unroll
    for (int mt=0;mt<4;mt++){
        int row = m0 + wm*64 + mt*16;
        if (row >= 800) continue;
        int o = row >> 4, ol = o - obase;
        float bias = cb[o];
        #pragma unroll
        for (int rr=0; rr<2; rr++){
            int q = r8 + rr*8;
            #pragma unroll
            for (int nt=0;nt<4;nt++){
                int col = wn*32 + nt*8 + q4*2;
                #pragma unroll
                for (int j=0;j<2;j++){
                    int dl = col + j;
                    float v = acc[mt][nt][rr*2 + j] + bias;
                    if (any){
                        for (int dq = 0; dq < 3; dq++)
                            for (int dd = 0; dd < KW; dd++)
                                v += wem[ol][dq*KW+dd] * ems[q+dq][dl+dd+3-PW];
                    }
                    v = fmaxf(v, 0.f);
                    g_f[(((size_t)img*150 + OCB + o)*QLn + q)*DLn + dl] = v;
                }
            }
        }
    }
}

// ---------------- 1x1 conv + maxpool + linear (tf32 mma) ----------------
#define SCORE_DSM ((3*8*264 + 152*36)*4)
__global__ __launch_bounds__(256,2) void score_k(
    const float* __restrict__ ccW, const float* __restrict__ ccb,
    const float* __restrict__ outW, const float* __restrict__ outb,
    float* __restrict__ out)
{
    extern __shared__ float dsm[];
    float* fs = dsm;               // 3 stages x [8][264]
    float* Ws = dsm + 3*8*264;     // [152][36]: Ws[k*36+m]
    __shared__ float red[32][8];
    __shared__ float part[32];
    int img = blockIdx.x, tid = threadIdx.x;
    int lane = tid & 31, warp = tid >> 5;
    int r8 = lane >> 2, q4 = lane & 3;

    for (int idx = tid; idx < 152*32; idx += 256){
        int m = idx & 31, k = idx >> 5;
        Ws[k*36 + m] = (m < MFc && k < 150) ? ccW[m*150 + k] : 0.f;
    }

    const float* fimg = &g_f[(size_t)img*150*2048];
    auto issue = [&](int kt, int pch, int buf){
        #pragma unroll
        for (int h = 0; h < 2; h++){
            int ch = tid + 256*h;
            int row = ch >> 6, off = (ch & 63)*4;
            int kr = kt*8 + row;
            cpa16(sptr(fs + buf*2112 + row*264 + off),
                  fimg + (size_t)kr*2048 + pch*256 + off, kr < 150);
        }
        CP_COMMIT();
    };

    float bb0 = (r8      < MFc) ? ccb[r8]      : 0.f;
    float bb0b= (r8+8    < MFc) ? ccb[r8+8]    : 0.f;
    float maxv[2][2] = {{-1e30f,-1e30f},{-1e30f,-1e30f}};
    __syncthreads();   // Ws ready

    for (int pch = 0; pch < 8; pch++){
        float acc[2][4][4] = {};
        issue(0, pch, 0);
        issue(1, pch, 1);
        int buf = 0;
        for (int kt = 0; kt < 19; kt++){
            if (kt >= 17) CP_WAIT0(); else CP_WAIT1();
            __syncthreads();
            if (kt+2 < 19) issue(kt+2, pch, buf == 0 ? 2 : buf-1);
            const float* fb2 = fs + buf*2112;
            unsigned af[2][4];
            #pragma unroll
            for (int mt=0; mt<2; mt++){
                int mb = mt*16;
                af[mt][0] = __float_as_uint(Ws[(kt*8+q4  )*36 + mb+r8]);
                af[mt][1] = __float_as_uint(Ws[(kt*8+q4  )*36 + mb+r8+8]);
                af[mt][2] = __float_as_uint(Ws[(kt*8+q4+4)*36 + mb+r8]);
                af[mt][3] = __float_as_uint(Ws[(kt*8+q4+4)*36 + mb+r8+8]);
            }
            #pragma unroll
            for (int nt=0; nt<4; nt++){
                int nb = warp*32 + nt*8;
                unsigned bf[2];
                bf[0] = __float_as_uint(fb2[(q4  )*264 + nb+r8]);
                bf[1] = __float_as_uint(fb2[(q4+4)*264 + nb+r8]);
                #pragma unroll
                for (int mt=0; mt<2; mt++)
                    mma8(acc[mt][nt], af[mt], bf);
            }
            buf = (buf == 2) ? 0 : buf+1;
            __syncthreads();
        }
        #pragma unroll
        for (int mt=0; mt<2; mt++){
            float b0 = (mt==0) ? bb0  : ((16+r8 < MFc) ? ccb[16+r8] : 0.f);
            float b1 = (mt==0) ? bb0b : 0.f;
            #pragma unroll
            for (int nt=0; nt<4; nt++){
                float* cc = acc[mt][nt];
                maxv[mt][0] = fmaxf(maxv[mt][0], fmaxf(cc[0], cc[1]) + b0);
                maxv[mt][1] = fmaxf(maxv[mt][1], fmaxf(cc[2], cc[3]) + b1);
            }
        }
    }
    #pragma unroll
    for (int mt=0; mt<2; mt++)
        #pragma unroll
        for (int h=0; h<2; h++){
            float v = maxv[mt][h];
            v = fmaxf(v, __shfl_xor_sync(0xFFFFFFFFu, v, 1));
            v = fmaxf(v, __shfl_xor_sync(0xFFFFFFFFu, v, 2));
            maxv[mt][h] = v;
        }
    if (q4 == 0){
        #pragma unroll
        for (int mt=0; mt<2; mt++)
            #pragma unroll
            for (int h=0; h<2; h++)
                red[mt*16 + h*8 + r8][warp] = maxv[mt][h];
    }
    __syncthreads();
    if (tid < 32){
        float m = red[tid][0];
        #pragma unroll
        for (int w = 1; w < 8; w++) m = fmaxf(m, red[tid][w]);
        part[tid] = (tid < MFc) ? m * outW[tid] : 0.f;
    }
    __syncthreads();
    if (tid == 0){
        float sc = outb[0];
        #pragma unroll
        for (int mf = 0; mf < MFc; mf++) sc += part[mf];
        out[img] = sc;
    }
}

// ---------------- launch ----------------
extern "C" void kernel_launch(void* const* d_in, const int* in_sizes, int n_in,
                              void* d_out, int out_size)
{
    const int* bqtok = nullptr; const int* bdtok = nullptr;
    for (int i = 0; i < 4; i++){
        if (in_sizes[i] == NTQ)      bqtok = (const int*)d_in[i];
        else if (in_sizes[i] == NTD) bdtok = (const int*)d_in[i];
    }
    const float* emb    = (const float*)d_in[4];
    const float* projW  = (const float*)d_in[5];
    const float* projb  = (const float*)d_in[6];
    const float* qWih   = (const float*)d_in[7];
    const float* qWhh   = (const float*)d_in[8];
    const float* qbih   = (const float*)d_in[9];
    const float* qbhh   = (const float*)d_in[10];
    const float* dWih   = (const float*)d_in[11];
    const float* dWhh   = (const float*)d_in[12];
    const float* dbih   = (const float*)d_in[13];
    const float* dbhh   = (const float*)d_in[14];
    const float* qpW    = (const float*)d_in[15];
    const float* qpb    = (const float*)d_in[16];
    const float* dpW    = (const float*)d_in[17];
    const float* dpb    = (const float*)d_in[18];
    const float* alpha  = (const float*)d_in[19];
    const float* c1W    = (const float*)d_in[20];
    const float* c1b    = (const float*)d_in[21];
    const float* c2W    = (const float*)d_in[22];
    const float* c2b    = (const float*)d_in[23];
    const float* c3W    = (const float*)d_in[24];
    const float* c3b    = (const float*)d_in[25];
    const float* ccW    = (const float*)d_in[26];
    const float* ccb    = (const float*)d_in[27];
    const float* outW   = (const float*)d_in[28];
    const float* outb   = (const float*)d_in[29];
    float* out = (float*)d_out;

    float *pXq,*pXd,*pxgq,*pxgd,*pencq,*pencd,*ppq,*ppdT,*ps3,*ps5,*ps7,*pqb,*pdb,*pWTq,*pWTd;
    cudaGetSymbolAddress((void**)&pXq,  g_Xq);
    cudaGetSymbolAddress((void**)&pXd,  g_Xd);
    cudaGetSymbolAddress((void**)&pxgq, g_xgq);
    cudaGetSymbolAddress((void**)&pxgd, g_xgd);
    cudaGetSymbolAddress((void**)&pencq,g_encq);
    cudaGetSymbolAddress((void**)&pencd,g_encd);
    cudaGetSymbolAddress((void**)&ppq,  g_pq);
    cudaGetSymbolAddress((void**)&ppdT, g_pdT);
    cudaGetSymbolAddress((void**)&ps3,  g_s3);
    cudaGetSymbolAddress((void**)&ps5,  g_s5);
    cudaGetSymbolAddress((void**)&ps7,  g_s7);
    cudaGetSymbolAddress((void**)&pqb,  g_qb);
    cudaGetSymbolAddress((void**)&pdb,  g_db);
    cudaGetSymbolAddress((void**)&pWTq, g_WTq);
    cudaGetSymbolAddress((void**)&pWTd, g_WTd);

    cudaFuncSetAttribute(lstm_persist, cudaFuncAttributeMaxDynamicSharedMemorySize, LSTM_SMEM);
    cudaFuncSetAttribute(gemm_dual<true,true,false>,  cudaFuncAttributeMaxDynamicSharedMemorySize, GEMM_DSM);
    cudaFuncSetAttribute(gemm_dual<false,true,true>,  cudaFuncAttributeMaxDynamicSharedMemorySize, GEMM_DSM);
    cudaFuncSetAttribute(gemm_dual<false,false,false>,cudaFuncAttributeMaxDynamicSharedMemorySize, GEMM_DSM);
    cudaFuncSetAttribute(convgemm_k, cudaFuncAttributeMaxDynamicSharedMemorySize, CONV_DSM);
    cudaFuncSetAttribute(score_k, cudaFuncAttributeMaxDynamicSharedMemorySize, SCORE_DSM);

    bias_sum_k<<<4,256>>>(qbih,qbhh,dbih,dbhh);
    wt_k<<<dim3(10,32,2),dim3(32,8)>>>(qWih, dWih);

    // embed + proj (dual): X = emb[tok] @ projW + projb
    { GS s1{emb, bqtok, projW, projb, pXq, NTQ, Ff, 0};
      GS s2{emb, bdtok, projW, projb, pXd, NTD, Ff, 0};
      gemm_dual<true,true,false><<<dim3(3,324),256,GEMM_DSM>>>(s1,s2,4, Ff,Ff, Ff,Ff); }

    // input gates (dual, packed WT): xg = X @ Wih^T + (bih+bhh)
    { GS s1{pXq, nullptr, pWTq, pqb, pxgq, NTQ, G4, 0};
      GS s2{pXd, nullptr, pWTd, pdb, pxgd, NTD, G4, 0};
      gemm_dual<false,true,true><<<dim3(8,324),256,GEMM_DSM>>>(s1,s2,4, Ff,G4, G4,Ff); }

    // persistent LSTMs (merged: 11 clusters x 8 blocks)
    lstm_persist<<<88,256,LSTM_SMEM>>>(pxgq, qWhh, pencq, pxgd, dWhh, pencd);

    // projections (dual): pq [512,50]; pdT per image
    { GS s1{pencq, nullptr, qpW, qpb, ppq,  NTQ, Cc, 0};
      GS s2{pencd, nullptr, dpW, dpb, ppdT, NTD, 0,  1};
      gemm_dual<false,false,false><<<dim3(1,324),256,GEMM_DSM>>>(s1,s2,4, Hh,Cc, Cc,Hh); }

    // conv stage 1 (merged)
    {
        long t7 = (long)Bq*NFc*QLn*352;
        s_k<<<dim3((unsigned)((t7+255)/256),3),256>>>(c1W,c2W,c3W, ps3,ps5,ps7);
    }
    // conv stage 2 (merged z-dispatch)
    convgemm_k<<<dim3(7,BD,3),256,CONV_DSM>>>(ps3,ps5,ps7, c1W,c1b, c2W,c2b, c3W,c3b,
                                              bqtok, bdtok, alpha);

    // 1x1 conv + maxpool + linear (tf32 mma)
    score_k<<<BD,256,SCORE_DSM>>>(ccW, ccb, outW, outb, out);
}

// round 12
// speedup vs baseline: 1.0495x; 1.0495x over previous
#include <cuda_runtime.h>
#include <math.h>

// ---------------- problem constants ----------------
#define Bq  32
#define Dn  10
#define QLn 16
#define DLn 128
#define BD  320
#define Ff  300
#define Hh  256
#define G4  1024
#define Cc  50
#define NFc 50
#define MFc 20
#define NTQ (Bq*QLn)      // 512
#define NTD (BD*DLn)      // 40960

// ---------------- device scratch ----------------
__device__ float g_Xq[NTQ*Ff];
__device__ float g_Xd[(size_t)NTD*Ff];
__device__ float g_xgq[(size_t)NTQ*G4];
__device__ float g_xgd[(size_t)NTD*G4];
__device__ float g_encq[NTQ*Hh];
__device__ float g_encd[(size_t)NTD*Hh];
__device__ float g_pq[NTQ*Cc];
__device__ float g_pdT[(size_t)BD*Cc*DLn];
__device__ float g_s3[(size_t)Bq*NFc*QLn*152 + 16];
__device__ float g_s5[(size_t)Bq*NFc*QLn*252 + 16];
__device__ float g_s7[(size_t)Bq*NFc*QLn*352 + 16];
__device__ float g_f[(size_t)BD*150*QLn*DLn];
__device__ float g_qb[G4];
__device__ float g_db[G4];
__device__ float g_WTq[Ff*G4];     // Wih^T, column-permuted for packed loads
__device__ float g_WTd[Ff*G4];

__device__ __forceinline__ float tha(float x){
    float y; asm("tanh.approx.f32 %0, %1;" : "=f"(y) : "f"(x)); return y;
}
__device__ __forceinline__ float sigf(float x){ return fmaf(tha(0.5f*x), 0.5f, 0.5f); }

__device__ __forceinline__ void mma8(float* c, const unsigned* a, const unsigned* b){
    asm volatile("mma.sync.aligned.m16n8k8.row.col.f32.tf32.tf32.f32 "
        "{%0,%1,%2,%3}, {%4,%5,%6,%7}, {%8,%9}, {%0,%1,%2,%3};"
        : "+f"(c[0]),"+f"(c[1]),"+f"(c[2]),"+f"(c[3])
        : "r"(a[0]),"r"(a[1]),"r"(a[2]),"r"(a[3]), "r"(b[0]),"r"(b[1]));
}
__device__ __forceinline__ unsigned sptr(const void* p){
    return (unsigned)__cvta_generic_to_shared(p);
}
__device__ __forceinline__ void cpa16(unsigned dst, const void* src, bool pred){
    int sz = pred ? 16 : 0;
    asm volatile("cp.async.cg.shared.global [%0], [%1], 16, %2;" :: "r"(dst), "l"(src), "r"(sz));
}
#define CP_COMMIT() asm volatile("cp.async.commit_group;")
#define CP_WAIT0()  asm volatile("cp.async.wait_group 0;")
#define CP_WAIT1()  asm volatile("cp.async.wait_group 1;")
#define CLUSTER_ARRIVE() asm volatile("barrier.cluster.arrive.aligned;" ::: "memory")
#define CLUSTER_WAIT()   asm volatile("barrier.cluster.wait.aligned;" ::: "memory")

// ---------------- bias precombine ----------------
__global__ void bias_sum_k(const float* __restrict__ qb1, const float* __restrict__ qb2,
                           const float* __restrict__ db1, const float* __restrict__ db2)
{
    int t = blockIdx.x*blockDim.x + threadIdx.x;
    if (t < G4){ g_qb[t] = qb1[t]+qb2[t]; g_db[t] = db1[t]+db2[t]; }
}

// ---------------- Wih transpose: smem-tiled, coalesced both sides ----------
__global__ void wt_k(const float* __restrict__ qW, const float* __restrict__ dW)
{
    __shared__ float t[32][33];
    const float* src = blockIdx.z ? dW : qW;
    float* dst = blockIdx.z ? g_WTd : g_WTq;
    int k0 = blockIdx.x*32, n0 = blockIdx.y*32;
    int tx = threadIdx.x, ty = threadIdx.y;     // block (32,8)
    #pragma unroll
    for (int dy = 0; dy < 32; dy += 8){
        int n = n0 + ty + dy, k = k0 + tx;
        t[ty+dy][tx] = (k < Ff) ? src[(size_t)n*Ff + k] : 0.f;
    }
    __syncthreads();
    #pragma unroll
    for (int dy = 0; dy < 32; dy += 8){
        int k = k0 + ty + dy;
        int n = n0 + tx;
        int np = (n & ~31) | ((n & 7)*4 + ((n >> 3) & 3));
        if (k < Ff) dst[(size_t)k*G4 + np] = t[tx][ty+dy];
    }
}

// ---------------- dual-side 3-stage pipelined tf32 GEMM (!BT only) ----------
struct GS {
    const float* A; const int* idx; const float* Bm; const float* bias;
    float* C; int M; int ldc; int store;   // store 0: C[m*ldc+n]; 1: pdT layout
};
#define GEMM_DSM (6*2560*4)
template<bool GATHER, bool BASYNC, bool PACKB>
__global__ __launch_bounds__(256,2) void gemm_dual(
    GS s1, GS s2, int ysplit, int lda, int ldb, int N, int K)
{
    extern __shared__ float dsm[];
    float* Asm = dsm;            // 3 stages x [128][20]
    float* Bsm = dsm + 3*2560;   // 3 stages x [16][132]
    int tid = threadIdx.x;
    int lane = tid & 31, warp = tid >> 5;
    int wm = warp >> 2, wn = warp & 3;
    bool side2 = ((int)blockIdx.y >= ysplit);
    const float* A_   = side2 ? s2.A    : s1.A;
    const int*   idx_ = side2 ? s2.idx  : s1.idx;
    const float* Bm_  = side2 ? s2.Bm   : s1.Bm;
    const float* bias = side2 ? s2.bias : s1.bias;
    float*       C    = side2 ? s2.C    : s1.C;
    int M    = side2 ? s2.M    : s1.M;
    int ldc  = side2 ? s2.ldc  : s1.ldc;
    int store= side2 ? s2.store: s1.store;
    int by = (int)blockIdx.y - (side2 ? ysplit : 0);
    int m0 = by*128, n0 = blockIdx.x*128;
    int nk = (K + 15) >> 4;
    int r8 = lane>>2, q4 = lane&3;

    int arow = tid >> 1;
    int acp  = (tid & 1) * 8;
    bool mrowok = (m0 + arow) < M;
    const float* Arow;
    { long r = GATHER ? (long)idx_[m0 + (mrowok ? arow : 0)] : (long)(m0 + (mrowok ? arow : 0));
      Arow = A_ + r*(long)lda; }

    int bkr = tid >> 4, bnf = (tid & 15)*8;

    auto issue = [&](int kt, int buf){
        int k0 = kt*16;
        unsigned d = sptr(Asm + buf*2560 + arow*20 + acp);
        cpa16(d,    Arow + k0 + acp,     mrowok && (k0+acp)   < K);
        cpa16(d+16, Arow + k0 + acp + 4, mrowok && (k0+acp+4) < K);
        if (BASYNC){
            const float* src = Bm_ + (size_t)(k0+bkr)*ldb + n0 + bnf;
            unsigned db = sptr(Bsm + buf*2560 + bkr*132 + bnf);
            bool kok = (k0+bkr) < K;
            cpa16(db,    src,   kok && (n0+bnf)   < N);
            cpa16(db+16, src+4, kok && (n0+bnf+4) < N);
        }
        CP_COMMIT();
    };

    float bv[8];
    int nc = (tid&31)*4, kr = tid>>5;
    auto ldgB = [&](int kt){
        int k0 = kt*16;
        #pragma unroll
        for (int h=0;h<2;h++){
            int kk = k0 + kr + h*8;
            #pragma unroll
            for (int j=0;j<4;j++){
                int n = n0 + nc + j;
                bv[h*4+j] = (kk < K && n < N) ? Bm_[(size_t)kk*ldb + n] : 0.f;
            }
        }
    };
    auto stsB = [&](int buf){
        #pragma unroll
        for (int h=0;h<2;h++)
            #pragma unroll
            for (int j=0;j<4;j++) Bsm[buf*2560 + (kr+h*8)*132 + nc+j] = bv[h*4+j];
    };

    float acc[4][4][4] = {};

    issue(0,0);
    if (nk > 1) issue(1,1);
    if (!BASYNC) ldgB(0);

    int buf = 0;
    for (int kt = 0; kt < nk; kt++){
        if (kt >= nk-1) CP_WAIT0(); else CP_WAIT1();
        __syncthreads();
        if (!BASYNC) stsB(buf);
        if (kt+2 < nk) issue(kt+2, buf == 0 ? 2 : buf-1);
        if (!BASYNC){
            if (kt+1 < nk) ldgB(kt+1);
            __syncthreads();
        }
        const float* Ab2 = Asm + buf*2560;
        const float* Bb2 = Bsm + buf*2560;
        #pragma unroll
        for (int kb=0; kb<2; kb++){
            int ko = kb*8;
            unsigned af[4][4], bf[4][2];
            #pragma unroll
            for (int mt=0; mt<4; mt++){
                int rb = wm*64 + mt*16;
                af[mt][0] = __float_as_uint(Ab2[(rb+r8  )*20 + ko+q4  ]);
                af[mt][1] = __float_as_uint(Ab2[(rb+r8+8)*20 + ko+q4  ]);
                af[mt][2] = __float_as_uint(Ab2[(rb+r8  )*20 + ko+q4+4]);
                af[mt][3] = __float_as_uint(Ab2[(rb+r8+8)*20 + ko+q4+4]);
            }
            if (PACKB){
                float4 b0 = *(const float4*)&Bb2[(ko+q4  )*132 + wn*32 + r8*4];
                float4 b1 = *(const float4*)&Bb2[(ko+q4+4)*132 + wn*32 + r8*4];
                bf[0][0]=__float_as_uint(b0.x); bf[1][0]=__float_as_uint(b0.y);
                bf[2][0]=__float_as_uint(b0.z); bf[3][0]=__float_as_uint(b0.w);
                bf[0][1]=__float_as_uint(b1.x); bf[1][1]=__float_as_uint(b1.y);
                bf[2][1]=__float_as_uint(b1.z); bf[3][1]=__float_as_uint(b1.w);
            } else {
                #pragma unroll
                for (int nt=0; nt<4; nt++){
                    int nb = wn*32 + nt*8;
                    bf[nt][0] = __float_as_uint(Bb2[(ko+q4  )*132 + nb+r8]);
                    bf[nt][1] = __float_as_uint(Bb2[(ko+q4+4)*132 + nb+r8]);
                }
            }
            #pragma unroll
            for (int mt=0;mt<4;mt++)
                #pragma unroll
                for (int nt=0;nt<4;nt++)
                    mma8(acc[mt][nt], af[mt], bf[nt]);
        }
        buf = (buf == 2) ? 0 : buf+1;
    }

    #pragma unroll
    for (int mt=0;mt<4;mt++){
        int row = m0 + wm*64 + mt*16 + r8;
        #pragma unroll
        for (int nt=0;nt<4;nt++){
            int col = n0 + wn*32 + nt*8 + q4*2;
            const float* cc = acc[mt][nt];
            #pragma unroll
            for (int j=0;j<2;j++){
                int n = col + j;
                if (n >= N) continue;
                float bb = bias ? bias[n] : 0.f;
                float v0 = cc[j] + bb, v1 = cc[2+j] + bb;
                if (store == 0){
                    if (row < M)   C[(size_t)row*ldc + n] = v0;
                    if (row+8 < M) C[(size_t)(row+8)*ldc + n] = v1;
                } else {
                    int img = row >> 7;
                    C[((size_t)img*Cc + n)*DLn + (row & 127)] = v0;
                    C[((size_t)img*Cc + n)*DLn + ((row+8) & 127)] = v1;
                }
            }
        }
    }
}

// ---------------- persistent LSTM: R9 structure + packed Bs -----------------
// Bs: [256][136] Whh slice, columns permuted (phys r8*4+nt <- logical nt*8+r8).
// As: [32][260] h_prev m-major (coalesced full-row cp.async). xs: [32][132].
#define LSTM_BS_W  (256*136)
#define LSTM_AS_W  (32*260)
#define LSTM_XS_W  (32*132)
#define LSTM_SMEM  ((LSTM_BS_W + LSTM_AS_W + LSTM_XS_W)*4)
__global__ __cluster_dims__(8,1,1) __launch_bounds__(256,1) void lstm_persist(
    const float* __restrict__ xgq, const float* __restrict__ Whq, float* __restrict__ encq,
    const float* __restrict__ xgd, const float* __restrict__ Whd, float* __restrict__ encd)
{
    extern __shared__ unsigned smbuf[];
    unsigned* Bs = smbuf;
    float* Bsf = (float*)Bs;
    float* As = (float*)(smbuf + LSTM_BS_W);
    float* xs = As + LSTM_AS_W;
    int tid = threadIdx.x;
    int lane = tid & 31, warp = tid >> 5;
    int r8 = lane >> 2, q4 = lane & 3;
    int wm = warp & 1, wn = warp >> 1;
    int cid = blockIdx.x >> 3, hb = blockIdx.x & 7;
    const float* xg; const float* Whh; float* enc; int T, n0;
    if (cid == 0){ xg = xgq; Whh = Whq; enc = encq; T = QLn; n0 = 0; }
    else        { xg = xgd; Whh = Whd; enc = encd; T = DLn; n0 = (cid-1)*32; }
    int h0 = hb * 32;

    // fill Bs with column permutation: physical p holds logical j
    for (int idx = tid; idx < 128*256; idx += 256){
        int p = idx >> 8, k = idx & 255;
        int p32 = p & 31;
        int j = (p & ~31) | (((p32 & 3) << 3) | (p32 >> 2));   // nt*8 + r8
        int r = ((j & 3) << 8) + h0 + (j >> 2);
        Bs[k*136 + p] = __float_as_uint(Whh[(size_t)r*Hh + k]);
    }

    auto issueXS = [&](int t){
        #pragma unroll
        for (int u = 0; u < 4; u++){
            int ch = tid + 256*u;
            int m  = ch >> 5;
            int g  = (ch >> 3) & 3;
            int o4 = (ch & 7) * 4;
            const float* src = xg + ((size_t)(n0+m)*T + t)*G4 + g*256 + h0 + o4;
            cpa16(sptr(xs + m*132 + g*32 + o4), src, true);
        }
        CP_COMMIT();
    };
    auto issueAS = [&](int t){     // coalesced: 64 consecutive threads per m-row
        #pragma unroll
        for (int u = 0; u < 8; u++){
            int ch = tid + 256*u;
            int m  = ch >> 6;
            int k4 = (ch & 63) * 4;
            cpa16(sptr(As + m*260 + k4), enc + ((size_t)(n0+m)*T + (t-1))*Hh + k4, true);
        }
        CP_COMMIT();
    };

    issueXS(0);
    float creg[4] = {0.f, 0.f, 0.f, 0.f};
    int rb = wm*16;

    for (int t = 0; t < T; t++){
        if (t == 0){
            for (int idx = tid; idx < 32*256; idx += 256)
                As[(idx >> 8)*260 + (idx & 255)] = 0.f;
        } else {
            issueAS(t);
        }
        CP_WAIT0();
        __syncthreads();

        float acc[4][4] = {};
        #pragma unroll 4
        for (int ko = 0; ko < 256; ko += 8){
            unsigned af[4];
            af[0] = __float_as_uint(As[(rb+r8  )*260 + ko+q4  ]);
            af[1] = __float_as_uint(As[(rb+r8+8)*260 + ko+q4  ]);
            af[2] = __float_as_uint(As[(rb+r8  )*260 + ko+q4+4]);
            af[3] = __float_as_uint(As[(rb+r8+8)*260 + ko+q4+4]);
            float4 b0 = *(const float4*)&Bsf[(ko+q4  )*136 + wn*32 + r8*4];
            float4 b1 = *(const float4*)&Bsf[(ko+q4+4)*136 + wn*32 + r8*4];
            unsigned bf0[2] = {__float_as_uint(b0.x), __float_as_uint(b1.x)};
            unsigned bf1[2] = {__float_as_uint(b0.y), __float_as_uint(b1.y)};
            unsigned bf2[2] = {__float_as_uint(b0.z), __float_as_uint(b1.z)};
            unsigned bf3[2] = {__float_as_uint(b0.w), __float_as_uint(b1.w)};
            mma8(acc[0], af, bf0);
            mma8(acc[1], af, bf1);
            mma8(acc[2], af, bf2);
            mma8(acc[3], af, bf3);
        }

        // shfl epilogue: lane^1 holds the complementary gate pair
        bool odd = (q4 & 1);
        int m  = rb + r8 + (odd ? 8 : 0);
        #pragma unroll
        for (int nt = 0; nt < 4; nt++){
            float a0 = acc[nt][0], a1 = acc[nt][1], a2 = acc[nt][2], a3 = acc[nt][3];
            float e0 = __shfl_xor_sync(0xFFFFFFFFu, a0, 1);
            float e1 = __shfl_xor_sync(0xFFFFFFFFu, a1, 1);
            float e2 = __shfl_xor_sync(0xFFFFFFFFu, a2, 1);
            float e3 = __shfl_xor_sync(0xFFFFFFFFu, a3, 1);
            float g0 = odd ? e2 : a0;
            float g1 = odd ? e3 : a1;
            float g2 = odd ? a2 : e0;
            float g3 = odd ? a3 : e1;
            int hp = wn*8 + nt*2 + (q4 >> 1);
            const float* xr = xs + m*132 + hp;
            float gi = g0 + xr[0];
            float gf = g1 + xr[32];
            float gg = g2 + xr[64];
            float go = g3 + xr[96];
            float cv = sigf(gf)*creg[nt] + sigf(gi)*tha(gg);
            creg[nt] = cv;
            enc[((size_t)(n0+m)*T + t)*Hh + h0 + hp] = sigf(go)*tha(cv);
        }
        __syncthreads();
        if (t+1 < T) issueXS(t+1);
        CLUSTER_ARRIVE();
        CLUSTER_WAIT();
    }
}

// ---------------- conv stage 1 (merged 3 convs via blockIdx.y) ----------------
__global__ void s_k(const float* __restrict__ c1W, const float* __restrict__ c2W,
                    const float* __restrict__ c3W,
                    float* __restrict__ s3, float* __restrict__ s5, float* __restrict__ s7)
{
    int z = blockIdx.y;
    int KW = 3 + 2*z, KP = 152 + 100*z;
    const float* cW = (z==0) ? c1W : (z==1) ? c2W : c3W;
    float* s = (z==0) ? s3 : (z==1) ? s5 : s7;
    long total = (long)Bq*NFc*QLn*KP;
    long i = (long)blockIdx.x*blockDim.x + threadIdx.x;
    if (i >= total) return;
    int kk = (int)(i % KP);
    long r = i / KP;
    int q  = (int)(r % QLn); r /= QLn;
    int o  = (int)(r % NFc);
    int b  = (int)(r / NFc);
    float v = 0.f;
    if (kk < Cc*KW){
        int dd = kk / Cc, c = kk - dd*Cc;
        #pragma unroll
        for (int dq = 0; dq < 3; dq++){
            int qq = q + dq - 1;
            if (qq >= 0 && qq < QLn)
                v += cW[(((size_t)o*51 + c)*3 + dq)*KW + dd] * g_pq[((size_t)b*QLn + qq)*Cc + c];
        }
    }
    s[i] = v;
}

// ---------------- conv stage 2: merged (blockIdx.z), resident-B, 3-stage A ----
#define CONV_DSM ((3*2560 + 50*132)*4)
__global__ __launch_bounds__(256,2) void convgemm_k(
    const float* __restrict__ sA3, const float* __restrict__ sA5, const float* __restrict__ sA7,
    const float* __restrict__ c1W, const float* __restrict__ c1b,
    const float* __restrict__ c2W, const float* __restrict__ c2b,
    const float* __restrict__ c3W, const float* __restrict__ c3b,
    const int* __restrict__ bqtok, const int* __restrict__ bdtok,
    const float* __restrict__ alpha)
{
    int z = blockIdx.z;
    const int KW = 3 + 2*z, KP = 152 + 100*z, PW = KW >> 1, OCB = z*50;
    const int nk = (KP + 15) >> 4;
    const float* sA = (z==0) ? sA3 : (z==1) ? sA5 : sA7;
    const float* cW = (z==0) ? c1W : (z==1) ? c2W : c3W;
    const float* cb = (z==0) ? c1b : (z==1) ? c2b : c3b;
    extern __shared__ float dsm[];
    float* Asm = dsm;              // 3 stages x [128][20]
    float* pdt = dsm + 3*2560;     // [50][132]
    __shared__ float ems[18][136];
    __shared__ float wem[8][21];
    __shared__ int qt[16], dt[128], s_any;
    int tid = threadIdx.x;
    int lane = tid & 31, warp = tid >> 5;
    int wm = warp >> 2, wn = warp & 3;
    int img = blockIdx.y, b = img / Dn;
    int m0 = blockIdx.x*128, obase = m0 >> 4;
    int r8 = lane>>2, q4 = lane&3;

    const float* Pd = &g_pdT[(size_t)img*Cc*DLn];
    int arow = tid >> 1, acp = (tid & 1)*8;
    bool mok = (m0 + arow) < 800;
    const float* Arow = sA + ((size_t)b*800 + (mok ? m0+arow : 0))*KP;

    auto issueA = [&](int kt, int buf){
        int k0 = kt*16;
        unsigned d = sptr(Asm + buf*2560 + arow*20 + acp);
        cpa16(d,    Arow + k0 + acp,     mok && (k0+acp)   < KP);
        cpa16(d+16, Arow + k0 + acp + 4, mok && (k0+acp+4) < KP);
    };

    for (int ch = tid; ch < 1600; ch += 256){
        int row = ch >> 5, off = (ch & 31) * 4;
        cpa16(sptr(pdt + row*132 + off), Pd + row*128 + off, true);
    }
    issueA(0,0); CP_COMMIT();
    issueA(1,1); CP_COMMIT();

    if (tid == 0) s_any = 0;
    if (tid < 16) qt[tid] = bqtok[b*QLn + tid];
    if (tid < 128) dt[tid] = bdtok[(size_t)img*DLn + tid];
    if (tid < 8*3*KW){
        int ol = tid/(3*KW), rr = tid%(3*KW);
        int o = obase + ol;
        wem[ol][rr] = (o < NFc) ? cW[(((size_t)o*51 + 50)*3 + rr/KW)*KW + rr%KW] : 0.f;
    }
    __syncthreads();
    float al = alpha[0];
    for (int e = tid; e < 18*136; e += 256){
        int qi = e/136, dj = e%136;
        int q = qi-1, dl = dj-3;
        float v = 0.f;
        if (q >= 0 && q < QLn && dl >= 0 && dl < DLn && qt[q] == dt[dl]){ v = al; s_any = 1; }
        ems[qi][dj] = v;
    }

    float acc[4][4][4] = {};
    int buf = 0;
    for (int kt = 0; kt < nk; kt++){
        if (kt >= nk-1) CP_WAIT0(); else CP_WAIT1();
        __syncthreads();
        if (kt+2 < nk){ issueA(kt+2, buf == 0 ? 2 : buf-1); CP_COMMIT(); }
        const float* Ab2 = Asm + buf*2560;
        #pragma unroll
        for (int kb=0; kb<2; kb++){
            int ko = kb*8;
            int ka = kt*16 + ko + q4;
            int k2 = ka + 4;
            int dda = ka/Cc, ca = ka - dda*Cc;
            int ddb = k2/Cc, cbb = k2 - ddb*Cc;
            unsigned af[4][4], bf[4][2];
            #pragma unroll
            for (int mt=0; mt<4; mt++){
                int rb = wm*64 + mt*16;
                af[mt][0] = __float_as_uint(Ab2[(rb+r8  )*20 + ko+q4  ]);
                af[mt][1] = __float_as_uint(Ab2[(rb+r8+8)*20 + ko+q4  ]);
                af[mt][2] = __float_as_uint(Ab2[(rb+r8  )*20 + ko+q4+4]);
                af[mt][3] = __float_as_uint(Ab2[(rb+r8+8)*20 + ko+q4+4]);
            }
            #pragma unroll
            for (int nt=0; nt<4; nt++){
                int col = wn*32 + nt*8 + r8;
                int sa = col + dda - PW;
                int sb = col + ddb - PW;
                bf[nt][0] = ((unsigned)sa < 128u) ? __float_as_uint(pdt[ca*132 + sa]) : 0u;
                bf[nt][1] = ((unsigned)sb < 128u) ? __float_as_uint(pdt[cbb*132 + sb]) : 0u;
            }
            #pragma unroll
            for (int mt=0;mt<4;mt++)
                #pragma unroll
                for (int nt=0;nt<4;nt++)
                    mma8(acc[mt][nt], af[mt], bf[nt]);
        }
        buf = (buf == 2) ? 0 : buf+1;
    }

    int any = s_any;
    #pragma unroll
    for (int mt=0;mt<4;mt++){
        int row = m0 + wm*64 + mt*16;
        if (row >= 800) continue;
        int o = row >> 4, ol = o - obase;
        float bias = cb[o];
        #pragma unroll
        for (int rr=0; rr<2; rr++){
            int q = r8 + rr*8;
            #pragma unroll
            for (int nt=0;nt<4;nt++){
                int col = wn*32 + nt*8 + q4*2;
                #pragma unroll
                for (int j=0;j<2;j++){
                    int dl = col + j;
                    float v = acc[mt][nt][rr*2 + j] + bias;
                    if (any){
                        for (int dq = 0; dq < 3; dq++)
                            for (int dd = 0; dd < KW; dd++)
                                v += wem[ol][dq*KW+dd] * ems[q+dq][dl+dd+3-PW];
                    }
                    v = fmaxf(v, 0.f);
                    g_f[(((size_t)img*150 + OCB + o)*QLn + q)*DLn + dl] = v;
                }
            }
        }
    }
}

// ---------------- 1x1 conv + maxpool + linear (tf32 mma) ----------------
#define SCORE_DSM ((3*8*264 + 152*36)*4)
__global__ __launch_bounds__(256,2) void score_k(
    const float* __restrict__ ccW, const float* __restrict__ ccb,
    const float* __restrict__ outW, const float* __restrict__ outb,
    float* __restrict__ out)
{
    extern __shared__ float dsm[];
    float* fs = dsm;               // 3 stages x [8][264]
    float* Ws = dsm + 3*8*264;     // [152][36]: Ws[k*36+m]
    __shared__ float red[32][8];
    __shared__ float part[32];
    int img = blockIdx.x, tid = threadIdx.x;
    int lane = tid & 31, warp = tid >> 5;
    int r8 = lane >> 2, q4 = lane & 3;

    for (int idx = tid; idx < 152*32; idx += 256){
        int m = idx & 31, k = idx >> 5;
        Ws[k*36 + m] = (m < MFc && k < 150) ? ccW[m*150 + k] : 0.f;
    }

    const float* fimg = &g_f[(size_t)img*150*2048];
    auto issue = [&](int kt, int pch, int buf){
        #pragma unroll
        for (int h = 0; h < 2; h++){
            int ch = tid + 256*h;
            int row = ch >> 6, off = (ch & 63)*4;
            int kr = kt*8 + row;
            cpa16(sptr(fs + buf*2112 + row*264 + off),
                  fimg + (size_t)kr*2048 + pch*256 + off, kr < 150);
        }
        CP_COMMIT();
    };

    float bb0 = (r8      < MFc) ? ccb[r8]      : 0.f;
    float bb0b= (r8+8    < MFc) ? ccb[r8+8]    : 0.f;
    float maxv[2][2] = {{-1e30f,-1e30f},{-1e30f,-1e30f}};
    __syncthreads();   // Ws ready

    for (int pch = 0; pch < 8; pch++){
        float acc[2][4][4] = {};
        issue(0, pch, 0);
        issue(1, pch, 1);
        int buf = 0;
        for (int kt = 0; kt < 19; kt++){
            if (kt >= 17) CP_WAIT0(); else CP_WAIT1();
            __syncthreads();
            if (kt+2 < 19) issue(kt+2, pch, buf == 0 ? 2 : buf-1);
            const float* fb2 = fs + buf*2112;
            unsigned af[2][4];
            #pragma unroll
            for (int mt=0; mt<2; mt++){
                int mb = mt*16;
                af[mt][0] = __float_as_uint(Ws[(kt*8+q4  )*36 + mb+r8]);
                af[mt][1] = __float_as_uint(Ws[(kt*8+q4  )*36 + mb+r8+8]);
                af[mt][2] = __float_as_uint(Ws[(kt*8+q4+4)*36 + mb+r8]);
                af[mt][3] = __float_as_uint(Ws[(kt*8+q4+4)*36 + mb+r8+8]);
            }
            #pragma unroll
            for (int nt=0; nt<4; nt++){
                int nb = warp*32 + nt*8;
                unsigned bf[2];
                bf[0] = __float_as_uint(fb2[(q4  )*264 + nb+r8]);
                bf[1] = __float_as_uint(fb2[(q4+4)*264 + nb+r8]);
                #pragma unroll
                for (int mt=0; mt<2; mt++)
                    mma8(acc[mt][nt], af[mt], bf);
            }
            buf = (buf == 2) ? 0 : buf+1;
            __syncthreads();
        }
        #pragma unroll
        for (int mt=0; mt<2; mt++){
            float b0 = (mt==0) ? bb0  : ((16+r8 < MFc) ? ccb[16+r8] : 0.f);
            float b1 = (mt==0) ? bb0b : 0.f;
            #pragma unroll
            for (int nt=0; nt<4; nt++){
                float* cc = acc[mt][nt];
                maxv[mt][0] = fmaxf(maxv[mt][0], fmaxf(cc[0], cc[1]) + b0);
                maxv[mt][1] = fmaxf(maxv[mt][1], fmaxf(cc[2], cc[3]) + b1);
            }
        }
    }
    #pragma unroll
    for (int mt=0; mt<2; mt++)
        #pragma unroll
        for (int h=0; h<2; h++){
            float v = maxv[mt][h];
            v = fmaxf(v, __shfl_xor_sync(0xFFFFFFFFu, v, 1));
            v = fmaxf(v, __shfl_xor_sync(0xFFFFFFFFu, v, 2));
            maxv[mt][h] = v;
        }
    if (q4 == 0){
        #pragma unroll
        for (int mt=0; mt<2; mt++)
            #pragma unroll
            for (int h=0; h<2; h++)
                red[mt*16 + h*8 + r8][warp] = maxv[mt][h];
    }
    __syncthreads();
    if (tid < 32){
        float m = red[tid][0];
        #pragma unroll
        for (int w = 1; w < 8; w++) m = fmaxf(m, red[tid][w]);
        part[tid] = (tid < MFc) ? m * outW[tid] : 0.f;
    }
    __syncthreads();
    if (tid == 0){
        float sc = outb[0];
        #pragma unroll
        for (int mf = 0; mf < MFc; mf++) sc += part[mf];
        out[img] = sc;
    }
}

// ---------------- launch ----------------
extern "C" void kernel_launch(void* const* d_in, const int* in_sizes, int n_in,
                              void* d_out, int out_size)
{
    const int* bqtok = nullptr; const int* bdtok = nullptr;
    for (int i = 0; i < 4; i++){
        if (in_sizes[i] == NTQ)      bqtok = (const int*)d_in[i];
        else if (in_sizes[i] == NTD) bdtok = (const int*)d_in[i];
    }
    const float* emb    = (const float*)d_in[4];
    const float* projW  = (const float*)d_in[5];
    const float* projb  = (const float*)d_in[6];
    const float* qWih   = (const float*)d_in[7];
    const float* qWhh   = (const float*)d_in[8];
    const float* qbih   = (const float*)d_in[9];
    const float* qbhh   = (const float*)d_in[10];
    const float* dWih   = (const float*)d_in[11];
    const float* dWhh   = (const float*)d_in[12];
    const float* dbih   = (const float*)d_in[13];
    const float* dbhh   = (const float*)d_in[14];
    const float* qpW    = (const float*)d_in[15];
    const float* qpb    = (const float*)d_in[16];
    const float* dpW    = (const float*)d_in[17];
    const float* dpb    = (const float*)d_in[18];
    const float* alpha  = (const float*)d_in[19];
    const float* c1W    = (const float*)d_in[20];
    const float* c1b    = (const float*)d_in[21];
    const float* c2W    = (const float*)d_in[22];
    const float* c2b    = (const float*)d_in[23];
    const float* c3W    = (const float*)d_in[24];
    const float* c3b    = (const float*)d_in[25];
    const float* ccW    = (const float*)d_in[26];
    const float* ccb    = (const float*)d_in[27];
    const float* outW   = (const float*)d_in[28];
    const float* outb   = (const float*)d_in[29];
    float* out = (float*)d_out;

    float *pXq,*pXd,*pxgq,*pxgd,*pencq,*pencd,*ppq,*ppdT,*ps3,*ps5,*ps7,*pqb,*pdb,*pWTq,*pWTd;
    cudaGetSymbolAddress((void**)&pXq,  g_Xq);
    cudaGetSymbolAddress((void**)&pXd,  g_Xd);
    cudaGetSymbolAddress((void**)&pxgq, g_xgq);
    cudaGetSymbolAddress((void**)&pxgd, g_xgd);
    cudaGetSymbolAddress((void**)&pencq,g_encq);
    cudaGetSymbolAddress((void**)&pencd,g_encd);
    cudaGetSymbolAddress((void**)&ppq,  g_pq);
    cudaGetSymbolAddress((void**)&ppdT, g_pdT);
    cudaGetSymbolAddress((void**)&ps3,  g_s3);
    cudaGetSymbolAddress((void**)&ps5,  g_s5);
    cudaGetSymbolAddress((void**)&ps7,  g_s7);
    cudaGetSymbolAddress((void**)&pqb,  g_qb);
    cudaGetSymbolAddress((void**)&pdb,  g_db);
    cudaGetSymbolAddress((void**)&pWTq, g_WTq);
    cudaGetSymbolAddress((void**)&pWTd, g_WTd);

    cudaFuncSetAttribute(lstm_persist, cudaFuncAttributeMaxDynamicSharedMemorySize, LSTM_SMEM);
    cudaFuncSetAttribute(gemm_dual<true,true,false>,  cudaFuncAttributeMaxDynamicSharedMemorySize, GEMM_DSM);
    cudaFuncSetAttribute(gemm_dual<false,true,true>,  cudaFuncAttributeMaxDynamicSharedMemorySize, GEMM_DSM);
    cudaFuncSetAttribute(gemm_dual<false,false,false>,cudaFuncAttributeMaxDynamicSharedMemorySize, GEMM_DSM);
    cudaFuncSetAttribute(convgemm_k, cudaFuncAttributeMaxDynamicSharedMemorySize, CONV_DSM);
    cudaFuncSetAttribute(score_k, cudaFuncAttributeMaxDynamicSharedMemorySize, SCORE_DSM);

    bias_sum_k<<<4,256>>>(qbih,qbhh,dbih,dbhh);
    wt_k<<<dim3(10,32,2),dim3(32,8)>>>(qWih, dWih);

    // embed + proj (dual): X = emb[tok] @ projW + projb
    { GS s1{emb, bqtok, projW, projb, pXq, NTQ, Ff, 0};
      GS s2{emb, bdtok, projW, projb, pXd, NTD, Ff, 0};
      gemm_dual<true,true,false><<<dim3(3,324),256,GEMM_DSM>>>(s1,s2,4, Ff,Ff, Ff,Ff); }

    // input gates (dual, packed WT): xg = X @ Wih^T + (bih+bhh)
    { GS s1{pXq, nullptr, pWTq, pqb, pxgq, NTQ, G4, 0};
      GS s2{pXd, nullptr, pWTd, pdb, pxgd, NTD, G4, 0};
      gemm_dual<false,true,true><<<dim3(8,324),256,GEMM_DSM>>>(s1,s2,4, Ff,G4, G4,Ff); }

    // persistent LSTMs (merged: 11 clusters x 8 blocks)
    lstm_persist<<<88,256,LSTM_SMEM>>>(pxgq, qWhh, pencq, pxgd, dWhh, pencd);

    // projections (dual): pq [512,50]; pdT per image
    { GS s1{pencq, nullptr, qpW, qpb, ppq,  NTQ, Cc, 0};
      GS s2{pencd, nullptr, dpW, dpb, ppdT, NTD, 0,  1};
      gemm_dual<false,false,false><<<dim3(1,324),256,GEMM_DSM>>>(s1,s2,4, Hh,Cc, Cc,Hh); }

    // conv stage 1 (merged)
    {
        long t7 = (long)Bq*NFc*QLn*352;
        s_k<<<dim3((unsigned)((t7+255)/256),3),256>>>(c1W,c2W,c3W, ps3,ps5,ps7);
    }
    // conv stage 2 (merged z-dispatch)
    convgemm_k<<<dim3(7,BD,3),256,CONV_DSM>>>(ps3,ps5,ps7, c1W,c1b, c2W,c2b, c3W,c3b,
                                              bqtok, bdtok, alpha);

    // 1x1 conv + maxpool + linear (tf32 mma)
    score_k<<<BD,256,SCORE_DSM>>>(ccW, ccb, outW, outb, out);
}

// round 13
// speedup vs baseline: 1.0944x; 1.0428x over previous
#include <cuda_runtime.h>
#include <math.h>

// ---------------- problem constants ----------------
#define Bq  32
#define Dn  10
#define QLn 16
#define DLn 128
#define BD  320
#define Ff  300
#define Hh  256
#define G4  1024
#define Cc  50
#define NFc 50
#define MFc 20
#define NTQ (Bq*QLn)      // 512
#define NTD (BD*DLn)      // 40960

// ---------------- device scratch ----------------
__device__ float g_Xq[NTQ*Ff];
__device__ float g_Xd[(size_t)NTD*Ff];
__device__ float g_xgq[(size_t)NTQ*G4];
__device__ float g_xgd[(size_t)NTD*G4];
__device__ float g_encq[NTQ*Hh];
__device__ float g_encd[(size_t)NTD*Hh];
__device__ float g_pq[NTQ*Cc];
__device__ float g_pdT[(size_t)BD*Cc*DLn];
__device__ float g_s3[(size_t)Bq*NFc*QLn*152 + 16];
__device__ float g_s5[(size_t)Bq*NFc*QLn*252 + 16];
__device__ float g_s7[(size_t)Bq*NFc*QLn*352 + 16];
__device__ float g_f[(size_t)BD*150*QLn*DLn];
__device__ float g_qb[G4];
__device__ float g_db[G4];
__device__ float g_WTq[Ff*G4];     // Wih^T, column-permuted for packed loads
__device__ float g_WTd[Ff*G4];

__device__ __forceinline__ float tha(float x){
    float y; asm("tanh.approx.f32 %0, %1;" : "=f"(y) : "f"(x)); return y;
}
__device__ __forceinline__ float sigf(float x){ return fmaf(tha(0.5f*x), 0.5f, 0.5f); }

__device__ __forceinline__ void mma8(float* c, const unsigned* a, const unsigned* b){
    asm volatile("mma.sync.aligned.m16n8k8.row.col.f32.tf32.tf32.f32 "
        "{%0,%1,%2,%3}, {%4,%5,%6,%7}, {%8,%9}, {%0,%1,%2,%3};"
        : "+f"(c[0]),"+f"(c[1]),"+f"(c[2]),"+f"(c[3])
        : "r"(a[0]),"r"(a[1]),"r"(a[2]),"r"(a[3]), "r"(b[0]),"r"(b[1]));
}
__device__ __forceinline__ unsigned sptr(const void* p){
    return (unsigned)__cvta_generic_to_shared(p);
}
__device__ __forceinline__ void cpa16(unsigned dst, const void* src, bool pred){
    int sz = pred ? 16 : 0;
    asm volatile("cp.async.cg.shared.global [%0], [%1], 16, %2;" :: "r"(dst), "l"(src), "r"(sz));
}
__device__ __forceinline__ void cpa8(unsigned dst, const void* src, bool pred){
    int sz = pred ? 8 : 0;
    asm volatile("cp.async.ca.shared.global [%0], [%1], 8, %2;" :: "r"(dst), "l"(src), "r"(sz));
}
#define CP_COMMIT() asm volatile("cp.async.commit_group;")
#define CP_WAIT0()  asm volatile("cp.async.wait_group 0;")
#define CP_WAIT1()  asm volatile("cp.async.wait_group 1;")
#define CLUSTER_ARRIVE() asm volatile("barrier.cluster.arrive.aligned;" ::: "memory")
#define CLUSTER_WAIT()   asm volatile("barrier.cluster.wait.aligned;" ::: "memory")

// ---------------- bias precombine ----------------
__global__ void bias_sum_k(const float* __restrict__ qb1, const float* __restrict__ qb2,
                           const float* __restrict__ db1, const float* __restrict__ db2)
{
    int t = blockIdx.x*blockDim.x + threadIdx.x;
    if (t < G4){ g_qb[t] = qb1[t]+qb2[t]; g_db[t] = db1[t]+db2[t]; }
}

// ---------------- Wih transpose: smem-tiled, coalesced both sides ----------
__global__ void wt_k(const float* __restrict__ qW, const float* __restrict__ dW)
{
    __shared__ float t[32][33];
    const float* src = blockIdx.z ? dW : qW;
    float* dst = blockIdx.z ? g_WTd : g_WTq;
    int k0 = blockIdx.x*32, n0 = blockIdx.y*32;
    int tx = threadIdx.x, ty = threadIdx.y;     // block (32,8)
    #pragma unroll
    for (int dy = 0; dy < 32; dy += 8){
        int n = n0 + ty + dy, k = k0 + tx;
        t[ty+dy][tx] = (k < Ff) ? src[(size_t)n*Ff + k] : 0.f;
    }
    __syncthreads();
    #pragma unroll
    for (int dy = 0; dy < 32; dy += 8){
        int k = k0 + ty + dy;
        int n = n0 + tx;
        int np = (n & ~31) | ((n & 7)*4 + ((n >> 3) & 3));
        if (k < Ff) dst[(size_t)k*G4 + np] = t[tx][ty+dy];
    }
}

// ---------------- dual-side 3-stage pipelined tf32 GEMM, k-step 32 ----------
// B8: B rows only 8B-aligned -> cp.async 8B chunks. PACKB: column-permuted WT.
struct GS {
    const float* A; const int* idx; const float* Bm; const float* bias;
    float* C; int M; int ldc; int store;   // store 0: C[m*ldc+n]; 1: pdT layout
};
#define ASTG 4608            // 128 x 36 floats per stage
#define BSTG 4352            // 32 x 136 floats per stage
#define GEMM_DSM ((3*ASTG + 3*BSTG)*4)
template<bool GATHER, bool B8, bool PACKB>
__global__ __launch_bounds__(256,2) void gemm_dual(
    GS s1, GS s2, int ysplit, int lda, int ldb, int N, int K)
{
    extern __shared__ float dsm[];
    float* Asm = dsm;            // 3 x [128][36]
    float* Bsm = dsm + 3*ASTG;   // 3 x [32][136]
    int tid = threadIdx.x;
    int lane = tid & 31, warp = tid >> 5;
    int wm = warp >> 2, wn = warp & 3;
    bool side2 = ((int)blockIdx.y >= ysplit);
    const float* A_   = side2 ? s2.A    : s1.A;
    const int*   idx_ = side2 ? s2.idx  : s1.idx;
    const float* Bm_  = side2 ? s2.Bm   : s1.Bm;
    const float* bias = side2 ? s2.bias : s1.bias;
    float*       C    = side2 ? s2.C    : s1.C;
    int M    = side2 ? s2.M    : s1.M;
    int ldc  = side2 ? s2.ldc  : s1.ldc;
    int store= side2 ? s2.store: s1.store;
    int by = (int)blockIdx.y - (side2 ? ysplit : 0);
    int m0 = by*128, n0 = blockIdx.x*128;
    int nk = (K + 31) >> 5;
    int r8 = lane>>2, q4 = lane&3;

    // A: 4 chunks/thread, rows r_u = (tid>>3) + 32u, off (tid&7)*4
    int arb = tid >> 3, aoff = (tid & 7)*4;
    const float* ArowP[4];
    bool mok[4];
    #pragma unroll
    for (int u = 0; u < 4; u++){
        int r = arb + 32*u;
        mok[u] = (m0 + r) < M;
        long g = GATHER ? (long)idx_[m0 + (mok[u] ? r : 0)] : (long)(m0 + (mok[u] ? r : 0));
        ArowP[u] = A_ + g*(long)lda;
    }
    // B16: rows (tid>>5)+8u, off (tid&31)*4.  B8: rows (tid>>6)+4u, off2 (tid&63)*2
    int brb16 = tid >> 5, boff16 = (tid & 31)*4;
    int brb8  = tid >> 6, boff8  = (tid & 63)*2;

    auto issue = [&](int kt, int buf){
        int k0 = kt*32;
        float* Ab = Asm + buf*ASTG;
        #pragma unroll
        for (int u = 0; u < 4; u++){
            int r = arb + 32*u;
            cpa16(sptr(Ab + r*36 + aoff), ArowP[u] + k0 + aoff,
                  mok[u] && (k0 + aoff) < K);
        }
        float* Bb = Bsm + buf*BSTG;
        if (B8){
            #pragma unroll
            for (int u = 0; u < 8; u++){
                int r = brb8 + 4*u;
                cpa8(sptr(Bb + r*136 + boff8),
                     Bm_ + (size_t)(k0+r)*ldb + n0 + boff8,
                     (k0+r) < K && (n0+boff8) < N);
            }
        } else {
            #pragma unroll
            for (int u = 0; u < 4; u++){
                int r = brb16 + 8*u;
                cpa16(sptr(Bb + r*136 + boff16),
                      Bm_ + (size_t)(k0+r)*ldb + n0 + boff16,
                      (k0+r) < K && (n0+boff16) < N);
            }
        }
        CP_COMMIT();
    };

    float acc[4][4][4] = {};

    issue(0,0);
    if (nk > 1) issue(1,1);

    int buf = 0;
    for (int kt = 0; kt < nk; kt++){
        if (kt >= nk-1) CP_WAIT0(); else CP_WAIT1();
        __syncthreads();
        if (kt+2 < nk) issue(kt+2, buf == 0 ? 2 : buf-1);
        const float* Ab2 = Asm + buf*ASTG;
        const float* Bb2 = Bsm + buf*BSTG;
        #pragma unroll
        for (int kb=0; kb<4; kb++){
            int ko = kb*8;
            unsigned af[4][4], bf[4][2];
            #pragma unroll
            for (int mt=0; mt<4; mt++){
                int rb = wm*64 + mt*16;
                af[mt][0] = __float_as_uint(Ab2[(rb+r8  )*36 + ko+q4  ]);
                af[mt][1] = __float_as_uint(Ab2[(rb+r8+8)*36 + ko+q4  ]);
                af[mt][2] = __float_as_uint(Ab2[(rb+r8  )*36 + ko+q4+4]);
                af[mt][3] = __float_as_uint(Ab2[(rb+r8+8)*36 + ko+q4+4]);
            }
            if (PACKB){
                float4 b0 = *(const float4*)&Bb2[(ko+q4  )*136 + wn*32 + r8*4];
                float4 b1 = *(const float4*)&Bb2[(ko+q4+4)*136 + wn*32 + r8*4];
                bf[0][0]=__float_as_uint(b0.x); bf[1][0]=__float_as_uint(b0.y);
                bf[2][0]=__float_as_uint(b0.z); bf[3][0]=__float_as_uint(b0.w);
                bf[0][1]=__float_as_uint(b1.x); bf[1][1]=__float_as_uint(b1.y);
                bf[2][1]=__float_as_uint(b1.z); bf[3][1]=__float_as_uint(b1.w);
            } else {
                #pragma unroll
                for (int nt=0; nt<4; nt++){
                    int nb = wn*32 + nt*8;
                    bf[nt][0] = __float_as_uint(Bb2[(ko+q4  )*136 + nb+r8]);
                    bf[nt][1] = __float_as_uint(Bb2[(ko+q4+4)*136 + nb+r8]);
                }
            }
            #pragma unroll
            for (int mt=0;mt<4;mt++)
                #pragma unroll
                for (int nt=0;nt<4;nt++)
                    mma8(acc[mt][nt], af[mt], bf[nt]);
        }
        buf = (buf == 2) ? 0 : buf+1;
    }

    #pragma unroll
    for (int mt=0;mt<4;mt++){
        int row = m0 + wm*64 + mt*16 + r8;
        #pragma unroll
        for (int nt=0;nt<4;nt++){
            int col = n0 + wn*32 + nt*8 + q4*2;
            const float* cc = acc[mt][nt];
            #pragma unroll
            for (int j=0;j<2;j++){
                int n = col + j;
                if (n >= N) continue;
                float bb = bias ? bias[n] : 0.f;
                float v0 = cc[j] + bb, v1 = cc[2+j] + bb;
                if (store == 0){
                    if (row < M)   C[(size_t)row*ldc + n] = v0;
                    if (row+8 < M) C[(size_t)(row+8)*ldc + n] = v1;
                } else {
                    int img = row >> 7;
                    C[((size_t)img*Cc + n)*DLn + (row & 127)] = v0;
                    C[((size_t)img*Cc + n)*DLn + ((row+8) & 127)] = v1;
                }
            }
        }
    }
}

// ---------------- persistent LSTM: R12 (packed Bs, coalesced As) ------------
#define LSTM_BS_W  (256*136)
#define LSTM_AS_W  (32*260)
#define LSTM_XS_W  (32*132)
#define LSTM_SMEM  ((LSTM_BS_W + LSTM_AS_W + LSTM_XS_W)*4)
__global__ __cluster_dims__(8,1,1) __launch_bounds__(256,1) void lstm_persist(
    const float* __restrict__ xgq, const float* __restrict__ Whq, float* __restrict__ encq,
    const float* __restrict__ xgd, const float* __restrict__ Whd, float* __restrict__ encd)
{
    extern __shared__ unsigned smbuf[];
    unsigned* Bs = smbuf;
    float* Bsf = (float*)Bs;
    float* As = (float*)(smbuf + LSTM_BS_W);
    float* xs = As + LSTM_AS_W;
    int tid = threadIdx.x;
    int lane = tid & 31, warp = tid >> 5;
    int r8 = lane >> 2, q4 = lane & 3;
    int wm = warp & 1, wn = warp >> 1;
    int cid = blockIdx.x >> 3, hb = blockIdx.x & 7;
    const float* xg; const float* Whh; float* enc; int T, n0;
    if (cid == 0){ xg = xgq; Whh = Whq; enc = encq; T = QLn; n0 = 0; }
    else        { xg = xgd; Whh = Whd; enc = encd; T = DLn; n0 = (cid-1)*32; }
    int h0 = hb * 32;

    for (int idx = tid; idx < 128*256; idx += 256){
        int p = idx >> 8, k = idx & 255;
        int p32 = p & 31;
        int j = (p & ~31) | (((p32 & 3) << 3) | (p32 >> 2));   // nt*8 + r8
        int r = ((j & 3) << 8) + h0 + (j >> 2);
        Bs[k*136 + p] = __float_as_uint(Whh[(size_t)r*Hh + k]);
    }

    auto issueXS = [&](int t){
        #pragma unroll
        for (int u = 0; u < 4; u++){
            int ch = tid + 256*u;
            int m  = ch >> 5;
            int g  = (ch >> 3) & 3;
            int o4 = (ch & 7) * 4;
            const float* src = xg + ((size_t)(n0+m)*T + t)*G4 + g*256 + h0 + o4;
            cpa16(sptr(xs + m*132 + g*32 + o4), src, true);
        }
        CP_COMMIT();
    };
    auto issueAS = [&](int t){
        #pragma unroll
        for (int u = 0; u < 8; u++){
            int ch = tid + 256*u;
            int m  = ch >> 6;
            int k4 = (ch & 63) * 4;
            cpa16(sptr(As + m*260 + k4), enc + ((size_t)(n0+m)*T + (t-1))*Hh + k4, true);
        }
        CP_COMMIT();
    };

    issueXS(0);
    float creg[4] = {0.f, 0.f, 0.f, 0.f};
    int rb = wm*16;

    for (int t = 0; t < T; t++){
        if (t == 0){
            for (int idx = tid; idx < 32*256; idx += 256)
                As[(idx >> 8)*260 + (idx & 255)] = 0.f;
        } else {
            issueAS(t);
        }
        CP_WAIT0();
        __syncthreads();

        float acc[4][4] = {};
        #pragma unroll 4
        for (int ko = 0; ko < 256; ko += 8){
            unsigned af[4];
            af[0] = __float_as_uint(As[(rb+r8  )*260 + ko+q4  ]);
            af[1] = __float_as_uint(As[(rb+r8+8)*260 + ko+q4  ]);
            af[2] = __float_as_uint(As[(rb+r8  )*260 + ko+q4+4]);
            af[3] = __float_as_uint(As[(rb+r8+8)*260 + ko+q4+4]);
            float4 b0 = *(const float4*)&Bsf[(ko+q4  )*136 + wn*32 + r8*4];
            float4 b1 = *(const float4*)&Bsf[(ko+q4+4)*136 + wn*32 + r8*4];
            unsigned bf0[2] = {__float_as_uint(b0.x), __float_as_uint(b1.x)};
            unsigned bf1[2] = {__float_as_uint(b0.y), __float_as_uint(b1.y)};
            unsigned bf2[2] = {__float_as_uint(b0.z), __float_as_uint(b1.z)};
            unsigned bf3[2] = {__float_as_uint(b0.w), __float_as_uint(b1.w)};
            mma8(acc[0], af, bf0);
            mma8(acc[1], af, bf1);
            mma8(acc[2], af, bf2);
            mma8(acc[3], af, bf3);
        }

        bool odd = (q4 & 1);
        int m  = rb + r8 + (odd ? 8 : 0);
        #pragma unroll
        for (int nt = 0; nt < 4; nt++){
            float a0 = acc[nt][0], a1 = acc[nt][1], a2 = acc[nt][2], a3 = acc[nt][3];
            float e0 = __shfl_xor_sync(0xFFFFFFFFu, a0, 1);
            float e1 = __shfl_xor_sync(0xFFFFFFFFu, a1, 1);
            float e2 = __shfl_xor_sync(0xFFFFFFFFu, a2, 1);
            float e3 = __shfl_xor_sync(0xFFFFFFFFu, a3, 1);
            float g0 = odd ? e2 : a0;
            float g1 = odd ? e3 : a1;
            float g2 = odd ? a2 : e0;
            float g3 = odd ? a3 : e1;
            int hp = wn*8 + nt*2 + (q4 >> 1);
            const float* xr = xs + m*132 + hp;
            float gi = g0 + xr[0];
            float gf = g1 + xr[32];
            float gg = g2 + xr[64];
            float go = g3 + xr[96];
            float cv = sigf(gf)*creg[nt] + sigf(gi)*tha(gg);
            creg[nt] = cv;
            enc[((size_t)(n0+m)*T + t)*Hh + h0 + hp] = sigf(go)*tha(cv);
        }
        __syncthreads();
        if (t+1 < T) issueXS(t+1);
        CLUSTER_ARRIVE();
        CLUSTER_WAIT();
    }
}

// ---------------- conv stage 1 (merged 3 convs via blockIdx.y) ----------------
__global__ void s_k(const float* __restrict__ c1W, const float* __restrict__ c2W,
                    const float* __restrict__ c3W,
                    float* __restrict__ s3, float* __restrict__ s5, float* __restrict__ s7)
{
    int z = blockIdx.y;
    int KW = 3 + 2*z, KP = 152 + 100*z;
    const float* cW = (z==0) ? c1W : (z==1) ? c2W : c3W;
    float* s = (z==0) ? s3 : (z==1) ? s5 : s7;
    long total = (long)Bq*NFc*QLn*KP;
    long i = (long)blockIdx.x*blockDim.x + threadIdx.x;
    if (i >= total) return;
    int kk = (int)(i % KP);
    long r = i / KP;
    int q  = (int)(r % QLn); r /= QLn;
    int o  = (int)(r % NFc);
    int b  = (int)(r / NFc);
    float v = 0.f;
    if (kk < Cc*KW){
        int dd = kk / Cc, c = kk - dd*Cc;
        #pragma unroll
        for (int dq = 0; dq < 3; dq++){
            int qq = q + dq - 1;
            if (qq >= 0 && qq < QLn)
                v += cW[(((size_t)o*51 + c)*3 + dq)*KW + dd] * g_pq[((size_t)b*QLn + qq)*Cc + c];
        }
    }
    s[i] = v;
}

// ---------------- conv stage 2: merged (blockIdx.z), resident-B, 3-stage A ----
#define CONV_DSM ((3*2560 + 50*132)*4)
__global__ __launch_bounds__(256,2) void convgemm_k(
    const float* __restrict__ sA3, const float* __restrict__ sA5, const float* __restrict__ sA7,
    const float* __restrict__ c1W, const float* __restrict__ c1b,
    const float* __restrict__ c2W, const float* __restrict__ c2b,
    const float* __restrict__ c3W, const float* __restrict__ c3b,
    const int* __restrict__ bqtok, const int* __restrict__ bdtok,
    const float* __restrict__ alpha)
{
    int z = blockIdx.z;
    const int KW = 3 + 2*z, KP = 152 + 100*z, PW = KW >> 1, OCB = z*50;
    const int nk = (KP + 15) >> 4;
    const float* sA = (z==0) ? sA3 : (z==1) ? sA5 : sA7;
    const float* cW = (z==0) ? c1W : (z==1) ? c2W : c3W;
    const float* cb = (z==0) ? c1b : (z==1) ? c2b : c3b;
    extern __shared__ float dsm[];
    float* Asm = dsm;              // 3 stages x [128][20]
    float* pdt = dsm + 3*2560;     // [50][132]
    __shared__ float ems[18][136];
    __shared__ float wem[8][21];
    __shared__ int qt[16], dt[128], s_any;
    int tid = threadIdx.x;
    int lane = tid & 31, warp = tid >> 5;
    int wm = warp >> 2, wn = warp & 3;
    int img = blockIdx.y, b = img / Dn;
    int m0 = blockIdx.x*128, obase = m0 >> 4;
    int r8 = lane>>2, q4 = lane&3;

    const float* Pd = &g_pdT[(size_t)img*Cc*DLn];
    int arow = tid >> 1, acp = (tid & 1)*8;
    bool mok = (m0 + arow) < 800;
    const float* Arow = sA + ((size_t)b*800 + (mok ? m0+arow : 0))*KP;

    auto issueA = [&](int kt, int buf){
        int k0 = kt*16;
        unsigned d = sptr(Asm + buf*2560 + arow*20 + acp);
        cpa16(d,    Arow + k0 + acp,     mok && (k0+acp)   < KP);
        cpa16(d+16, Arow + k0 + acp + 4, mok && (k0+acp+4) < KP);
    };

    for (int ch = tid; ch < 1600; ch += 256){
        int row = ch >> 5, off = (ch & 31) * 4;
        cpa16(sptr(pdt + row*132 + off), Pd + row*128 + off, true);
    }
    issueA(0,0); CP_COMMIT();
    issueA(1,1); CP_COMMIT();

    if (tid == 0) s_any = 0;
    if (tid < 16) qt[tid] = bqtok[b*QLn + tid];
    if (tid < 128) dt[tid] = bdtok[(size_t)img*DLn + tid];
    if (tid < 8*3*KW){
        int ol = tid/(3*KW), rr = tid%(3*KW);
        int o = obase + ol;
        wem[ol][rr] = (o < NFc) ? cW[(((size_t)o*51 + 50)*3 + rr/KW)*KW + rr%KW] : 0.f;
    }
    __syncthreads();
    float al = alpha[0];
    for (int e = tid; e < 18*136; e += 256){
        int qi = e/136, dj = e%136;
        int q = qi-1, dl = dj-3;
        float v = 0.f;
        if (q >= 0 && q < QLn && dl >= 0 && dl < DLn && qt[q] == dt[dl]){ v = al; s_any = 1; }
        ems[qi][dj] = v;
    }

    float acc[4][4][4] = {};
    int buf = 0;
    for (int kt = 0; kt < nk; kt++){
        if (kt >= nk-1) CP_WAIT0(); else CP_WAIT1();
        __syncthreads();
        if (kt+2 < nk){ issueA(kt+2, buf == 0 ? 2 : buf-1); CP_COMMIT(); }
        const float* Ab2 = Asm + buf*2560;
        #pragma unroll
        for (int kb=0; kb<2; kb++){
            int ko = kb*8;
            int ka = kt*16 + ko + q4;
            int k2 = ka + 4;
            int dda = ka/Cc, ca = ka - dda*Cc;
            int ddb = k2/Cc, cbb = k2 - ddb*Cc;
            unsigned af[4][4], bf[4][2];
            #pragma unroll
            for (int mt=0; mt<4; mt++){
                int rb = wm*64 + mt*16;
                af[mt][0] = __float_as_uint(Ab2[(rb+r8  )*20 + ko+q4  ]);
                af[mt][1] = __float_as_uint(Ab2[(rb+r8+8)*20 + ko+q4  ]);
                af[mt][2] = __float_as_uint(Ab2[(rb+r8  )*20 + ko+q4+4]);
                af[mt][3] = __float_as_uint(Ab2[(rb+r8+8)*20 + ko+q4+4]);
            }
            #pragma unroll
            for (int nt=0; nt<4; nt++){
                int col = wn*32 + nt*8 + r8;
                int sa = col + dda - PW;
                int sb = col + ddb - PW;
                bf[nt][0] = ((unsigned)sa < 128u) ? __float_as_uint(pdt[ca*132 + sa]) : 0u;
                bf[nt][1] = ((unsigned)sb < 128u) ? __float_as_uint(pdt[cbb*132 + sb]) : 0u;
            }
            #pragma unroll
            for (int mt=0;mt<4;mt++)
                #pragma unroll
                for (int nt=0;nt<4;nt++)
                    mma8(acc[mt][nt], af[mt], bf[nt]);
        }
        buf = (buf == 2) ? 0 : buf+1;
    }

    int any = s_any;
    #pragma unroll
    for (int mt=0;mt<4;mt++){
        int row = m0 + wm*64 + mt*16;
        if (row >= 800) continue;
        int o = row >> 4, ol = o - obase;
        float bias = cb[o];
        #pragma unroll
        for (int rr=0; rr<2; rr++){
            int q = r8 + rr*8;
            #pragma unroll
            for (int nt=0;nt<4;nt++){
                int col = wn*32 + nt*8 + q4*2;
                #pragma unroll
                for (int j=0;j<2;j++){
                    int dl = col + j;
                    float v = acc[mt][nt][rr*2 + j] + bias;
                    if (any){
                        for (int dq = 0; dq < 3; dq++)
                            for (int dd = 0; dd < KW; dd++)
                                v += wem[ol][dq*KW+dd] * ems[q+dq][dl+dd+3-PW];
                    }
                    v = fmaxf(v, 0.f);
                    g_f[(((size_t)img*150 + OCB + o)*QLn + q)*DLn + dl] = v;
                }
            }
        }
    }
}

// ---------------- 1x1 conv + maxpool + linear (tf32 mma) ----------------
#define SCORE_DSM ((3*8*264 + 152*36)*4)
__global__ __launch_bounds__(256,2) void score_k(
    const float* __restrict__ ccW, const float* __restrict__ ccb,
    const float* __restrict__ outW, const float* __restrict__ outb,
    float* __restrict__ out)
{
    extern __shared__ float dsm[];
    float* fs = dsm;               // 3 stages x [8][264]
    float* Ws = dsm + 3*8*264;     // [152][36]: Ws[k*36+m]
    __shared__ float red[32][8];
    __shared__ float part[32];
    int img = blockIdx.x, tid = threadIdx.x;
    int lane = tid & 31, warp = tid >> 5;
    int r8 = lane >> 2, q4 = lane & 3;

    for (int idx = tid; idx < 152*32; idx += 256){
        int m = idx & 31, k = idx >> 5;
        Ws[k*36 + m] = (m < MFc && k < 150) ? ccW[m*150 + k] : 0.f;
    }

    const float* fimg = &g_f[(size_t)img*150*2048];
    auto issue = [&](int kt, int pch, int buf){
        #pragma unroll
        for (int h = 0; h < 2; h++){
            int ch = tid + 256*h;
            int row = ch >> 6, off = (ch & 63)*4;
            int kr = kt*8 + row;
            cpa16(sptr(fs + buf*2112 + row*264 + off),
                  fimg + (size_t)kr*2048 + pch*256 + off, kr < 150);
        }
        CP_COMMIT();
    };

    float bb0 = (r8      < MFc) ? ccb[r8]      : 0.f;
    float bb0b= (r8+8    < MFc) ? ccb[r8+8]    : 0.f;
    float maxv[2][2] = {{-1e30f,-1e30f},{-1e30f,-1e30f}};
    __syncthreads();   // Ws ready

    for (int pch = 0; pch < 8; pch++){
        float acc[2][4][4] = {};
        if (pch) __syncthreads();        // all reads of fs from prev pch done
        issue(0, pch, 0);
        issue(1, pch, 1);
        int buf = 0;
        for (int kt = 0; kt < 19; kt++){
            if (kt >= 17) CP_WAIT0(); else CP_WAIT1();
            __syncthreads();
            if (kt+2 < 19) issue(kt+2, pch, buf == 0 ? 2 : buf-1);
            const float* fb2 = fs + buf*2112;
            unsigned af[2][4];
            #pragma unroll
            for (int mt=0; mt<2; mt++){
                int mb = mt*16;
                af[mt][0] = __float_as_uint(Ws[(kt*8+q4  )*36 + mb+r8]);
                af[mt][1] = __float_as_uint(Ws[(kt*8+q4  )*36 + mb+r8+8]);
                af[mt][2] = __float_as_uint(Ws[(kt*8+q4+4)*36 + mb+r8]);
                af[mt][3] = __float_as_uint(Ws[(kt*8+q4+4)*36 + mb+r8+8]);
            }
            #pragma unroll
            for (int nt=0; nt<4; nt++){
                int nb = warp*32 + nt*8;
                unsigned bf[2];
                bf[0] = __float_as_uint(fb2[(q4  )*264 + nb+r8]);
                bf[1] = __float_as_uint(fb2[(q4+4)*264 + nb+r8]);
                #pragma unroll
                for (int mt=0; mt<2; mt++)
                    mma8(acc[mt][nt], af[mt], bf);
            }
            buf = (buf == 2) ? 0 : buf+1;
        }
        #pragma unroll
        for (int mt=0; mt<2; mt++){
            float b0 = (mt==0) ? bb0  : ((16+r8 < MFc) ? ccb[16+r8] : 0.f);
            float b1 = (mt==0) ? bb0b : 0.f;
            #pragma unroll
            for (int nt=0; nt<4; nt++){
                float* cc = acc[mt][nt];
                maxv[mt][0] = fmaxf(maxv[mt][0], fmaxf(cc[0], cc[1]) + b0);
                maxv[mt][1] = fmaxf(maxv[mt][1], fmaxf(cc[2], cc[3]) + b1);
            }
        }
    }
    #pragma unroll
    for (int mt=0; mt<2; mt++)
        #pragma unroll
        for (int h=0; h<2; h++){
            float v = maxv[mt][h];
            v = fmaxf(v, __shfl_xor_sync(0xFFFFFFFFu, v, 1));
            v = fmaxf(v, __shfl_xor_sync(0xFFFFFFFFu, v, 2));
            maxv[mt][h] = v;
        }
    if (q4 == 0){
        #pragma unroll
        for (int mt=0; mt<2; mt++)
            #pragma unroll
            for (int h=0; h<2; h++)
                red[mt*16 + h*8 + r8][warp] = maxv[mt][h];
    }
    __syncthreads();
    if (tid < 32){
        float m = red[tid][0];
        #pragma unroll
        for (int w = 1; w < 8; w++) m = fmaxf(m, red[tid][w]);
        part[tid] = (tid < MFc) ? m * outW[tid] : 0.f;
    }
    __syncthreads();
    if (tid == 0){
        float sc = outb[0];
        #pragma unroll
        for (int mf = 0; mf < MFc; mf++) sc += part[mf];
        out[img] = sc;
    }
}

// ---------------- launch ----------------
extern "C" void kernel_launch(void* const* d_in, const int* in_sizes, int n_in,
                              void* d_out, int out_size)
{
    const int* bqtok = nullptr; const int* bdtok = nullptr;
    for (int i = 0; i < 4; i++){
        if (in_sizes[i] == NTQ)      bqtok = (const int*)d_in[i];
        else if (in_sizes[i] == NTD) bdtok = (const int*)d_in[i];
    }
    const float* emb    = (const float*)d_in[4];
    const float* projW  = (const float*)d_in[5];
    const float* projb  = (const float*)d_in[6];
    const float* qWih   = (const float*)d_in[7];
    const float* qWhh   = (const float*)d_in[8];
    const float* qbih   = (const float*)d_in[9];
    const float* qbhh   = (const float*)d_in[10];
    const float* dWih   = (const float*)d_in[11];
    const float* dWhh   = (const float*)d_in[12];
    const float* dbih   = (const float*)d_in[13];
    const float* dbhh   = (const float*)d_in[14];
    const float* qpW    = (const float*)d_in[15];
    const float* qpb    = (const float*)d_in[16];
    const float* dpW    = (const float*)d_in[17];
    const float* dpb    = (const float*)d_in[18];
    const float* alpha  = (const float*)d_in[19];
    const float* c1W    = (const float*)d_in[20];
    const float* c1b    = (const float*)d_in[21];
    const float* c2W    = (const float*)d_in[22];
    const float* c2b    = (const float*)d_in[23];
    const float* c3W    = (const float*)d_in[24];
    const float* c3b    = (const float*)d_in[25];
    const float* ccW    = (const float*)d_in[26];
    const float* ccb    = (const float*)d_in[27];
    const float* outW   = (const float*)d_in[28];
    const float* outb   = (const float*)d_in[29];
    float* out = (float*)d_out;

    float *pXq,*pXd,*pxgq,*pxgd,*pencq,*pencd,*ppq,*ppdT,*ps3,*ps5,*ps7,*pqb,*pdb,*pWTq,*pWTd;
    cudaGetSymbolAddress((void**)&pXq,  g_Xq);
    cudaGetSymbolAddress((void**)&pXd,  g_Xd);
    cudaGetSymbolAddress((void**)&pxgq, g_xgq);
    cudaGetSymbolAddress((void**)&pxgd, g_xgd);
    cudaGetSymbolAddress((void**)&pencq,g_encq);
    cudaGetSymbolAddress((void**)&pencd,g_encd);
    cudaGetSymbolAddress((void**)&ppq,  g_pq);
    cudaGetSymbolAddress((void**)&ppdT, g_pdT);
    cudaGetSymbolAddress((void**)&ps3,  g_s3);
    cudaGetSymbolAddress((void**)&ps5,  g_s5);
    cudaGetSymbolAddress((void**)&ps7,  g_s7);
    cudaGetSymbolAddress((void**)&pqb,  g_qb);
    cudaGetSymbolAddress((void**)&pdb,  g_db);
    cudaGetSymbolAddress((void**)&pWTq, g_WTq);
    cudaGetSymbolAddress((void**)&pWTd, g_WTd);

    cudaFuncSetAttribute(lstm_persist, cudaFuncAttributeMaxDynamicSharedMemorySize, LSTM_SMEM);
    cudaFuncSetAttribute(gemm_dual<true,false,false>, cudaFuncAttributeMaxDynamicSharedMemorySize, GEMM_DSM);
    cudaFuncSetAttribute(gemm_dual<false,false,true>, cudaFuncAttributeMaxDynamicSharedMemorySize, GEMM_DSM);
    cudaFuncSetAttribute(gemm_dual<false,true,false>, cudaFuncAttributeMaxDynamicSharedMemorySize, GEMM_DSM);
    cudaFuncSetAttribute(convgemm_k, cudaFuncAttributeMaxDynamicSharedMemorySize, CONV_DSM);
    cudaFuncSetAttribute(score_k, cudaFuncAttributeMaxDynamicSharedMemorySize, SCORE_DSM);

    bias_sum_k<<<4,256>>>(qbih,qbhh,dbih,dbhh);
    wt_k<<<dim3(10,32,2),dim3(32,8)>>>(qWih, dWih);

    // embed + proj (dual): X = emb[tok] @ projW + projb
    { GS s1{emb, bqtok, projW, projb, pXq, NTQ, Ff, 0};
      GS s2{emb, bdtok, projW, projb, pXd, NTD, Ff, 0};
      gemm_dual<true,false,false><<<dim3(3,324),256,GEMM_DSM>>>(s1,s2,4, Ff,Ff, Ff,Ff); }

    // input gates (dual, packed WT): xg = X @ Wih^T + (bih+bhh)
    { GS s1{pXq, nullptr, pWTq, pqb, pxgq, NTQ, G4, 0};
      GS s2{pXd, nullptr, pWTd, pdb, pxgd, NTD, G4, 0};
      gemm_dual<false,false,true><<<dim3(8,324),256,GEMM_DSM>>>(s1,s2,4, Ff,G4, G4,Ff); }

    // persistent LSTMs (merged: 11 clusters x 8 blocks)
    lstm_persist<<<88,256,LSTM_SMEM>>>(pxgq, qWhh, pencq, pxgd, dWhh, pencd);

    // projections (dual, 8B-async B): pq [512,50]; pdT per image
    { GS s1{pencq, nullptr, qpW, qpb, ppq,  NTQ, Cc, 0};
      GS s2{pencd, nullptr, dpW, dpb, ppdT, NTD, 0,  1};
      gemm_dual<false,true,false><<<dim3(1,324),256,GEMM_DSM>>>(s1,s2,4, Hh,Cc, Cc,Hh); }

    // conv stage 1 (merged)
    {
        long t7 = (long)Bq*NFc*QLn*352;
        s_k<<<dim3((unsigned)((t7+255)/256),3),256>>>(c1W,c2W,c3W, ps3,ps5,ps7);
    }
    // conv stage 2 (merged z-dispatch)
    convgemm_k<<<dim3(7,BD,3),256,CONV_DSM>>>(ps3,ps5,ps7, c1W,c1b, c2W,c2b, c3W,c3b,
                                              bqtok, bdtok, alpha);

    // 1x1 conv + maxpool + linear (tf32 mma)
    score_k<<<BD,256,SCORE_DSM>>>(ccW, ccb, outW, outb, out);
}

// round 14
// speedup vs baseline: 1.1296x; 1.0321x over previous
#include <cuda_runtime.h>
#include <math.h>

// ---------------- problem constants ----------------
#define Bq  32
#define Dn  10
#define QLn 16
#define DLn 128
#define BD  320
#define Ff  300
#define Hh  256
#define G4  1024
#define Cc  50
#define NFc 50
#define MFc 20
#define NTQ (Bq*QLn)      // 512
#define NTD (BD*DLn)      // 40960

// ---------------- device scratch ----------------
__device__ float g_Xq[NTQ*Ff];
__device__ float g_Xd[(size_t)NTD*Ff];
__device__ float g_xgq[(size_t)NTQ*G4];
__device__ float g_xgd[(size_t)NTD*G4];
__device__ float g_encq[NTQ*Hh];
__device__ float g_encd[(size_t)NTD*Hh];
__device__ float g_pq[NTQ*Cc];
__device__ float g_pdT[(size_t)BD*Cc*DLn];
__device__ float g_s3[(size_t)Bq*NFc*QLn*152 + 16];
__device__ float g_s5[(size_t)Bq*NFc*QLn*252 + 16];
__device__ float g_s7[(size_t)Bq*NFc*QLn*352 + 16];
__device__ float g_f[(size_t)BD*150*QLn*DLn];
__device__ float g_qb[G4];
__device__ float g_db[G4];
__device__ float g_WTq[Ff*G4];     // Wih^T, column-permuted for packed loads
__device__ float g_WTd[Ff*G4];

__device__ __forceinline__ float tha(float x){
    float y; asm("tanh.approx.f32 %0, %1;" : "=f"(y) : "f"(x)); return y;
}
__device__ __forceinline__ float sigf(float x){ return fmaf(tha(0.5f*x), 0.5f, 0.5f); }

__device__ __forceinline__ void mma8(float* c, const unsigned* a, const unsigned* b){
    asm volatile("mma.sync.aligned.m16n8k8.row.col.f32.tf32.tf32.f32 "
        "{%0,%1,%2,%3}, {%4,%5,%6,%7}, {%8,%9}, {%0,%1,%2,%3};"
        : "+f"(c[0]),"+f"(c[1]),"+f"(c[2]),"+f"(c[3])
        : "r"(a[0]),"r"(a[1]),"r"(a[2]),"r"(a[3]), "r"(b[0]),"r"(b[1]));
}
__device__ __forceinline__ unsigned sptr(const void* p){
    return (unsigned)__cvta_generic_to_shared(p);
}
__device__ __forceinline__ void cpa16(unsigned dst, const void* src, bool pred){
    int sz = pred ? 16 : 0;
    asm volatile("cp.async.cg.shared.global [%0], [%1], 16, %2;" :: "r"(dst), "l"(src), "r"(sz));
}
__device__ __forceinline__ void cpa8(unsigned dst, const void* src, bool pred){
    int sz = pred ? 8 : 0;
    asm volatile("cp.async.ca.shared.global [%0], [%1], 8, %2;" :: "r"(dst), "l"(src), "r"(sz));
}
#define CP_COMMIT() asm volatile("cp.async.commit_group;")
#define CP_WAIT0()  asm volatile("cp.async.wait_group 0;")
#define CP_WAIT1()  asm volatile("cp.async.wait_group 1;")
#define CLUSTER_ARRIVE() asm volatile("barrier.cluster.arrive.aligned;" ::: "memory")
#define CLUSTER_WAIT()   asm volatile("barrier.cluster.wait.aligned;" ::: "memory")

// ---------------- bias precombine ----------------
__global__ void bias_sum_k(const float* __restrict__ qb1, const float* __restrict__ qb2,
                           const float* __restrict__ db1, const float* __restrict__ db2)
{
    int t = blockIdx.x*blockDim.x + threadIdx.x;
    if (t < G4){ g_qb[t] = qb1[t]+qb2[t]; g_db[t] = db1[t]+db2[t]; }
}

// ---------------- Wih transpose: smem-tiled, coalesced both sides ----------
__global__ void wt_k(const float* __restrict__ qW, const float* __restrict__ dW)
{
    __shared__ float t[32][33];
    const float* src = blockIdx.z ? dW : qW;
    float* dst = blockIdx.z ? g_WTd : g_WTq;
    int k0 = blockIdx.x*32, n0 = blockIdx.y*32;
    int tx = threadIdx.x, ty = threadIdx.y;     // block (32,8)
    #pragma unroll
    for (int dy = 0; dy < 32; dy += 8){
        int n = n0 + ty + dy, k = k0 + tx;
        t[ty+dy][tx] = (k < Ff) ? src[(size_t)n*Ff + k] : 0.f;
    }
    __syncthreads();
    #pragma unroll
    for (int dy = 0; dy < 32; dy += 8){
        int k = k0 + ty + dy;
        int n = n0 + tx;
        int np = (n & ~31) | ((n & 7)*4 + ((n >> 3) & 3));
        if (k < Ff) dst[(size_t)k*G4 + np] = t[tx][ty+dy];
    }
}

// ---------------- dual-side 3-stage pipelined tf32 GEMM, k-step 32 ----------
struct GS {
    const float* A; const int* idx; const float* Bm; const float* bias;
    float* C; int M; int ldc; int store;   // store 0: C[m*ldc+n]; 1: pdT layout
};
#define ASTG 4608            // 128 x 36 floats per stage
#define BSTG 4352            // 32 x 136 floats per stage
#define GEMM_DSM ((3*ASTG + 3*BSTG)*4)
template<bool GATHER, bool B8, bool PACKB>
__global__ __launch_bounds__(256,2) void gemm_dual(
    GS s1, GS s2, int ysplit, int lda, int ldb, int N, int K)
{
    extern __shared__ float dsm[];
    float* Asm = dsm;            // 3 x [128][36]
    float* Bsm = dsm + 3*ASTG;   // 3 x [32][136]
    int tid = threadIdx.x;
    int lane = tid & 31, warp = tid >> 5;
    int wm = warp >> 2, wn = warp & 3;
    bool side2 = ((int)blockIdx.y >= ysplit);
    const float* A_   = side2 ? s2.A    : s1.A;
    const int*   idx_ = side2 ? s2.idx  : s1.idx;
    const float* Bm_  = side2 ? s2.Bm   : s1.Bm;
    const float* bias = side2 ? s2.bias : s1.bias;
    float*       C    = side2 ? s2.C    : s1.C;
    int M    = side2 ? s2.M    : s1.M;
    int ldc  = side2 ? s2.ldc  : s1.ldc;
    int store= side2 ? s2.store: s1.store;
    int by = (int)blockIdx.y - (side2 ? ysplit : 0);
    int m0 = by*128, n0 = blockIdx.x*128;
    int nk = (K + 31) >> 5;
    int r8 = lane>>2, q4 = lane&3;

    int arb = tid >> 3, aoff = (tid & 7)*4;
    const float* ArowP[4];
    bool mok[4];
    #pragma unroll
    for (int u = 0; u < 4; u++){
        int r = arb + 32*u;
        mok[u] = (m0 + r) < M;
        long g = GATHER ? (long)idx_[m0 + (mok[u] ? r : 0)] : (long)(m0 + (mok[u] ? r : 0));
        ArowP[u] = A_ + g*(long)lda;
    }
    int brb16 = tid >> 5, boff16 = (tid & 31)*4;
    int brb8  = tid >> 6, boff8  = (tid & 63)*2;

    auto issue = [&](int kt, int buf){
        int k0 = kt*32;
        float* Ab = Asm + buf*ASTG;
        #pragma unroll
        for (int u = 0; u < 4; u++){
            int r = arb + 32*u;
            cpa16(sptr(Ab + r*36 + aoff), ArowP[u] + k0 + aoff,
                  mok[u] && (k0 + aoff) < K);
        }
        float* Bb = Bsm + buf*BSTG;
        if (B8){
            #pragma unroll
            for (int u = 0; u < 8; u++){
                int r = brb8 + 4*u;
                cpa8(sptr(Bb + r*136 + boff8),
                     Bm_ + (size_t)(k0+r)*ldb + n0 + boff8,
                     (k0+r) < K && (n0+boff8) < N);
            }
        } else {
            #pragma unroll
            for (int u = 0; u < 4; u++){
                int r = brb16 + 8*u;
                cpa16(sptr(Bb + r*136 + boff16),
                      Bm_ + (size_t)(k0+r)*ldb + n0 + boff16,
                      (k0+r) < K && (n0+boff16) < N);
            }
        }
        CP_COMMIT();
    };

    float acc[4][4][4] = {};

    issue(0,0);
    if (nk > 1) issue(1,1);

    int buf = 0;
    for (int kt = 0; kt < nk; kt++){
        if (kt >= nk-1) CP_WAIT0(); else CP_WAIT1();
        __syncthreads();
        if (kt+2 < nk) issue(kt+2, buf == 0 ? 2 : buf-1);
        const float* Ab2 = Asm + buf*ASTG;
        const float* Bb2 = Bsm + buf*BSTG;
        #pragma unroll
        for (int kb=0; kb<4; kb++){
            int ko = kb*8;
            unsigned af[4][4], bf[4][2];
            #pragma unroll
            for (int mt=0; mt<4; mt++){
                int rb = wm*64 + mt*16;
                af[mt][0] = __float_as_uint(Ab2[(rb+r8  )*36 + ko+q4  ]);
                af[mt][1] = __float_as_uint(Ab2[(rb+r8+8)*36 + ko+q4  ]);
                af[mt][2] = __float_as_uint(Ab2[(rb+r8  )*36 + ko+q4+4]);
                af[mt][3] = __float_as_uint(Ab2[(rb+r8+8)*36 + ko+q4+4]);
            }
            if (PACKB){
                float4 b0 = *(const float4*)&Bb2[(ko+q4  )*136 + wn*32 + r8*4];
                float4 b1 = *(const float4*)&Bb2[(ko+q4+4)*136 + wn*32 + r8*4];
                bf[0][0]=__float_as_uint(b0.x); bf[1][0]=__float_as_uint(b0.y);
                bf[2][0]=__float_as_uint(b0.z); bf[3][0]=__float_as_uint(b0.w);
                bf[0][1]=__float_as_uint(b1.x); bf[1][1]=__float_as_uint(b1.y);
                bf[2][1]=__float_as_uint(b1.z); bf[3][1]=__float_as_uint(b1.w);
            } else {
                #pragma unroll
                for (int nt=0; nt<4; nt++){
                    int nb = wn*32 + nt*8;
                    bf[nt][0] = __float_as_uint(Bb2[(ko+q4  )*136 + nb+r8]);
                    bf[nt][1] = __float_as_uint(Bb2[(ko+q4+4)*136 + nb+r8]);
                }
            }
            #pragma unroll
            for (int mt=0;mt<4;mt++)
                #pragma unroll
                for (int nt=0;nt<4;nt++)
                    mma8(acc[mt][nt], af[mt], bf[nt]);
        }
        buf = (buf == 2) ? 0 : buf+1;
    }

    #pragma unroll
    for (int mt=0;mt<4;mt++){
        int row = m0 + wm*64 + mt*16 + r8;
        #pragma unroll
        for (int nt=0;nt<4;nt++){
            int col = n0 + wn*32 + nt*8 + q4*2;
            const float* cc = acc[mt][nt];
            #pragma unroll
            for (int j=0;j<2;j++){
                int n = col + j;
                if (n >= N) continue;
                float bb = bias ? bias[n] : 0.f;
                float v0 = cc[j] + bb, v1 = cc[2+j] + bb;
                if (store == 0){
                    if (row < M)   C[(size_t)row*ldc + n] = v0;
                    if (row+8 < M) C[(size_t)(row+8)*ldc + n] = v1;
                } else {
                    int img = row >> 7;
                    C[((size_t)img*Cc + n)*DLn + (row & 127)] = v0;
                    C[((size_t)img*Cc + n)*DLn + ((row+8) & 127)] = v1;
                }
            }
        }
    }
}

// ---------------- persistent LSTM: R12 (packed Bs, coalesced As) ------------
#define LSTM_BS_W  (256*136)
#define LSTM_AS_W  (32*260)
#define LSTM_XS_W  (32*132)
#define LSTM_SMEM  ((LSTM_BS_W + LSTM_AS_W + LSTM_XS_W)*4)
__global__ __cluster_dims__(8,1,1) __launch_bounds__(256,1) void lstm_persist(
    const float* __restrict__ xgq, const float* __restrict__ Whq, float* __restrict__ encq,
    const float* __restrict__ xgd, const float* __restrict__ Whd, float* __restrict__ encd)
{
    extern __shared__ unsigned smbuf[];
    unsigned* Bs = smbuf;
    float* Bsf = (float*)Bs;
    float* As = (float*)(smbuf + LSTM_BS_W);
    float* xs = As + LSTM_AS_W;
    int tid = threadIdx.x;
    int lane = tid & 31, warp = tid >> 5;
    int r8 = lane >> 2, q4 = lane & 3;
    int wm = warp & 1, wn = warp >> 1;
    int cid = blockIdx.x >> 3, hb = blockIdx.x & 7;
    const float* xg; const float* Whh; float* enc; int T, n0;
    if (cid == 0){ xg = xgq; Whh = Whq; enc = encq; T = QLn; n0 = 0; }
    else        { xg = xgd; Whh = Whd; enc = encd; T = DLn; n0 = (cid-1)*32; }
    int h0 = hb * 32;

    for (int idx = tid; idx < 128*256; idx += 256){
        int p = idx >> 8, k = idx & 255;
        int p32 = p & 31;
        int j = (p & ~31) | (((p32 & 3) << 3) | (p32 >> 2));   // nt*8 + r8
        int r = ((j & 3) << 8) + h0 + (j >> 2);
        Bs[k*136 + p] = __float_as_uint(Whh[(size_t)r*Hh + k]);
    }

    auto issueXS = [&](int t){
        #pragma unroll
        for (int u = 0; u < 4; u++){
            int ch = tid + 256*u;
            int m  = ch >> 5;
            int g  = (ch >> 3) & 3;
            int o4 = (ch & 7) * 4;
            const float* src = xg + ((size_t)(n0+m)*T + t)*G4 + g*256 + h0 + o4;
            cpa16(sptr(xs + m*132 + g*32 + o4), src, true);
        }
        CP_COMMIT();
    };
    auto issueAS = [&](int t){
        #pragma unroll
        for (int u = 0; u < 8; u++){
            int ch = tid + 256*u;
            int m  = ch >> 6;
            int k4 = (ch & 63) * 4;
            cpa16(sptr(As + m*260 + k4), enc + ((size_t)(n0+m)*T + (t-1))*Hh + k4, true);
        }
        CP_COMMIT();
    };

    issueXS(0);
    float creg[4] = {0.f, 0.f, 0.f, 0.f};
    int rb = wm*16;

    for (int t = 0; t < T; t++){
        if (t == 0){
            for (int idx = tid; idx < 32*256; idx += 256)
                As[(idx >> 8)*260 + (idx & 255)] = 0.f;
        } else {
            issueAS(t);
        }
        CP_WAIT0();
        __syncthreads();

        float acc[4][4] = {};
        #pragma unroll 4
        for (int ko = 0; ko < 256; ko += 8){
            unsigned af[4];
            af[0] = __float_as_uint(As[(rb+r8  )*260 + ko+q4  ]);
            af[1] = __float_as_uint(As[(rb+r8+8)*260 + ko+q4  ]);
            af[2] = __float_as_uint(As[(rb+r8  )*260 + ko+q4+4]);
            af[3] = __float_as_uint(As[(rb+r8+8)*260 + ko+q4+4]);
            float4 b0 = *(const float4*)&Bsf[(ko+q4  )*136 + wn*32 + r8*4];
            float4 b1 = *(const float4*)&Bsf[(ko+q4+4)*136 + wn*32 + r8*4];
            unsigned bf0[2] = {__float_as_uint(b0.x), __float_as_uint(b1.x)};
            unsigned bf1[2] = {__float_as_uint(b0.y), __float_as_uint(b1.y)};
            unsigned bf2[2] = {__float_as_uint(b0.z), __float_as_uint(b1.z)};
            unsigned bf3[2] = {__float_as_uint(b0.w), __float_as_uint(b1.w)};
            mma8(acc[0], af, bf0);
            mma8(acc[1], af, bf1);
            mma8(acc[2], af, bf2);
            mma8(acc[3], af, bf3);
        }

        bool odd = (q4 & 1);
        int m  = rb + r8 + (odd ? 8 : 0);
        #pragma unroll
        for (int nt = 0; nt < 4; nt++){
            float a0 = acc[nt][0], a1 = acc[nt][1], a2 = acc[nt][2], a3 = acc[nt][3];
            float e0 = __shfl_xor_sync(0xFFFFFFFFu, a0, 1);
            float e1 = __shfl_xor_sync(0xFFFFFFFFu, a1, 1);
            float e2 = __shfl_xor_sync(0xFFFFFFFFu, a2, 1);
            float e3 = __shfl_xor_sync(0xFFFFFFFFu, a3, 1);
            float g0 = odd ? e2 : a0;
            float g1 = odd ? e3 : a1;
            float g2 = odd ? a2 : e0;
            float g3 = odd ? a3 : e1;
            int hp = wn*8 + nt*2 + (q4 >> 1);
            const float* xr = xs + m*132 + hp;
            float gi = g0 + xr[0];
            float gf = g1 + xr[32];
            float gg = g2 + xr[64];
            float go = g3 + xr[96];
            float cv = sigf(gf)*creg[nt] + sigf(gi)*tha(gg);
            creg[nt] = cv;
            enc[((size_t)(n0+m)*T + t)*Hh + h0 + hp] = sigf(go)*tha(cv);
        }
        __syncthreads();
        if (t+1 < T) issueXS(t+1);
        CLUSTER_ARRIVE();
        CLUSTER_WAIT();
    }
}

// ---------------- conv stage 1 (merged 3 convs via blockIdx.y) ----------------
__global__ void s_k(const float* __restrict__ c1W, const float* __restrict__ c2W,
                    const float* __restrict__ c3W,
                    float* __restrict__ s3, float* __restrict__ s5, float* __restrict__ s7)
{
    int z = blockIdx.y;
    int KW = 3 + 2*z, KP = 152 + 100*z;
    const float* cW = (z==0) ? c1W : (z==1) ? c2W : c3W;
    float* s = (z==0) ? s3 : (z==1) ? s5 : s7;
    long total = (long)Bq*NFc*QLn*KP;
    long i = (long)blockIdx.x*blockDim.x + threadIdx.x;
    if (i >= total) return;
    int kk = (int)(i % KP);
    long r = i / KP;
    int q  = (int)(r % QLn); r /= QLn;
    int o  = (int)(r % NFc);
    int b  = (int)(r / NFc);
    float v = 0.f;
    if (kk < Cc*KW){
        int dd = kk / Cc, c = kk - dd*Cc;
        #pragma unroll
        for (int dq = 0; dq < 3; dq++){
            int qq = q + dq - 1;
            if (qq >= 0 && qq < QLn)
                v += cW[(((size_t)o*51 + c)*3 + dq)*KW + dd] * g_pq[((size_t)b*QLn + qq)*Cc + c];
        }
    }
    s[i] = v;
}

// ---------------- conv stage 2: k-step 32, resident-B, 3-stage A ------------
#define CASTG 4608           // 128 x 36 floats per stage
#define CONV_DSM ((3*CASTG + 50*132)*4)
__global__ __launch_bounds__(256,2) void convgemm_k(
    const float* __restrict__ sA3, const float* __restrict__ sA5, const float* __restrict__ sA7,
    const float* __restrict__ c1W, const float* __restrict__ c1b,
    const float* __restrict__ c2W, const float* __restrict__ c2b,
    const float* __restrict__ c3W, const float* __restrict__ c3b,
    const int* __restrict__ bqtok, const int* __restrict__ bdtok,
    const float* __restrict__ alpha)
{
    int z = blockIdx.z;
    const int KW = 3 + 2*z, KP = 152 + 100*z, PW = KW >> 1, OCB = z*50;
    const int nk = (KP + 31) >> 5;
    const float* sA = (z==0) ? sA3 : (z==1) ? sA5 : sA7;
    const float* cW = (z==0) ? c1W : (z==1) ? c2W : c3W;
    const float* cb = (z==0) ? c1b : (z==1) ? c2b : c3b;
    extern __shared__ float dsm[];
    float* Asm = dsm;              // 3 stages x [128][36]
    float* pdt = dsm + 3*CASTG;    // [50][132]
    __shared__ float ems[18][136];
    __shared__ float wem[8][21];
    __shared__ int qt[16], dt[128], s_any;
    int tid = threadIdx.x;
    int lane = tid & 31, warp = tid >> 5;
    int wm = warp >> 2, wn = warp & 3;
    int img = blockIdx.y, b = img / Dn;
    int m0 = blockIdx.x*128, obase = m0 >> 4;
    int r8 = lane>>2, q4 = lane&3;

    const float* Pd = &g_pdT[(size_t)img*Cc*DLn];
    int arb = tid >> 3, aoff = (tid & 7)*4;
    const float* ArowP[4];
    bool mok[4];
    #pragma unroll
    for (int u = 0; u < 4; u++){
        int r = arb + 32*u;
        mok[u] = (m0 + r) < 800;
        ArowP[u] = sA + ((size_t)b*800 + (mok[u] ? m0+r : 0))*KP;
    }

    auto issueA = [&](int kt, int buf){
        int k0 = kt*32;
        float* Ab = Asm + buf*CASTG;
        #pragma unroll
        for (int u = 0; u < 4; u++){
            int r = arb + 32*u;
            cpa16(sptr(Ab + r*36 + aoff), ArowP[u] + k0 + aoff,
                  mok[u] && (k0 + aoff) < KP);
        }
    };

    for (int ch = tid; ch < 1600; ch += 256){
        int row = ch >> 5, off = (ch & 31) * 4;
        cpa16(sptr(pdt + row*132 + off), Pd + row*128 + off, true);
    }
    issueA(0,0); CP_COMMIT();
    issueA(1,1); CP_COMMIT();

    if (tid == 0) s_any = 0;
    if (tid < 16) qt[tid] = bqtok[b*QLn + tid];
    if (tid < 128) dt[tid] = bdtok[(size_t)img*DLn + tid];
    if (tid < 8*3*KW){
        int ol = tid/(3*KW), rr = tid%(3*KW);
        int o = obase + ol;
        wem[ol][rr] = (o < NFc) ? cW[(((size_t)o*51 + 50)*3 + rr/KW)*KW + rr%KW] : 0.f;
    }
    __syncthreads();
    float al = alpha[0];
    for (int e = tid; e < 18*136; e += 256){
        int qi = e/136, dj = e%136;
        int q = qi-1, dl = dj-3;
        float v = 0.f;
        if (q >= 0 && q < QLn && dl >= 0 && dl < DLn && qt[q] == dt[dl]){ v = al; s_any = 1; }
        ems[qi][dj] = v;
    }

    float acc[4][4][4] = {};
    int buf = 0;
    for (int kt = 0; kt < nk; kt++){
        if (kt >= nk-1) CP_WAIT0(); else CP_WAIT1();
        __syncthreads();
        if (kt+2 < nk){ issueA(kt+2, buf == 0 ? 2 : buf-1); CP_COMMIT(); }
        const float* Ab2 = Asm + buf*CASTG;
        #pragma unroll
        for (int kb=0; kb<4; kb++){
            int ko = kb*8;
            int ka = kt*32 + ko + q4;
            int k2 = ka + 4;
            int dda = ka/Cc, ca = ka - dda*Cc;
            int ddb = k2/Cc, cbb = k2 - ddb*Cc;
            unsigned af[4][4], bf[4][2];
            #pragma unroll
            for (int mt=0; mt<4; mt++){
                int rb = wm*64 + mt*16;
                af[mt][0] = __float_as_uint(Ab2[(rb+r8  )*36 + ko+q4  ]);
                af[mt][1] = __float_as_uint(Ab2[(rb+r8+8)*36 + ko+q4  ]);
                af[mt][2] = __float_as_uint(Ab2[(rb+r8  )*36 + ko+q4+4]);
                af[mt][3] = __float_as_uint(Ab2[(rb+r8+8)*36 + ko+q4+4]);
            }
            #pragma unroll
            for (int nt=0; nt<4; nt++){
                int col = wn*32 + nt*8 + r8;
                int sa = col + dda - PW;
                int sb = col + ddb - PW;
                bf[nt][0] = ((unsigned)sa < 128u && ka < KP) ? __float_as_uint(pdt[ca*132 + sa]) : 0u;
                bf[nt][1] = ((unsigned)sb < 128u && k2 < KP) ? __float_as_uint(pdt[cbb*132 + sb]) : 0u;
            }
            #pragma unroll
            for (int mt=0;mt<4;mt++)
                #pragma unroll
                for (int nt=0;nt<4;nt++)
                    mma8(acc[mt][nt], af[mt], bf[nt]);
        }
        buf = (buf == 2) ? 0 : buf+1;
    }

    int any = s_any;
    #pragma unroll
    for (int mt=0;mt<4;mt++){
        int row = m0 + wm*64 + mt*16;
        if (row >= 800) continue;
        int o = row >> 4, ol = o - obase;
        float bias = cb[o];
        #pragma unroll
        for (int rr=0; rr<2; rr++){
            int q = r8 + rr*8;
            #pragma unroll
            for (int nt=0;nt<4;nt++){
                int col = wn*32 + nt*8 + q4*2;
                #pragma unroll
                for (int j=0;j<2;j++){
                    int dl = col + j;
                    float v = acc[mt][nt][rr*2 + j] + bias;
                    if (any){
                        for (int dq = 0; dq < 3; dq++)
                            for (int dd = 0; dd < KW; dd++)
                                v += wem[ol][dq*KW+dd] * ems[q+dq][dl+dd+3-PW];
                    }
                    v = fmaxf(v, 0.f);
                    g_f[(((size_t)img*150 + OCB + o)*QLn + q)*DLn + dl] = v;
                }
            }
        }
    }
}

// ---------------- 1x1 conv + maxpool + linear (tf32 mma) ----------------
#define SCORE_DSM ((3*8*264 + 152*36)*4)
__global__ __launch_bounds__(256,2) void score_k(
    const float* __restrict__ ccW, const float* __restrict__ ccb,
    const float* __restrict__ outW, const float* __restrict__ outb,
    float* __restrict__ out)
{
    extern __shared__ float dsm[];
    float* fs = dsm;               // 3 stages x [8][264]
    float* Ws = dsm + 3*8*264;     // [152][36]: Ws[k*36+m]
    __shared__ float red[32][8];
    __shared__ float part[32];
    int img = blockIdx.x, tid = threadIdx.x;
    int lane = tid & 31, warp = tid >> 5;
    int r8 = lane >> 2, q4 = lane & 3;

    for (int idx = tid; idx < 152*32; idx += 256){
        int m = idx & 31, k = idx >> 5;
        Ws[k*36 + m] = (m < MFc && k < 150) ? ccW[m*150 + k] : 0.f;
    }

    const float* fimg = &g_f[(size_t)img*150*2048];
    auto issue = [&](int kt, int pch, int buf){
        #pragma unroll
        for (int h = 0; h < 2; h++){
            int ch = tid + 256*h;
            int row = ch >> 6, off = (ch & 63)*4;
            int kr = kt*8 + row;
            cpa16(sptr(fs + buf*2112 + row*264 + off),
                  fimg + (size_t)kr*2048 + pch*256 + off, kr < 150);
        }
        CP_COMMIT();
    };

    float bb0 = (r8      < MFc) ? ccb[r8]      : 0.f;
    float bb0b= (r8+8    < MFc) ? ccb[r8+8]    : 0.f;
    float maxv[2][2] = {{-1e30f,-1e30f},{-1e30f,-1e30f}};
    __syncthreads();   // Ws ready

    for (int pch = 0; pch < 8; pch++){
        float acc[2][4][4] = {};
        if (pch) __syncthreads();
        issue(0, pch, 0);
        issue(1, pch, 1);
        int buf = 0;
        for (int kt = 0; kt < 19; kt++){
            if (kt >= 17) CP_WAIT0(); else CP_WAIT1();
            __syncthreads();
            if (kt+2 < 19) issue(kt+2, pch, buf == 0 ? 2 : buf-1);
            const float* fb2 = fs + buf*2112;
            unsigned af[2][4];
            #pragma unroll
            for (int mt=0; mt<2; mt++){
                int mb = mt*16;
                af[mt][0] = __float_as_uint(Ws[(kt*8+q4  )*36 + mb+r8]);
                af[mt][1] = __float_as_uint(Ws[(kt*8+q4  )*36 + mb+r8+8]);
                af[mt][2] = __float_as_uint(Ws[(kt*8+q4+4)*36 + mb+r8]);
                af[mt][3] = __float_as_uint(Ws[(kt*8+q4+4)*36 + mb+r8+8]);
            }
            #pragma unroll
            for (int nt=0; nt<4; nt++){
                int nb = warp*32 + nt*8;
                unsigned bf[2];
                bf[0] = __float_as_uint(fb2[(q4  )*264 + nb+r8]);
                bf[1] = __float_as_uint(fb2[(q4+4)*264 + nb+r8]);
                #pragma unroll
                for (int mt=0; mt<2; mt++)
                    mma8(acc[mt][nt], af[mt], bf);
            }
            buf = (buf == 2) ? 0 : buf+1;
        }
        #pragma unroll
        for (int mt=0; mt<2; mt++){
            float b0 = (mt==0) ? bb0  : ((16+r8 < MFc) ? ccb[16+r8] : 0.f);
            float b1 = (mt==0) ? bb0b : 0.f;
            #pragma unroll
            for (int nt=0; nt<4; nt++){
                float* cc = acc[mt][nt];
                maxv[mt][0] = fmaxf(maxv[mt][0], fmaxf(cc[0], cc[1]) + b0);
                maxv[mt][1] = fmaxf(maxv[mt][1], fmaxf(cc[2], cc[3]) + b1);
            }
        }
    }
    #pragma unroll
    for (int mt=0; mt<2; mt++)
        #pragma unroll
        for (int h=0; h<2; h++){
            float v = maxv[mt][h];
            v = fmaxf(v, __shfl_xor_sync(0xFFFFFFFFu, v, 1));
            v = fmaxf(v, __shfl_xor_sync(0xFFFFFFFFu, v, 2));
            maxv[mt][h] = v;
        }
    if (q4 == 0){
        #pragma unroll
        for (int mt=0; mt<2; mt++)
            #pragma unroll
            for (int h=0; h<2; h++)
                red[mt*16 + h*8 + r8][warp] = maxv[mt][h];
    }
    __syncthreads();
    if (tid < 32){
        float m = red[tid][0];
        #pragma unroll
        for (int w = 1; w < 8; w++) m = fmaxf(m, red[tid][w]);
        part[tid] = (tid < MFc) ? m * outW[tid] : 0.f;
    }
    __syncthreads();
    if (tid == 0){
        float sc = outb[0];
        #pragma unroll
        for (int mf = 0; mf < MFc; mf++) sc += part[mf];
        out[img] = sc;
    }
}

// ---------------- launch ----------------
extern "C" void kernel_launch(void* const* d_in, const int* in_sizes, int n_in,
                              void* d_out, int out_size)
{
    const int* bqtok = nullptr; const int* bdtok = nullptr;
    for (int i = 0; i < 4; i++){
        if (in_sizes[i] == NTQ)      bqtok = (const int*)d_in[i];
        else if (in_sizes[i] == NTD) bdtok = (const int*)d_in[i];
    }
    const float* emb    = (const float*)d_in[4];
    const float* projW  = (const float*)d_in[5];
    const float* projb  = (const float*)d_in[6];
    const float* qWih   = (const float*)d_in[7];
    const float* qWhh   = (const float*)d_in[8];
    const float* qbih   = (const float*)d_in[9];
    const float* qbhh   = (const float*)d_in[10];
    const float* dWih   = (const float*)d_in[11];
    const float* dWhh   = (const float*)d_in[12];
    const float* dbih   = (const float*)d_in[13];
    const float* dbhh   = (const float*)d_in[14];
    const float* qpW    = (const float*)d_in[15];
    const float* qpb    = (const float*)d_in[16];
    const float* dpW    = (const float*)d_in[17];
    const float* dpb    = (const float*)d_in[18];
    const float* alpha  = (const float*)d_in[19];
    const float* c1W    = (const float*)d_in[20];
    const float* c1b    = (const float*)d_in[21];
    const float* c2W    = (const float*)d_in[22];
    const float* c2b    = (const float*)d_in[23];
    const float* c3W    = (const float*)d_in[24];
    const float* c3b    = (const float*)d_in[25];
    const float* ccW    = (const float*)d_in[26];
    const float* ccb    = (const float*)d_in[27];
    const float* outW   = (const float*)d_in[28];
    const float* outb   = (const float*)d_in[29];
    float* out = (float*)d_out;

    float *pXq,*pXd,*pxgq,*pxgd,*pencq,*pencd,*ppq,*ppdT,*ps3,*ps5,*ps7,*pqb,*pdb,*pWTq,*pWTd;
    cudaGetSymbolAddress((void**)&pXq,  g_Xq);
    cudaGetSymbolAddress((void**)&pXd,  g_Xd);
    cudaGetSymbolAddress((void**)&pxgq, g_xgq);
    cudaGetSymbolAddress((void**)&pxgd, g_xgd);
    cudaGetSymbolAddress((void**)&pencq,g_encq);
    cudaGetSymbolAddress((void**)&pencd,g_encd);
    cudaGetSymbolAddress((void**)&ppq,  g_pq);
    cudaGetSymbolAddress((void**)&ppdT, g_pdT);
    cudaGetSymbolAddress((void**)&ps3,  g_s3);
    cudaGetSymbolAddress((void**)&ps5,  g_s5);
    cudaGetSymbolAddress((void**)&ps7,  g_s7);
    cudaGetSymbolAddress((void**)&pqb,  g_qb);
    cudaGetSymbolAddress((void**)&pdb,  g_db);
    cudaGetSymbolAddress((void**)&pWTq, g_WTq);
    cudaGetSymbolAddress((void**)&pWTd, g_WTd);

    cudaFuncSetAttribute(lstm_persist, cudaFuncAttributeMaxDynamicSharedMemorySize, LSTM_SMEM);
    cudaFuncSetAttribute(gemm_dual<true,false,false>, cudaFuncAttributeMaxDynamicSharedMemorySize, GEMM_DSM);
    cudaFuncSetAttribute(gemm_dual<false,false,true>, cudaFuncAttributeMaxDynamicSharedMemorySize, GEMM_DSM);
    cudaFuncSetAttribute(gemm_dual<false,true,false>, cudaFuncAttributeMaxDynamicSharedMemorySize, GEMM_DSM);
    cudaFuncSetAttribute(convgemm_k, cudaFuncAttributeMaxDynamicSharedMemorySize, CONV_DSM);
    cudaFuncSetAttribute(score_k, cudaFuncAttributeMaxDynamicSharedMemorySize, SCORE_DSM);

    bias_sum_k<<<4,256>>>(qbih,qbhh,dbih,dbhh);
    wt_k<<<dim3(10,32,2),dim3(32,8)>>>(qWih, dWih);

    // embed + proj (dual): X = emb[tok] @ projW + projb
    { GS s1{emb, bqtok, projW, projb, pXq, NTQ, Ff, 0};
      GS s2{emb, bdtok, projW, projb, pXd, NTD, Ff, 0};
      gemm_dual<true,false,false><<<dim3(3,324),256,GEMM_DSM>>>(s1,s2,4, Ff,Ff, Ff,Ff); }

    // input gates (dual, packed WT): xg = X @ Wih^T + (bih+bhh)
    { GS s1{pXq, nullptr, pWTq, pqb, pxgq, NTQ, G4, 0};
      GS s2{pXd, nullptr, pWTd, pdb, pxgd, NTD, G4, 0};
      gemm_dual<false,false,true><<<dim3(8,324),256,GEMM_DSM>>>(s1,s2,4, Ff,G4, G4,Ff); }

    // persistent LSTMs (merged: 11 clusters x 8 blocks)
    lstm_persist<<<88,256,LSTM_SMEM>>>(pxgq, qWhh, pencq, pxgd, dWhh, pencd);

    // projections (dual, 8B-async B): pq [512,50]; pdT per image
    { GS s1{pencq, nullptr, qpW, qpb, ppq,  NTQ, Cc, 0};
      GS s2{pencd, nullptr, dpW, dpb, ppdT, NTD, 0,  1};
      gemm_dual<false,true,false><<<dim3(1,324),256,GEMM_DSM>>>(s1,s2,4, Hh,Cc, Cc,Hh); }

    // conv stage 1 (merged)
    {
        long t7 = (long)Bq*NFc*QLn*352;
        s_k<<<dim3((unsigned)((t7+255)/256),3),256>>>(c1W,c2W,c3W, ps3,ps5,ps7);
    }
    // conv stage 2 (k-step 32)
    convgemm_k<<<dim3(7,BD,3),256,CONV_DSM>>>(ps3,ps5,ps7, c1W,c1b, c2W,c2b, c3W,c3b,
                                              bqtok, bdtok, alpha);

    // 1x1 conv + maxpool + linear (tf32 mma)
    score_k<<<BD,256,SCORE_DSM>>>(ccW, ccb, outW, outb, out);
}

// round 15
// speedup vs baseline: 1.1440x; 1.0128x over previous
#include <cuda_runtime.h>
#include <math.h>

// ---------------- problem constants ----------------
#define Bq  32
#define Dn  10
#define QLn 16
#define DLn 128
#define BD  320
#define Ff  300
#define Hh  256
#define G4  1024
#define Cc  50
#define NFc 50
#define MFc 20
#define NTQ (Bq*QLn)      // 512
#define NTD (BD*DLn)      // 40960

// ---------------- device scratch ----------------
__device__ float g_Xq[NTQ*Ff];
__device__ float g_Xd[(size_t)NTD*Ff];
__device__ float g_xgq[(size_t)NTQ*G4];
__device__ float g_xgd[(size_t)NTD*G4];
__device__ float g_encq[NTQ*Hh];
__device__ float g_encd[(size_t)NTD*Hh];
__device__ float g_pq[NTQ*Cc];
__device__ float g_pdT[(size_t)BD*Cc*DLn];
__device__ float g_s3[(size_t)Bq*NFc*QLn*152 + 16];
__device__ float g_s5[(size_t)Bq*NFc*QLn*252 + 16];
__device__ float g_s7[(size_t)Bq*NFc*QLn*352 + 16];
__device__ float g_f[(size_t)BD*150*QLn*DLn];
__device__ float g_qb[G4];
__device__ float g_db[G4];
__device__ float g_WTq[Ff*G4];     // Wih^T, column-permuted for packed loads
__device__ float g_WTd[Ff*G4];

__device__ __forceinline__ float tha(float x){
    float y; asm("tanh.approx.f32 %0, %1;" : "=f"(y) : "f"(x)); return y;
}
__device__ __forceinline__ float sigf(float x){ return fmaf(tha(0.5f*x), 0.5f, 0.5f); }

__device__ __forceinline__ void mma8(float* c, const unsigned* a, const unsigned* b){
    asm volatile("mma.sync.aligned.m16n8k8.row.col.f32.tf32.tf32.f32 "
        "{%0,%1,%2,%3}, {%4,%5,%6,%7}, {%8,%9}, {%0,%1,%2,%3};"
        : "+f"(c[0]),"+f"(c[1]),"+f"(c[2]),"+f"(c[3])
        : "r"(a[0]),"r"(a[1]),"r"(a[2]),"r"(a[3]), "r"(b[0]),"r"(b[1]));
}
__device__ __forceinline__ unsigned sptr(const void* p){
    return (unsigned)__cvta_generic_to_shared(p);
}
__device__ __forceinline__ void cpa16(unsigned dst, const void* src, bool pred){
    int sz = pred ? 16 : 0;
    asm volatile("cp.async.cg.shared.global [%0], [%1], 16, %2;" :: "r"(dst), "l"(src), "r"(sz));
}
__device__ __forceinline__ void cpa8(unsigned dst, const void* src, bool pred){
    int sz = pred ? 8 : 0;
    asm volatile("cp.async.ca.shared.global [%0], [%1], 8, %2;" :: "r"(dst), "l"(src), "r"(sz));
}
#define CP_COMMIT() asm volatile("cp.async.commit_group;")
#define CP_WAIT0()  asm volatile("cp.async.wait_group 0;")
#define CP_WAIT1()  asm volatile("cp.async.wait_group 1;")
#define CLUSTER_ARRIVE() asm volatile("barrier.cluster.arrive.aligned;" ::: "memory")
#define CLUSTER_WAIT()   asm volatile("barrier.cluster.wait.aligned;" ::: "memory")

// ---------------- bias precombine ----------------
__global__ void bias_sum_k(const float* __restrict__ qb1, const float* __restrict__ qb2,
                           const float* __restrict__ db1, const float* __restrict__ db2)
{
    int t = blockIdx.x*blockDim.x + threadIdx.x;
    if (t < G4){ g_qb[t] = qb1[t]+qb2[t]; g_db[t] = db1[t]+db2[t]; }
}

// ---------------- Wih transpose: smem-tiled, coalesced both sides ----------
__global__ void wt_k(const float* __restrict__ qW, const float* __restrict__ dW)
{
    __shared__ float t[32][33];
    const float* src = blockIdx.z ? dW : qW;
    float* dst = blockIdx.z ? g_WTd : g_WTq;
    int k0 = blockIdx.x*32, n0 = blockIdx.y*32;
    int tx = threadIdx.x, ty = threadIdx.y;     // block (32,8)
    #pragma unroll
    for (int dy = 0; dy < 32; dy += 8){
        int n = n0 + ty + dy, k = k0 + tx;
        t[ty+dy][tx] = (k < Ff) ? src[(size_t)n*Ff + k] : 0.f;
    }
    __syncthreads();
    #pragma unroll
    for (int dy = 0; dy < 32; dy += 8){
        int k = k0 + ty + dy;
        int n = n0 + tx;
        int np = (n & ~31) | ((n & 7)*4 + ((n >> 3) & 3));
        if (k < Ff) dst[(size_t)k*G4 + np] = t[tx][ty+dy];
    }
}

// ---------------- dual-side 3-stage pipelined tf32 GEMM, k-step 32 ----------
struct GS {
    const float* A; const int* idx; const float* Bm; const float* bias;
    float* C; int M; int ldc; int store;   // store 0: C[m*ldc+n]; 1: pdT layout
};
#define ASTG 4608            // 128 x 36 floats per stage
#define BSTG 4352            // 32 x 136 floats per stage
#define GEMM_DSM ((3*ASTG + 3*BSTG)*4)
template<bool GATHER, bool B8, bool PACKB>
__global__ __launch_bounds__(256,2) void gemm_dual(
    GS s1, GS s2, int ysplit, int lda, int ldb, int N, int K)
{
    extern __shared__ float dsm[];
    float* Asm = dsm;            // 3 x [128][36]
    float* Bsm = dsm + 3*ASTG;   // 3 x [32][136]
    int tid = threadIdx.x;
    int lane = tid & 31, warp = tid >> 5;
    int wm = warp >> 2, wn = warp & 3;
    bool side2 = ((int)blockIdx.y >= ysplit);
    const float* A_   = side2 ? s2.A    : s1.A;
    const int*   idx_ = side2 ? s2.idx  : s1.idx;
    const float* Bm_  = side2 ? s2.Bm   : s1.Bm;
    const float* bias = side2 ? s2.bias : s1.bias;
    float*       C    = side2 ? s2.C    : s1.C;
    int M    = side2 ? s2.M    : s1.M;
    int ldc  = side2 ? s2.ldc  : s1.ldc;
    int store= side2 ? s2.store: s1.store;
    int by = (int)blockIdx.y - (side2 ? ysplit : 0);
    int m0 = by*128, n0 = blockIdx.x*128;
    int nk = (K + 31) >> 5;
    int r8 = lane>>2, q4 = lane&3;

    int arb = tid >> 3, aoff = (tid & 7)*4;
    const float* ArowP[4];
    bool mok[4];
    #pragma unroll
    for (int u = 0; u < 4; u++){
        int r = arb + 32*u;
        mok[u] = (m0 + r) < M;
        long g = GATHER ? (long)idx_[m0 + (mok[u] ? r : 0)] : (long)(m0 + (mok[u] ? r : 0));
        ArowP[u] = A_ + g*(long)lda;
    }
    int brb16 = tid >> 5, boff16 = (tid & 31)*4;
    int brb8  = tid >> 6, boff8  = (tid & 63)*2;

    auto issue = [&](int kt, int buf){
        int k0 = kt*32;
        float* Ab = Asm + buf*ASTG;
        #pragma unroll
        for (int u = 0; u < 4; u++){
            int r = arb + 32*u;
            cpa16(sptr(Ab + r*36 + aoff), ArowP[u] + k0 + aoff,
                  mok[u] && (k0 + aoff) < K);
        }
        float* Bb = Bsm + buf*BSTG;
        if (B8){
            #pragma unroll
            for (int u = 0; u < 8; u++){
                int r = brb8 + 4*u;
                cpa8(sptr(Bb + r*136 + boff8),
                     Bm_ + (size_t)(k0+r)*ldb + n0 + boff8,
                     (k0+r) < K && (n0+boff8) < N);
            }
        } else {
            #pragma unroll
            for (int u = 0; u < 4; u++){
                int r = brb16 + 8*u;
                cpa16(sptr(Bb + r*136 + boff16),
                      Bm_ + (size_t)(k0+r)*ldb + n0 + boff16,
                      (k0+r) < K && (n0+boff16) < N);
            }
        }
        CP_COMMIT();
    };

    float acc[4][4][4] = {};

    issue(0,0);
    if (nk > 1) issue(1,1);

    int buf = 0;
    for (int kt = 0; kt < nk; kt++){
        if (kt >= nk-1) CP_WAIT0(); else CP_WAIT1();
        __syncthreads();
        if (kt+2 < nk) issue(kt+2, buf == 0 ? 2 : buf-1);
        const float* Ab2 = Asm + buf*ASTG;
        const float* Bb2 = Bsm + buf*BSTG;
        #pragma unroll
        for (int kb=0; kb<4; kb++){
            int ko = kb*8;
            unsigned af[4][4], bf[4][2];
            #pragma unroll
            for (int mt=0; mt<4; mt++){
                int rb = wm*64 + mt*16;
                af[mt][0] = __float_as_uint(Ab2[(rb+r8  )*36 + ko+q4  ]);
                af[mt][1] = __float_as_uint(Ab2[(rb+r8+8)*36 + ko+q4  ]);
                af[mt][2] = __float_as_uint(Ab2[(rb+r8  )*36 + ko+q4+4]);
                af[mt][3] = __float_as_uint(Ab2[(rb+r8+8)*36 + ko+q4+4]);
            }
            if (PACKB){
                float4 b0 = *(const float4*)&Bb2[(ko+q4  )*136 + wn*32 + r8*4];
                float4 b1 = *(const float4*)&Bb2[(ko+q4+4)*136 + wn*32 + r8*4];
                bf[0][0]=__float_as_uint(b0.x); bf[1][0]=__float_as_uint(b0.y);
                bf[2][0]=__float_as_uint(b0.z); bf[3][0]=__float_as_uint(b0.w);
                bf[0][1]=__float_as_uint(b1.x); bf[1][1]=__float_as_uint(b1.y);
                bf[2][1]=__float_as_uint(b1.z); bf[3][1]=__float_as_uint(b1.w);
            } else {
                #pragma unroll
                for (int nt=0; nt<4; nt++){
                    int nb = wn*32 + nt*8;
                    bf[nt][0] = __float_as_uint(Bb2[(ko+q4  )*136 + nb+r8]);
                    bf[nt][1] = __float_as_uint(Bb2[(ko+q4+4)*136 + nb+r8]);
                }
            }
            #pragma unroll
            for (int mt=0;mt<4;mt++)
                #pragma unroll
                for (int nt=0;nt<4;nt++)
                    mma8(acc[mt][nt], af[mt], bf[nt]);
        }
        buf = (buf == 2) ? 0 : buf+1;
    }

    #pragma unroll
    for (int mt=0;mt<4;mt++){
        int row = m0 + wm*64 + mt*16 + r8;
        #pragma unroll
        for (int nt=0;nt<4;nt++){
            int col = n0 + wn*32 + nt*8 + q4*2;
            const float* cc = acc[mt][nt];
            #pragma unroll
            for (int j=0;j<2;j++){
                int n = col + j;
                if (n >= N) continue;
                float bb = bias ? bias[n] : 0.f;
                float v0 = cc[j] + bb, v1 = cc[2+j] + bb;
                if (store == 0){
                    if (row < M)   C[(size_t)row*ldc + n] = v0;
                    if (row+8 < M) C[(size_t)(row+8)*ldc + n] = v1;
                } else {
                    int img = row >> 7;
                    C[((size_t)img*Cc + n)*DLn + (row & 127)] = v0;
                    C[((size_t)img*Cc + n)*DLn + ((row+8) & 127)] = v1;
                }
            }
        }
    }
}

// ---------------- persistent LSTM: packed Bs + split-As k-half overlap ------
#define LSTM_BS_W  (256*136)
#define LSTM_AS_W  (32*260)
#define LSTM_XS_W  (32*132)
#define LSTM_SMEM  ((LSTM_BS_W + LSTM_AS_W + LSTM_XS_W)*4)
__global__ __cluster_dims__(8,1,1) __launch_bounds__(256,1) void lstm_persist(
    const float* __restrict__ xgq, const float* __restrict__ Whq, float* __restrict__ encq,
    const float* __restrict__ xgd, const float* __restrict__ Whd, float* __restrict__ encd)
{
    extern __shared__ unsigned smbuf[];
    unsigned* Bs = smbuf;
    float* Bsf = (float*)Bs;
    float* As = (float*)(smbuf + LSTM_BS_W);
    float* xs = As + LSTM_AS_W;
    int tid = threadIdx.x;
    int lane = tid & 31, warp = tid >> 5;
    int r8 = lane >> 2, q4 = lane & 3;
    int wm = warp & 1, wn = warp >> 1;
    int cid = blockIdx.x >> 3, hb = blockIdx.x & 7;
    const float* xg; const float* Whh; float* enc; int T, n0;
    if (cid == 0){ xg = xgq; Whh = Whq; enc = encq; T = QLn; n0 = 0; }
    else        { xg = xgd; Whh = Whd; enc = encd; T = DLn; n0 = (cid-1)*32; }
    int h0 = hb * 32;

    for (int idx = tid; idx < 128*256; idx += 256){
        int p = idx >> 8, k = idx & 255;
        int p32 = p & 31;
        int j = (p & ~31) | (((p32 & 3) << 3) | (p32 >> 2));   // nt*8 + r8
        int r = ((j & 3) << 8) + h0 + (j >> 2);
        Bs[k*136 + p] = __float_as_uint(Whh[(size_t)r*Hh + k]);
    }

    auto issueXS = [&](int t){
        #pragma unroll
        for (int u = 0; u < 4; u++){
            int ch = tid + 256*u;
            int m  = ch >> 5;
            int g  = (ch >> 3) & 3;
            int o4 = (ch & 7) * 4;
            const float* src = xg + ((size_t)(n0+m)*T + t)*G4 + g*256 + h0 + o4;
            cpa16(sptr(xs + m*132 + g*32 + o4), src, true);
        }
        CP_COMMIT();
    };
    // k-half coalesced: 32 consecutive threads stream 512B of one m-row
    auto issueASh = [&](int t, int h){
        #pragma unroll
        for (int u = 0; u < 4; u++){
            int ch = tid + 256*u;            // 0..1023
            int m  = ch >> 5;
            int k4 = (ch & 31)*4 + h*128;
            cpa16(sptr(As + m*260 + k4), enc + ((size_t)(n0+m)*T + (t-1))*Hh + k4, true);
        }
        CP_COMMIT();
    };

    issueXS(0);
    float creg[4] = {0.f, 0.f, 0.f, 0.f};
    int rb = wm*16;
    float acc[4][4];

    for (int t = 0; t < T; t++){
        #pragma unroll
        for (int nt = 0; nt < 4; nt++){
            acc[nt][0]=0.f; acc[nt][1]=0.f; acc[nt][2]=0.f; acc[nt][3]=0.f;
        }
        int kmid;
        if (t == 0){
            for (int idx = tid; idx < 32*256; idx += 256)
                As[(idx >> 8)*260 + (idx & 255)] = 0.f;
            CP_WAIT0();            // xs(0)
            __syncthreads();
            kmid = 256;            // do whole range in first pass
        } else {
            issueASh(t, 0);
            issueASh(t, 1);
            CP_WAIT1();            // xs(t) + As first k-half
            __syncthreads();
            kmid = 128;
        }
        for (int ko = 0; ko < kmid; ko += 8){
            unsigned af[4];
            af[0] = __float_as_uint(As[(rb+r8  )*260 + ko+q4  ]);
            af[1] = __float_as_uint(As[(rb+r8+8)*260 + ko+q4  ]);
            af[2] = __float_as_uint(As[(rb+r8  )*260 + ko+q4+4]);
            af[3] = __float_as_uint(As[(rb+r8+8)*260 + ko+q4+4]);
            float4 b0 = *(const float4*)&Bsf[(ko+q4  )*136 + wn*32 + r8*4];
            float4 b1 = *(const float4*)&Bsf[(ko+q4+4)*136 + wn*32 + r8*4];
            unsigned bf0[2] = {__float_as_uint(b0.x), __float_as_uint(b1.x)};
            unsigned bf1[2] = {__float_as_uint(b0.y), __float_as_uint(b1.y)};
            unsigned bf2[2] = {__float_as_uint(b0.z), __float_as_uint(b1.z)};
            unsigned bf3[2] = {__float_as_uint(b0.w), __float_as_uint(b1.w)};
            mma8(acc[0], af, bf0);
            mma8(acc[1], af, bf1);
            mma8(acc[2], af, bf2);
            mma8(acc[3], af, bf3);
        }
        if (kmid == 128){
            CP_WAIT0();            // As second k-half
            __syncthreads();
            for (int ko = 128; ko < 256; ko += 8){
                unsigned af[4];
                af[0] = __float_as_uint(As[(rb+r8  )*260 + ko+q4  ]);
                af[1] = __float_as_uint(As[(rb+r8+8)*260 + ko+q4  ]);
                af[2] = __float_as_uint(As[(rb+r8  )*260 + ko+q4+4]);
                af[3] = __float_as_uint(As[(rb+r8+8)*260 + ko+q4+4]);
                float4 b0 = *(const float4*)&Bsf[(ko+q4  )*136 + wn*32 + r8*4];
                float4 b1 = *(const float4*)&Bsf[(ko+q4+4)*136 + wn*32 + r8*4];
                unsigned bf0[2] = {__float_as_uint(b0.x), __float_as_uint(b1.x)};
                unsigned bf1[2] = {__float_as_uint(b0.y), __float_as_uint(b1.y)};
                unsigned bf2[2] = {__float_as_uint(b0.z), __float_as_uint(b1.z)};
                unsigned bf3[2] = {__float_as_uint(b0.w), __float_as_uint(b1.w)};
                mma8(acc[0], af, bf0);
                mma8(acc[1], af, bf1);
                mma8(acc[2], af, bf2);
                mma8(acc[3], af, bf3);
            }
        }

        bool odd = (q4 & 1);
        int m  = rb + r8 + (odd ? 8 : 0);
        #pragma unroll
        for (int nt = 0; nt < 4; nt++){
            float a0 = acc[nt][0], a1 = acc[nt][1], a2 = acc[nt][2], a3 = acc[nt][3];
            float e0 = __shfl_xor_sync(0xFFFFFFFFu, a0, 1);
            float e1 = __shfl_xor_sync(0xFFFFFFFFu, a1, 1);
            float e2 = __shfl_xor_sync(0xFFFFFFFFu, a2, 1);
            float e3 = __shfl_xor_sync(0xFFFFFFFFu, a3, 1);
            float g0 = odd ? e2 : a0;
            float g1 = odd ? e3 : a1;
            float g2 = odd ? a2 : e0;
            float g3 = odd ? a3 : e1;
            int hp = wn*8 + nt*2 + (q4 >> 1);
            const float* xr = xs + m*132 + hp;
            float gi = g0 + xr[0];
            float gf = g1 + xr[32];
            float gg = g2 + xr[64];
            float go = g3 + xr[96];
            float cv = sigf(gf)*creg[nt] + sigf(gi)*tha(gg);
            creg[nt] = cv;
            enc[((size_t)(n0+m)*T + t)*Hh + h0 + hp] = sigf(go)*tha(cv);
        }
        __syncthreads();
        if (t+1 < T) issueXS(t+1);
        CLUSTER_ARRIVE();
        CLUSTER_WAIT();
    }
}

// ---------------- conv stage 1 (merged 3 convs via blockIdx.y) ----------------
__global__ void s_k(const float* __restrict__ c1W, const float* __restrict__ c2W,
                    const float* __restrict__ c3W,
                    float* __restrict__ s3, float* __restrict__ s5, float* __restrict__ s7)
{
    int z = blockIdx.y;
    int KW = 3 + 2*z, KP = 152 + 100*z;
    const float* cW = (z==0) ? c1W : (z==1) ? c2W : c3W;
    float* s = (z==0) ? s3 : (z==1) ? s5 : s7;
    long total = (long)Bq*NFc*QLn*KP;
    long i = (long)blockIdx.x*blockDim.x + threadIdx.x;
    if (i >= total) return;
    int kk = (int)(i % KP);
    long r = i / KP;
    int q  = (int)(r % QLn); r /= QLn;
    int o  = (int)(r % NFc);
    int b  = (int)(r / NFc);
    float v = 0.f;
    if (kk < Cc*KW){
        int dd = kk / Cc, c = kk - dd*Cc;
        #pragma unroll
        for (int dq = 0; dq < 3; dq++){
            int qq = q + dq - 1;
            if (qq >= 0 && qq < QLn)
                v += cW[(((size_t)o*51 + c)*3 + dq)*KW + dd] * g_pq[((size_t)b*QLn + qq)*Cc + c];
        }
    }
    s[i] = v;
}

// ---------------- conv stage 2: k-step 32, resident-B, 3-stage A ------------
#define CASTG 4608           // 128 x 36 floats per stage
#define CONV_DSM ((3*CASTG + 50*132)*4)
__global__ __launch_bounds__(256,2) void convgemm_k(
    const float* __restrict__ sA3, const float* __restrict__ sA5, const float* __restrict__ sA7,
    const float* __restrict__ c1W, const float* __restrict__ c1b,
    const float* __restrict__ c2W, const float* __restrict__ c2b,
    const float* __restrict__ c3W, const float* __restrict__ c3b,
    const int* __restrict__ bqtok, const int* __restrict__ bdtok,
    const float* __restrict__ alpha)
{
    int z = blockIdx.z;
    const int KW = 3 + 2*z, KP = 152 + 100*z, PW = KW >> 1, OCB = z*50;
    const int nk = (KP + 31) >> 5;
    const float* sA = (z==0) ? sA3 : (z==1) ? sA5 : sA7;
    const float* cW = (z==0) ? c1W : (z==1) ? c2W : c3W;
    const float* cb = (z==0) ? c1b : (z==1) ? c2b : c3b;
    extern __shared__ float dsm[];
    float* Asm = dsm;              // 3 stages x [128][36]
    float* pdt = dsm + 3*CASTG;    // [50][132]
    __shared__ float ems[18][136];
    __shared__ float wem[8][21];
    __shared__ int qt[16], dt[128], s_any;
    int tid = threadIdx.x;
    int lane = tid & 31, warp = tid >> 5;
    int wm = warp >> 2, wn = warp & 3;
    int img = blockIdx.y, b = img / Dn;
    int m0 = blockIdx.x*128, obase = m0 >> 4;
    int r8 = lane>>2, q4 = lane&3;

    const float* Pd = &g_pdT[(size_t)img*Cc*DLn];
    int arb = tid >> 3, aoff = (tid & 7)*4;
    const float* ArowP[4];
    bool mok[4];
    #pragma unroll
    for (int u = 0; u < 4; u++){
        int r = arb + 32*u;
        mok[u] = (m0 + r) < 800;
        ArowP[u] = sA + ((size_t)b*800 + (mok[u] ? m0+r : 0))*KP;
    }

    auto issueA = [&](int kt, int buf){
        int k0 = kt*32;
        float* Ab = Asm + buf*CASTG;
        #pragma unroll
        for (int u = 0; u < 4; u++){
            int r = arb + 32*u;
            cpa16(sptr(Ab + r*36 + aoff), ArowP[u] + k0 + aoff,
                  mok[u] && (k0 + aoff) < KP);
        }
    };

    for (int ch = tid; ch < 1600; ch += 256){
        int row = ch >> 5, off = (ch & 31) * 4;
        cpa16(sptr(pdt + row*132 + off), Pd + row*128 + off, true);
    }
    issueA(0,0); CP_COMMIT();
    issueA(1,1); CP_COMMIT();

    if (tid == 0) s_any = 0;
    if (tid < 16) qt[tid] = bqtok[b*QLn + tid];
    if (tid < 128) dt[tid] = bdtok[(size_t)img*DLn + tid];
    if (tid < 8*3*KW){
        int ol = tid/(3*KW), rr = tid%(3*KW);
        int o = obase + ol;
        wem[ol][rr] = (o < NFc) ? cW[(((size_t)o*51 + 50)*3 + rr/KW)*KW + rr%KW] : 0.f;
    }
    __syncthreads();
    float al = alpha[0];
    for (int e = tid; e < 18*136; e += 256){
        int qi = e/136, dj = e%136;
        int q = qi-1, dl = dj-3;
        float v = 0.f;
        if (q >= 0 && q < QLn && dl >= 0 && dl < DLn && qt[q] == dt[dl]){ v = al; s_any = 1; }
        ems[qi][dj] = v;
    }

    float acc[4][4][4] = {};
    int buf = 0;
    for (int kt = 0; kt < nk; kt++){
        if (kt >= nk-1) CP_WAIT0(); else CP_WAIT1();
        __syncthreads();
        if (kt+2 < nk){ issueA(kt+2, buf == 0 ? 2 : buf-1); CP_COMMIT(); }
        const float* Ab2 = Asm + buf*CASTG;
        #pragma unroll
        for (int kb=0; kb<4; kb++){
            int ko = kb*8;
            int ka = kt*32 + ko + q4;
            int k2 = ka + 4;
            int dda = ka/Cc, ca = ka - dda*Cc;
            int ddb = k2/Cc, cbb = k2 - ddb*Cc;
            unsigned af[4][4], bf[4][2];
            #pragma unroll
            for (int mt=0; mt<4; mt++){
                int rb = wm*64 + mt*16;
                af[mt][0] = __float_as_uint(Ab2[(rb+r8  )*36 + ko+q4  ]);
                af[mt][1] = __float_as_uint(Ab2[(rb+r8+8)*36 + ko+q4  ]);
                af[mt][2] = __float_as_uint(Ab2[(rb+r8  )*36 + ko+q4+4]);
                af[mt][3] = __float_as_uint(Ab2[(rb+r8+8)*36 + ko+q4+4]);
            }
            #pragma unroll
            for (int nt=0; nt<4; nt++){
                int col = wn*32 + nt*8 + r8;
                int sa = col + dda - PW;
                int sb = col + ddb - PW;
                bf[nt][0] = ((unsigned)sa < 128u && ka < KP) ? __float_as_uint(pdt[ca*132 + sa]) : 0u;
                bf[nt][1] = ((unsigned)sb < 128u && k2 < KP) ? __float_as_uint(pdt[cbb*132 + sb]) : 0u;
            }
            #pragma unroll
            for (int mt=0;mt<4;mt++)
                #pragma unroll
                for (int nt=0;nt<4;nt++)
                    mma8(acc[mt][nt], af[mt], bf[nt]);
        }
        buf = (buf == 2) ? 0 : buf+1;
    }

    int any = s_any;
    #pragma unroll
    for (int mt=0;mt<4;mt++){
        int row = m0 + wm*64 + mt*16;
        if (row >= 800) continue;
        int o = row >> 4, ol = o - obase;
        float bias = cb[o];
        #pragma unroll
        for (int rr=0; rr<2; rr++){
            int q = r8 + rr*8;
            #pragma unroll
            for (int nt=0;nt<4;nt++){
                int col = wn*32 + nt*8 + q4*2;
                #pragma unroll
                for (int j=0;j<2;j++){
                    int dl = col + j;
                    float v = acc[mt][nt][rr*2 + j] + bias;
                    if (any){
                        for (int dq = 0; dq < 3; dq++)
                            for (int dd = 0; dd < KW; dd++)
                                v += wem[ol][dq*KW+dd] * ems[q+dq][dl+dd+3-PW];
                    }
                    v = fmaxf(v, 0.f);
                    g_f[(((size_t)img*150 + OCB + o)*QLn + q)*DLn + dl] = v;
                }
            }
        }
    }
}

// ---------------- 1x1 conv + maxpool + linear (tf32 mma, k-step 16) ---------
#define FSTG (16*264)
#define SCORE_DSM ((3*FSTG + 160*36)*4)
__global__ __launch_bounds__(256,2) void score_k(
    const float* __restrict__ ccW, const float* __restrict__ ccb,
    const float* __restrict__ outW, const float* __restrict__ outb,
    float* __restrict__ out)
{
    extern __shared__ float dsm[];
    float* fs = dsm;               // 3 stages x [16][264]
    float* Ws = dsm + 3*FSTG;      // [160][36]: Ws[k*36+m]
    __shared__ float red[32][8];
    __shared__ float part[32];
    int img = blockIdx.x, tid = threadIdx.x;
    int lane = tid & 31, warp = tid >> 5;
    int r8 = lane >> 2, q4 = lane & 3;

    for (int idx = tid; idx < 160*32; idx += 256){
        int m = idx & 31, k = idx >> 5;
        Ws[k*36 + m] = (m < MFc && k < 150) ? ccW[m*150 + k] : 0.f;
    }

    const float* fimg = &g_f[(size_t)img*150*2048];
    auto issue = [&](int kt, int pch, int buf){
        #pragma unroll
        for (int h = 0; h < 4; h++){
            int ch = tid + 256*h;
            int row = ch >> 6, off = (ch & 63)*4;
            int kr = kt*16 + row;
            cpa16(sptr(fs + buf*FSTG + row*264 + off),
                  fimg + (size_t)kr*2048 + pch*256 + off, kr < 150);
        }
        CP_COMMIT();
    };

    float bb0 = (r8      < MFc) ? ccb[r8]      : 0.f;
    float bb0b= (r8+8    < MFc) ? ccb[r8+8]    : 0.f;
    float maxv[2][2] = {{-1e30f,-1e30f},{-1e30f,-1e30f}};
    __syncthreads();   // Ws ready

    for (int pch = 0; pch < 8; pch++){
        float acc[2][4][4] = {};
        if (pch) __syncthreads();
        issue(0, pch, 0);
        issue(1, pch, 1);
        int buf = 0;
        for (int kt = 0; kt < 10; kt++){
            if (kt >= 8) CP_WAIT0(); else CP_WAIT1();
            __syncthreads();
            if (kt+2 < 10) issue(kt+2, pch, buf == 0 ? 2 : buf-1);
            const float* fb2 = fs + buf*FSTG;
            #pragma unroll
            for (int kb = 0; kb < 2; kb++){
                int ko = kb*8;
                unsigned af[2][4];
                #pragma unroll
                for (int mt=0; mt<2; mt++){
                    int mb = mt*16;
                    int kr = kt*16 + ko;
                    af[mt][0] = __float_as_uint(Ws[(kr+q4  )*36 + mb+r8]);
                    af[mt][1] = __float_as_uint(Ws[(kr+q4  )*36 + mb+r8+8]);
                    af[mt][2] = __float_as_uint(Ws[(kr+q4+4)*36 + mb+r8]);
                    af[mt][3] = __float_as_uint(Ws[(kr+q4+4)*36 + mb+r8+8]);
                }
                #pragma unroll
                for (int nt=0; nt<4; nt++){
                    int nb = warp*32 + nt*8;
                    unsigned bf[2];
                    bf[0] = __float_as_uint(fb2[(ko+q4  )*264 + nb+r8]);
                    bf[1] = __float_as_uint(fb2[(ko+q4+4)*264 + nb+r8]);
                    #pragma unroll
                    for (int mt=0; mt<2; mt++)
                        mma8(acc[mt][nt], af[mt], bf);
                }
            }
            buf = (buf == 2) ? 0 : buf+1;
        }
        #pragma unroll
        for (int mt=0; mt<2; mt++){
            float b0 = (mt==0) ? bb0  : ((16+r8 < MFc) ? ccb[16+r8] : 0.f);
            float b1 = (mt==0) ? bb0b : 0.f;
            #pragma unroll
            for (int nt=0; nt<4; nt++){
                float* cc = acc[mt][nt];
                maxv[mt][0] = fmaxf(maxv[mt][0], fmaxf(cc[0], cc[1]) + b0);
                maxv[mt][1] = fmaxf(maxv[mt][1], fmaxf(cc[2], cc[3]) + b1);
            }
        }
    }
    #pragma unroll
    for (int mt=0; mt<2; mt++)
        #pragma unroll
        for (int h=0; h<2; h++){
            float v = maxv[mt][h];
            v = fmaxf(v, __shfl_xor_sync(0xFFFFFFFFu, v, 1));
            v = fmaxf(v, __shfl_xor_sync(0xFFFFFFFFu, v, 2));
            maxv[mt][h] = v;
        }
    if (q4 == 0){
        #pragma unroll
        for (int mt=0; mt<2; mt++)
            #pragma unroll
            for (int h=0; h<2; h++)
                red[mt*16 + h*8 + r8][warp] = maxv[mt][h];
    }
    __syncthreads();
    if (tid < 32){
        float m = red[tid][0];
        #pragma unroll
        for (int w = 1; w < 8; w++) m = fmaxf(m, red[tid][w]);
        part[tid] = (tid < MFc) ? m * outW[tid] : 0.f;
    }
    __syncthreads();
    if (tid == 0){
        float sc = outb[0];
        #pragma unroll
        for (int mf = 0; mf < MFc; mf++) sc += part[mf];
        out[img] = sc;
    }
}

// ---------------- launch ----------------
extern "C" void kernel_launch(void* const* d_in, const int* in_sizes, int n_in,
                              void* d_out, int out_size)
{
    const int* bqtok = nullptr; const int* bdtok = nullptr;
    for (int i = 0; i < 4; i++){
        if (in_sizes[i] == NTQ)      bqtok = (const int*)d_in[i];
        else if (in_sizes[i] == NTD) bdtok = (const int*)d_in[i];
    }
    const float* emb    = (const float*)d_in[4];
    const float* projW  = (const float*)d_in[5];
    const float* projb  = (const float*)d_in[6];
    const float* qWih   = (const float*)d_in[7];
    const float* qWhh   = (const float*)d_in[8];
    const float* qbih   = (const float*)d_in[9];
    const float* qbhh   = (const float*)d_in[10];
    const float* dWih   = (const float*)d_in[11];
    const float* dWhh   = (const float*)d_in[12];
    const float* dbih   = (const float*)d_in[13];
    const float* dbhh   = (const float*)d_in[14];
    const float* qpW    = (const float*)d_in[15];
    const float* qpb    = (const float*)d_in[16];
    const float* dpW    = (const float*)d_in[17];
    const float* dpb    = (const float*)d_in[18];
    const float* alpha  = (const float*)d_in[19];
    const float* c1W    = (const float*)d_in[20];
    const float* c1b    = (const float*)d_in[21];
    const float* c2W    = (const float*)d_in[22];
    const float* c2b    = (const float*)d_in[23];
    const float* c3W    = (const float*)d_in[24];
    const float* c3b    = (const float*)d_in[25];
    const float* ccW    = (const float*)d_in[26];
    const float* ccb    = (const float*)d_in[27];
    const float* outW   = (const float*)d_in[28];
    const float* outb   = (const float*)d_in[29];
    float* out = (float*)d_out;

    float *pXq,*pXd,*pxgq,*pxgd,*pencq,*pencd,*ppq,*ppdT,*ps3,*ps5,*ps7,*pqb,*pdb,*pWTq,*pWTd;
    cudaGetSymbolAddress((void**)&pXq,  g_Xq);
    cudaGetSymbolAddress((void**)&pXd,  g_Xd);
    cudaGetSymbolAddress((void**)&pxgq, g_xgq);
    cudaGetSymbolAddress((void**)&pxgd, g_xgd);
    cudaGetSymbolAddress((void**)&pencq,g_encq);
    cudaGetSymbolAddress((void**)&pencd,g_encd);
    cudaGetSymbolAddress((void**)&ppq,  g_pq);
    cudaGetSymbolAddress((void**)&ppdT, g_pdT);
    cudaGetSymbolAddress((void**)&ps3,  g_s3);
    cudaGetSymbolAddress((void**)&ps5,  g_s5);
    cudaGetSymbolAddress((void**)&ps7,  g_s7);
    cudaGetSymbolAddress((void**)&pqb,  g_qb);
    cudaGetSymbolAddress((void**)&pdb,  g_db);
    cudaGetSymbolAddress((void**)&pWTq, g_WTq);
    cudaGetSymbolAddress((void**)&pWTd, g_WTd);

    cudaFuncSetAttribute(lstm_persist, cudaFuncAttributeMaxDynamicSharedMemorySize, LSTM_SMEM);
    cudaFuncSetAttribute(gemm_dual<true,false,false>, cudaFuncAttributeMaxDynamicSharedMemorySize, GEMM_DSM);
    cudaFuncSetAttribute(gemm_dual<false,false,true>, cudaFuncAttributeMaxDynamicSharedMemorySize, GEMM_DSM);
    cudaFuncSetAttribute(gemm_dual<false,true,false>, cudaFuncAttributeMaxDynamicSharedMemorySize, GEMM_DSM);
    cudaFuncSetAttribute(convgemm_k, cudaFuncAttributeMaxDynamicSharedMemorySize, CONV_DSM);
    cudaFuncSetAttribute(score_k, cudaFuncAttributeMaxDynamicSharedMemorySize, SCORE_DSM);

    bias_sum_k<<<4,256>>>(qbih,qbhh,dbih,dbhh);
    wt_k<<<dim3(10,32,2),dim3(32,8)>>>(qWih, dWih);

    // embed + proj (dual): X = emb[tok] @ projW + projb
    { GS s1{emb, bqtok, projW, projb, pXq, NTQ, Ff, 0};
      GS s2{emb, bdtok, projW, projb, pXd, NTD, Ff, 0};
      gemm_dual<true,false,false><<<dim3(3,324),256,GEMM_DSM>>>(s1,s2,4, Ff,Ff, Ff,Ff); }

    // input gates (dual, packed WT): xg = X @ Wih^T + (bih+bhh)
    { GS s1{pXq, nullptr, pWTq, pqb, pxgq, NTQ, G4, 0};
      GS s2{pXd, nullptr, pWTd, pdb, pxgd, NTD, G4, 0};
      gemm_dual<false,false,true><<<dim3(8,324),256,GEMM_DSM>>>(s1,s2,4, Ff,G4, G4,Ff); }

    // persistent LSTMs (merged: 11 clusters x 8 blocks)
    lstm_persist<<<88,256,LSTM_SMEM>>>(pxgq, qWhh, pencq, pxgd, dWhh, pencd);

    // projections (dual, 8B-async B): pq [512,50]; pdT per image
    { GS s1{pencq, nullptr, qpW, qpb, ppq,  NTQ, Cc, 0};
      GS s2{pencd, nullptr, dpW, dpb, ppdT, NTD, 0,  1};
      gemm_dual<false,true,false><<<dim3(1,324),256,GEMM_DSM>>>(s1,s2,4, Hh,Cc, Cc,Hh); }

    // conv stage 1 (merged)
    {
        long t7 = (long)Bq*NFc*QLn*352;
        s_k<<<dim3((unsigned)((t7+255)/256),3),256>>>(c1W,c2W,c3W, ps3,ps5,ps7);
    }
    // conv stage 2 (k-step 32)
    convgemm_k<<<dim3(7,BD,3),256,CONV_DSM>>>(ps3,ps5,ps7, c1W,c1b, c2W,c2b, c3W,c3b,
                                              bqtok, bdtok, alpha);

    // 1x1 conv + maxpool + linear (tf32 mma, k-step 16)
    score_k<<<BD,256,SCORE_DSM>>>(ccW, ccb, outW, outb, out);
}

// round 16
// speedup vs baseline: 1.1797x; 1.0311x over previous
#include <cuda_runtime.h>
#include <math.h>

// ---------------- problem constants ----------------
#define Bq  32
#define Dn  10
#define QLn 16
#define DLn 128
#define BD  320
#define Ff  300
#define Hh  256
#define G4  1024
#define Cc  50
#define NFc 50
#define MFc 20
#define NTQ (Bq*QLn)      // 512
#define NTD (BD*DLn)      // 40960

// ---------------- device scratch ----------------
__device__ float g_Xq[NTQ*Ff];
__device__ float g_Xd[(size_t)NTD*Ff];
__device__ float g_xgq[(size_t)NTQ*G4];
__device__ float g_xgd[(size_t)NTD*G4];
__device__ float g_encq[NTQ*Hh];
__device__ float g_encd[(size_t)NTD*Hh];
__device__ float g_pq[NTQ*Cc];
__device__ float g_pdT[(size_t)BD*Cc*DLn];
__device__ float g_s3[(size_t)Bq*NFc*QLn*152 + 16];
__device__ float g_s5[(size_t)Bq*NFc*QLn*252 + 16];
__device__ float g_s7[(size_t)Bq*NFc*QLn*352 + 16];
__device__ float g_f[(size_t)BD*150*QLn*DLn];
__device__ float g_qb[G4];
__device__ float g_db[G4];
__device__ float g_WTq[Ff*G4];     // Wih^T, column-permuted for packed loads
__device__ float g_WTd[Ff*G4];

__device__ __forceinline__ float tha(float x){
    float y; asm("tanh.approx.f32 %0, %1;" : "=f"(y) : "f"(x)); return y;
}
__device__ __forceinline__ float sigf(float x){ return fmaf(tha(0.5f*x), 0.5f, 0.5f); }

__device__ __forceinline__ void mma8(float* c, const unsigned* a, const unsigned* b){
    asm volatile("mma.sync.aligned.m16n8k8.row.col.f32.tf32.tf32.f32 "
        "{%0,%1,%2,%3}, {%4,%5,%6,%7}, {%8,%9}, {%0,%1,%2,%3};"
        : "+f"(c[0]),"+f"(c[1]),"+f"(c[2]),"+f"(c[3])
        : "r"(a[0]),"r"(a[1]),"r"(a[2]),"r"(a[3]), "r"(b[0]),"r"(b[1]));
}
__device__ __forceinline__ unsigned sptr(const void* p){
    return (unsigned)__cvta_generic_to_shared(p);
}
__device__ __forceinline__ void cpa16(unsigned dst, const void* src, bool pred){
    int sz = pred ? 16 : 0;
    asm volatile("cp.async.cg.shared.global [%0], [%1], 16, %2;" :: "r"(dst), "l"(src), "r"(sz));
}
__device__ __forceinline__ void cpa8(unsigned dst, const void* src, bool pred){
    int sz = pred ? 8 : 0;
    asm volatile("cp.async.ca.shared.global [%0], [%1], 8, %2;" :: "r"(dst), "l"(src), "r"(sz));
}
#define CP_COMMIT() asm volatile("cp.async.commit_group;")
#define CP_WAIT0()  asm volatile("cp.async.wait_group 0;")
#define CP_WAIT1()  asm volatile("cp.async.wait_group 1;")
#define CLUSTER_ARRIVE() asm volatile("barrier.cluster.arrive.aligned;" ::: "memory")
#define CLUSTER_WAIT()   asm volatile("barrier.cluster.wait.aligned;" ::: "memory")

// ---------------- bias precombine ----------------
__global__ void bias_sum_k(const float* __restrict__ qb1, const float* __restrict__ qb2,
                           const float* __restrict__ db1, const float* __restrict__ db2)
{
    int t = blockIdx.x*blockDim.x + threadIdx.x;
    if (t < G4){ g_qb[t] = qb1[t]+qb2[t]; g_db[t] = db1[t]+db2[t]; }
}

// ---------------- Wih transpose: smem-tiled, coalesced both sides ----------
__global__ void wt_k(const float* __restrict__ qW, const float* __restrict__ dW)
{
    __shared__ float t[32][33];
    const float* src = blockIdx.z ? dW : qW;
    float* dst = blockIdx.z ? g_WTd : g_WTq;
    int k0 = blockIdx.x*32, n0 = blockIdx.y*32;
    int tx = threadIdx.x, ty = threadIdx.y;     // block (32,8)
    #pragma unroll
    for (int dy = 0; dy < 32; dy += 8){
        int n = n0 + ty + dy, k = k0 + tx;
        t[ty+dy][tx] = (k < Ff) ? src[(size_t)n*Ff + k] : 0.f;
    }
    __syncthreads();
    #pragma unroll
    for (int dy = 0; dy < 32; dy += 8){
        int k = k0 + ty + dy;
        int n = n0 + tx;
        int np = (n & ~31) | ((n & 7)*4 + ((n >> 3) & 3));
        if (k < Ff) dst[(size_t)k*G4 + np] = t[tx][ty+dy];
    }
}

// ---------------- dual-side 3-stage pipelined tf32 GEMM, k-step 32 ----------
struct GS {
    const float* A; const int* idx; const float* Bm; const float* bias;
    float* C; int M; int ldc; int store;   // store 0: C[m*ldc+n]; 1: pdT layout
};
#define ASTG 4608            // 128 x 36 floats per stage
#define BSTG 4352            // 32 x 136 floats per stage
#define GEMM_DSM ((3*ASTG + 3*BSTG)*4)
template<bool GATHER, bool B8, bool PACKB>
__global__ __launch_bounds__(256,2) void gemm_dual(
    GS s1, GS s2, int ysplit, int lda, int ldb, int N, int K)
{
    extern __shared__ float dsm[];
    float* Asm = dsm;            // 3 x [128][36]
    float* Bsm = dsm + 3*ASTG;   // 3 x [32][136]
    int tid = threadIdx.x;
    int lane = tid & 31, warp = tid >> 5;
    int wm = warp >> 2, wn = warp & 3;
    bool side2 = ((int)blockIdx.y >= ysplit);
    const float* A_   = side2 ? s2.A    : s1.A;
    const int*   idx_ = side2 ? s2.idx  : s1.idx;
    const float* Bm_  = side2 ? s2.Bm   : s1.Bm;
    const float* bias = side2 ? s2.bias : s1.bias;
    float*       C    = side2 ? s2.C    : s1.C;
    int M    = side2 ? s2.M    : s1.M;
    int ldc  = side2 ? s2.ldc  : s1.ldc;
    int store= side2 ? s2.store: s1.store;
    int by = (int)blockIdx.y - (side2 ? ysplit : 0);
    int m0 = by*128, n0 = blockIdx.x*128;
    int nk = (K + 31) >> 5;
    int r8 = lane>>2, q4 = lane&3;

    int arb = tid >> 3, aoff = (tid & 7)*4;
    const float* ArowP[4];
    bool mok[4];
    #pragma unroll
    for (int u = 0; u < 4; u++){
        int r = arb + 32*u;
        mok[u] = (m0 + r) < M;
        long g = GATHER ? (long)idx_[m0 + (mok[u] ? r : 0)] : (long)(m0 + (mok[u] ? r : 0));
        ArowP[u] = A_ + g*(long)lda;
    }
    int brb16 = tid >> 5, boff16 = (tid & 31)*4;
    int brb8  = tid >> 6, boff8  = (tid & 63)*2;

    auto issue = [&](int kt, int buf){
        int k0 = kt*32;
        float* Ab = Asm + buf*ASTG;
        #pragma unroll
        for (int u = 0; u < 4; u++){
            int r = arb + 32*u;
            cpa16(sptr(Ab + r*36 + aoff), ArowP[u] + k0 + aoff,
                  mok[u] && (k0 + aoff) < K);
        }
        float* Bb = Bsm + buf*BSTG;
        if (B8){
            #pragma unroll
            for (int u = 0; u < 8; u++){
                int r = brb8 + 4*u;
                cpa8(sptr(Bb + r*136 + boff8),
                     Bm_ + (size_t)(k0+r)*ldb + n0 + boff8,
                     (k0+r) < K && (n0+boff8) < N);
            }
        } else {
            #pragma unroll
            for (int u = 0; u < 4; u++){
                int r = brb16 + 8*u;
                cpa16(sptr(Bb + r*136 + boff16),
                      Bm_ + (size_t)(k0+r)*ldb + n0 + boff16,
                      (k0+r) < K && (n0+boff16) < N);
            }
        }
        CP_COMMIT();
    };

    float acc[4][4][4] = {};

    issue(0,0);
    if (nk > 1) issue(1,1);

    int buf = 0;
    for (int kt = 0; kt < nk; kt++){
        if (kt >= nk-1) CP_WAIT0(); else CP_WAIT1();
        __syncthreads();
        if (kt+2 < nk) issue(kt+2, buf == 0 ? 2 : buf-1);
        const float* Ab2 = Asm + buf*ASTG;
        const float* Bb2 = Bsm + buf*BSTG;
        #pragma unroll
        for (int kb=0; kb<4; kb++){
            int ko = kb*8;
            unsigned af[4][4], bf[4][2];
            #pragma unroll
            for (int mt=0; mt<4; mt++){
                int rb = wm*64 + mt*16;
                af[mt][0] = __float_as_uint(Ab2[(rb+r8  )*36 + ko+q4  ]);
                af[mt][1] = __float_as_uint(Ab2[(rb+r8+8)*36 + ko+q4  ]);
                af[mt][2] = __float_as_uint(Ab2[(rb+r8  )*36 + ko+q4+4]);
                af[mt][3] = __float_as_uint(Ab2[(rb+r8+8)*36 + ko+q4+4]);
            }
            if (PACKB){
                float4 b0 = *(const float4*)&Bb2[(ko+q4  )*136 + wn*32 + r8*4];
                float4 b1 = *(const float4*)&Bb2[(ko+q4+4)*136 + wn*32 + r8*4];
                bf[0][0]=__float_as_uint(b0.x); bf[1][0]=__float_as_uint(b0.y);
                bf[2][0]=__float_as_uint(b0.z); bf[3][0]=__float_as_uint(b0.w);
                bf[0][1]=__float_as_uint(b1.x); bf[1][1]=__float_as_uint(b1.y);
                bf[2][1]=__float_as_uint(b1.z); bf[3][1]=__float_as_uint(b1.w);
            } else {
                #pragma unroll
                for (int nt=0; nt<4; nt++){
                    int nb = wn*32 + nt*8;
                    bf[nt][0] = __float_as_uint(Bb2[(ko+q4  )*136 + nb+r8]);
                    bf[nt][1] = __float_as_uint(Bb2[(ko+q4+4)*136 + nb+r8]);
                }
            }
            #pragma unroll
            for (int mt=0;mt<4;mt++)
                #pragma unroll
                for (int nt=0;nt<4;nt++)
                    mma8(acc[mt][nt], af[mt], bf[nt]);
        }
        buf = (buf == 2) ? 0 : buf+1;
    }

    #pragma unroll
    for (int mt=0;mt<4;mt++){
        int row = m0 + wm*64 + mt*16 + r8;
        #pragma unroll
        for (int nt=0;nt<4;nt++){
            int col = n0 + wn*32 + nt*8 + q4*2;
            const float* cc = acc[mt][nt];
            #pragma unroll
            for (int j=0;j<2;j++){
                int n = col + j;
                if (n >= N) continue;
                float bb = bias ? bias[n] : 0.f;
                float v0 = cc[j] + bb, v1 = cc[2+j] + bb;
                if (store == 0){
                    if (row < M)   C[(size_t)row*ldc + n] = v0;
                    if (row+8 < M) C[(size_t)(row+8)*ldc + n] = v1;
                } else {
                    int img = row >> 7;
                    C[((size_t)img*Cc + n)*DLn + (row & 127)] = v0;
                    C[((size_t)img*Cc + n)*DLn + ((row+8) & 127)] = v1;
                }
            }
        }
    }
}

// ---------------- persistent LSTM: coalesced enc store via smem stage -------
#define LSTM_BS_W  (256*136)
#define LSTM_AS_W  (32*260)
#define LSTM_XS_W  (32*132)
#define LSTM_HS_W  (32*36)
#define LSTM_SMEM  ((LSTM_BS_W + LSTM_AS_W + LSTM_XS_W + LSTM_HS_W)*4)
__global__ __cluster_dims__(8,1,1) __launch_bounds__(256,1) void lstm_persist(
    const float* __restrict__ xgq, const float* __restrict__ Whq, float* __restrict__ encq,
    const float* __restrict__ xgd, const float* __restrict__ Whd, float* __restrict__ encd)
{
    extern __shared__ unsigned smbuf[];
    unsigned* Bs = smbuf;
    float* Bsf = (float*)Bs;
    float* As = (float*)(smbuf + LSTM_BS_W);
    float* xs = As + LSTM_AS_W;
    float* hs = xs + LSTM_XS_W;          // [32][36] h staging
    int tid = threadIdx.x;
    int lane = tid & 31, warp = tid >> 5;
    int r8 = lane >> 2, q4 = lane & 3;
    int wm = warp & 1, wn = warp >> 1;
    int cid = blockIdx.x >> 3, hb = blockIdx.x & 7;
    const float* xg; const float* Whh; float* enc; int T, n0;
    if (cid == 0){ xg = xgq; Whh = Whq; enc = encq; T = QLn; n0 = 0; }
    else        { xg = xgd; Whh = Whd; enc = encd; T = DLn; n0 = (cid-1)*32; }
    int h0 = hb * 32;

    for (int idx = tid; idx < 128*256; idx += 256){
        int p = idx >> 8, k = idx & 255;
        int p32 = p & 31;
        int j = (p & ~31) | (((p32 & 3) << 3) | (p32 >> 2));   // nt*8 + r8
        int r = ((j & 3) << 8) + h0 + (j >> 2);
        Bs[k*136 + p] = __float_as_uint(Whh[(size_t)r*Hh + k]);
    }

    auto issueXS = [&](int t){
        #pragma unroll
        for (int u = 0; u < 4; u++){
            int ch = tid + 256*u;
            int m  = ch >> 5;
            int g  = (ch >> 3) & 3;
            int o4 = (ch & 7) * 4;
            const float* src = xg + ((size_t)(n0+m)*T + t)*G4 + g*256 + h0 + o4;
            cpa16(sptr(xs + m*132 + g*32 + o4), src, true);
        }
        CP_COMMIT();
    };
    auto issueASh = [&](int t, int h){
        #pragma unroll
        for (int u = 0; u < 4; u++){
            int ch = tid + 256*u;
            int m  = ch >> 5;
            int k4 = (ch & 31)*4 + h*128;
            cpa16(sptr(As + m*260 + k4), enc + ((size_t)(n0+m)*T + (t-1))*Hh + k4, true);
        }
        CP_COMMIT();
    };

    issueXS(0);
    float creg[4] = {0.f, 0.f, 0.f, 0.f};
    int rb = wm*16;
    float acc[4][4];
    int srow = tid >> 3, soff = (tid & 7)*4;   // coalesced store map

    for (int t = 0; t < T; t++){
        #pragma unroll
        for (int nt = 0; nt < 4; nt++){
            acc[nt][0]=0.f; acc[nt][1]=0.f; acc[nt][2]=0.f; acc[nt][3]=0.f;
        }
        int kmid;
        if (t == 0){
            for (int idx = tid; idx < 32*256; idx += 256)
                As[(idx >> 8)*260 + (idx & 255)] = 0.f;
            CP_WAIT0();
            __syncthreads();
            kmid = 256;
        } else {
            issueASh(t, 0);
            issueASh(t, 1);
            CP_WAIT1();
            __syncthreads();
            kmid = 128;
        }
        for (int ko = 0; ko < kmid; ko += 8){
            unsigned af[4];
            af[0] = __float_as_uint(As[(rb+r8  )*260 + ko+q4  ]);
            af[1] = __float_as_uint(As[(rb+r8+8)*260 + ko+q4  ]);
            af[2] = __float_as_uint(As[(rb+r8  )*260 + ko+q4+4]);
            af[3] = __float_as_uint(As[(rb+r8+8)*260 + ko+q4+4]);
            float4 b0 = *(const float4*)&Bsf[(ko+q4  )*136 + wn*32 + r8*4];
            float4 b1 = *(const float4*)&Bsf[(ko+q4+4)*136 + wn*32 + r8*4];
            unsigned bf0[2] = {__float_as_uint(b0.x), __float_as_uint(b1.x)};
            unsigned bf1[2] = {__float_as_uint(b0.y), __float_as_uint(b1.y)};
            unsigned bf2[2] = {__float_as_uint(b0.z), __float_as_uint(b1.z)};
            unsigned bf3[2] = {__float_as_uint(b0.w), __float_as_uint(b1.w)};
            mma8(acc[0], af, bf0);
            mma8(acc[1], af, bf1);
            mma8(acc[2], af, bf2);
            mma8(acc[3], af, bf3);
        }
        if (kmid == 128){
            CP_WAIT0();
            __syncthreads();
            for (int ko = 128; ko < 256; ko += 8){
                unsigned af[4];
                af[0] = __float_as_uint(As[(rb+r8  )*260 + ko+q4  ]);
                af[1] = __float_as_uint(As[(rb+r8+8)*260 + ko+q4  ]);
                af[2] = __float_as_uint(As[(rb+r8  )*260 + ko+q4+4]);
                af[3] = __float_as_uint(As[(rb+r8+8)*260 + ko+q4+4]);
                float4 b0 = *(const float4*)&Bsf[(ko+q4  )*136 + wn*32 + r8*4];
                float4 b1 = *(const float4*)&Bsf[(ko+q4+4)*136 + wn*32 + r8*4];
                unsigned bf0[2] = {__float_as_uint(b0.x), __float_as_uint(b1.x)};
                unsigned bf1[2] = {__float_as_uint(b0.y), __float_as_uint(b1.y)};
                unsigned bf2[2] = {__float_as_uint(b0.z), __float_as_uint(b1.z)};
                unsigned bf3[2] = {__float_as_uint(b0.w), __float_as_uint(b1.w)};
                mma8(acc[0], af, bf0);
                mma8(acc[1], af, bf1);
                mma8(acc[2], af, bf2);
                mma8(acc[3], af, bf3);
            }
        }

        // gate epilogue -> stage h into smem (scattered STS, cheap)
        bool odd = (q4 & 1);
        int m  = rb + r8 + (odd ? 8 : 0);
        #pragma unroll
        for (int nt = 0; nt < 4; nt++){
            float a0 = acc[nt][0], a1 = acc[nt][1], a2 = acc[nt][2], a3 = acc[nt][3];
            float e0 = __shfl_xor_sync(0xFFFFFFFFu, a0, 1);
            float e1 = __shfl_xor_sync(0xFFFFFFFFu, a1, 1);
            float e2 = __shfl_xor_sync(0xFFFFFFFFu, a2, 1);
            float e3 = __shfl_xor_sync(0xFFFFFFFFu, a3, 1);
            float g0 = odd ? e2 : a0;
            float g1 = odd ? e3 : a1;
            float g2 = odd ? a2 : e0;
            float g3 = odd ? a3 : e1;
            int hp = wn*8 + nt*2 + (q4 >> 1);
            const float* xr = xs + m*132 + hp;
            float gi = g0 + xr[0];
            float gf = g1 + xr[32];
            float gg = g2 + xr[64];
            float go = g3 + xr[96];
            float cv = sigf(gf)*creg[nt] + sigf(gi)*tha(gg);
            creg[nt] = cv;
            hs[m*36 + hp] = sigf(go)*tha(cv);
        }
        __syncthreads();
        // coalesced enc store: thread -> float4 of row srow
        {
            float4 v = *(const float4*)&hs[srow*36 + soff];
            *(float4*)&enc[((size_t)(n0+srow)*T + t)*Hh + h0 + soff] = v;
        }
        CLUSTER_ARRIVE();          // release (covers this thread's STG)
        if (t+1 < T) issueXS(t+1); // local prefetch while peers arrive
        CLUSTER_WAIT();
    }
}

// ---------------- conv stage 1 (merged 3 convs via blockIdx.y) ----------------
__global__ void s_k(const float* __restrict__ c1W, const float* __restrict__ c2W,
                    const float* __restrict__ c3W,
                    float* __restrict__ s3, float* __restrict__ s5, float* __restrict__ s7)
{
    int z = blockIdx.y;
    int KW = 3 + 2*z, KP = 152 + 100*z;
    const float* cW = (z==0) ? c1W : (z==1) ? c2W : c3W;
    float* s = (z==0) ? s3 : (z==1) ? s5 : s7;
    long total = (long)Bq*NFc*QLn*KP;
    long i = (long)blockIdx.x*blockDim.x + threadIdx.x;
    if (i >= total) return;
    int kk = (int)(i % KP);
    long r = i / KP;
    int q  = (int)(r % QLn); r /= QLn;
    int o  = (int)(r % NFc);
    int b  = (int)(r / NFc);
    float v = 0.f;
    if (kk < Cc*KW){
        int dd = kk / Cc, c = kk - dd*Cc;
        #pragma unroll
        for (int dq = 0; dq < 3; dq++){
            int qq = q + dq - 1;
            if (qq >= 0 && qq < QLn)
                v += cW[(((size_t)o*51 + c)*3 + dq)*KW + dd] * g_pq[((size_t)b*QLn + qq)*Cc + c];
        }
    }
    s[i] = v;
}

// ---------------- conv stage 2: k-step 32, resident-B, 3-stage A ------------
#define CASTG 4608           // 128 x 36 floats per stage
#define CONV_DSM ((3*CASTG + 50*132)*4)
__global__ __launch_bounds__(256,2) void convgemm_k(
    const float* __restrict__ sA3, const float* __restrict__ sA5, const float* __restrict__ sA7,
    const float* __restrict__ c1W, const float* __restrict__ c1b,
    const float* __restrict__ c2W, const float* __restrict__ c2b,
    const float* __restrict__ c3W, const float* __restrict__ c3b,
    const int* __restrict__ bqtok, const int* __restrict__ bdtok,
    const float* __restrict__ alpha)
{
    int z = blockIdx.z;
    const int KW = 3 + 2*z, KP = 152 + 100*z, PW = KW >> 1, OCB = z*50;
    const int nk = (KP + 31) >> 5;
    const float* sA = (z==0) ? sA3 : (z==1) ? sA5 : sA7;
    const float* cW = (z==0) ? c1W : (z==1) ? c2W : c3W;
    const float* cb = (z==0) ? c1b : (z==1) ? c2b : c3b;
    extern __shared__ float dsm[];
    float* Asm = dsm;              // 3 stages x [128][36]
    float* pdt = dsm + 3*CASTG;    // [50][132]
    __shared__ float ems[18][136];
    __shared__ float wem[8][21];
    __shared__ int qt[16], dt[128], s_any;
    int tid = threadIdx.x;
    int lane = tid & 31, warp = tid >> 5;
    int wm = warp >> 2, wn = warp & 3;
    int img = blockIdx.y, b = img / Dn;
    int m0 = blockIdx.x*128, obase = m0 >> 4;
    int r8 = lane>>2, q4 = lane&3;

    const float* Pd = &g_pdT[(size_t)img*Cc*DLn];
    int arb = tid >> 3, aoff = (tid & 7)*4;
    const float* ArowP[4];
    bool mok[4];
    #pragma unroll
    for (int u = 0; u < 4; u++){
        int r = arb + 32*u;
        mok[u] = (m0 + r) < 800;
        ArowP[u] = sA + ((size_t)b*800 + (mok[u] ? m0+r : 0))*KP;
    }

    auto issueA = [&](int kt, int buf){
        int k0 = kt*32;
        float* Ab = Asm + buf*CASTG;
        #pragma unroll
        for (int u = 0; u < 4; u++){
            int r = arb + 32*u;
            cpa16(sptr(Ab + r*36 + aoff), ArowP[u] + k0 + aoff,
                  mok[u] && (k0 + aoff) < KP);
        }
    };

    for (int ch = tid; ch < 1600; ch += 256){
        int row = ch >> 5, off = (ch & 31) * 4;
        cpa16(sptr(pdt + row*132 + off), Pd + row*128 + off, true);
    }
    issueA(0,0); CP_COMMIT();
    issueA(1,1); CP_COMMIT();

    if (tid == 0) s_any = 0;
    if (tid < 16) qt[tid] = bqtok[b*QLn + tid];
    if (tid < 128) dt[tid] = bdtok[(size_t)img*DLn + tid];
    if (tid < 8*3*KW){
        int ol = tid/(3*KW), rr = tid%(3*KW);
        int o = obase + ol;
        wem[ol][rr] = (o < NFc) ? cW[(((size_t)o*51 + 50)*3 + rr/KW)*KW + rr%KW] : 0.f;
    }
    __syncthreads();
    float al = alpha[0];
    for (int e = tid; e < 18*136; e += 256){
        int qi = e/136, dj = e%136;
        int q = qi-1, dl = dj-3;
        float v = 0.f;
        if (q >= 0 && q < QLn && dl >= 0 && dl < DLn && qt[q] == dt[dl]){ v = al; s_any = 1; }
        ems[qi][dj] = v;
    }

    float acc[4][4][4] = {};
    int buf = 0;
    for (int kt = 0; kt < nk; kt++){
        if (kt >= nk-1) CP_WAIT0(); else CP_WAIT1();
        __syncthreads();
        if (kt+2 < nk){ issueA(kt+2, buf == 0 ? 2 : buf-1); CP_COMMIT(); }
        const float* Ab2 = Asm + buf*CASTG;
        #pragma unroll
        for (int kb=0; kb<4; kb++){
            int ko = kb*8;
            int ka = kt*32 + ko + q4;
            int k2 = ka + 4;
            int dda = ka/Cc, ca = ka - dda*Cc;
            int ddb = k2/Cc, cbb = k2 - ddb*Cc;
            unsigned af[4][4], bf[4][2];
            #pragma unroll
            for (int mt=0; mt<4; mt++){
                int rb = wm*64 + mt*16;
                af[mt][0] = __float_as_uint(Ab2[(rb+r8  )*36 + ko+q4  ]);
                af[mt][1] = __float_as_uint(Ab2[(rb+r8+8)*36 + ko+q4  ]);
                af[mt][2] = __float_as_uint(Ab2[(rb+r8  )*36 + ko+q4+4]);
                af[mt][3] = __float_as_uint(Ab2[(rb+r8+8)*36 + ko+q4+4]);
            }
            #pragma unroll
            for (int nt=0; nt<4; nt++){
                int col = wn*32 + nt*8 + r8;
                int sa = col + dda - PW;
                int sb = col + ddb - PW;
                bf[nt][0] = ((unsigned)sa < 128u && ka < KP) ? __float_as_uint(pdt[ca*132 + sa]) : 0u;
                bf[nt][1] = ((unsigned)sb < 128u && k2 < KP) ? __float_as_uint(pdt[cbb*132 + sb]) : 0u;
            }
            #pragma unroll
            for (int mt=0;mt<4;mt++)
                #pragma unroll
                for (int nt=0;nt<4;nt++)
                    mma8(acc[mt][nt], af[mt], bf[nt]);
        }
        buf = (buf == 2) ? 0 : buf+1;
    }

    int any = s_any;
    #pragma unroll
    for (int mt=0;mt<4;mt++){
        int row = m0 + wm*64 + mt*16;
        if (row >= 800) continue;
        int o = row >> 4, ol = o - obase;
        float bias = cb[o];
        #pragma unroll
        for (int rr=0; rr<2; rr++){
            int q = r8 + rr*8;
            #pragma unroll
            for (int nt=0;nt<4;nt++){
                int col = wn*32 + nt*8 + q4*2;
                #pragma unroll
                for (int j=0;j<2;j++){
                    int dl = col + j;
                    float v = acc[mt][nt][rr*2 + j] + bias;
                    if (any){
                        for (int dq = 0; dq < 3; dq++)
                            for (int dd = 0; dd < KW; dd++)
                                v += wem[ol][dq*KW+dd] * ems[q+dq][dl+dd+3-PW];
                    }
                    v = fmaxf(v, 0.f);
                    g_f[(((size_t)img*150 + OCB + o)*QLn + q)*DLn + dl] = v;
                }
            }
        }
    }
}

// ---------------- 1x1 conv + maxpool + linear (tf32 mma, k-step 16) ---------
#define FSTG (16*264)
#define SCORE_DSM ((3*FSTG + 160*36)*4)
__global__ __launch_bounds__(256,2) void score_k(
    const float* __restrict__ ccW, const float* __restrict__ ccb,
    const float* __restrict__ outW, const float* __restrict__ outb,
    float* __restrict__ out)
{
    extern __shared__ float dsm[];
    float* fs = dsm;               // 3 stages x [16][264]
    float* Ws = dsm + 3*FSTG;      // [160][36]: Ws[k*36+m]
    __shared__ float red[32][8];
    __shared__ float part[32];
    int img = blockIdx.x, tid = threadIdx.x;
    int lane = tid & 31, warp = tid >> 5;
    int r8 = lane >> 2, q4 = lane & 3;

    for (int idx = tid; idx < 160*32; idx += 256){
        int m = idx & 31, k = idx >> 5;
        Ws[k*36 + m] = (m < MFc && k < 150) ? ccW[m*150 + k] : 0.f;
    }

    const float* fimg = &g_f[(size_t)img*150*2048];
    auto issue = [&](int kt, int pch, int buf){
        #pragma unroll
        for (int h = 0; h < 4; h++){
            int ch = tid + 256*h;
            int row = ch >> 6, off = (ch & 63)*4;
            int kr = kt*16 + row;
            cpa16(sptr(fs + buf*FSTG + row*264 + off),
                  fimg + (size_t)kr*2048 + pch*256 + off, kr < 150);
        }
        CP_COMMIT();
    };

    float bb0 = (r8      < MFc) ? ccb[r8]      : 0.f;
    float bb0b= (r8+8    < MFc) ? ccb[r8+8]    : 0.f;
    float maxv[2][2] = {{-1e30f,-1e30f},{-1e30f,-1e30f}};
    __syncthreads();   // Ws ready

    for (int pch = 0; pch < 8; pch++){
        float acc[2][4][4] = {};
        if (pch) __syncthreads();
        issue(0, pch, 0);
        issue(1, pch, 1);
        int buf = 0;
        for (int kt = 0; kt < 10; kt++){
            if (kt >= 8) CP_WAIT0(); else CP_WAIT1();
            __syncthreads();
            if (kt+2 < 10) issue(kt+2, pch, buf == 0 ? 2 : buf-1);
            const float* fb2 = fs + buf*FSTG;
            #pragma unroll
            for (int kb = 0; kb < 2; kb++){
                int ko = kb*8;
                unsigned af[2][4];
                #pragma unroll
                for (int mt=0; mt<2; mt++){
                    int mb = mt*16;
                    int kr = kt*16 + ko;
                    af[mt][0] = __float_as_uint(Ws[(kr+q4  )*36 + mb+r8]);
                    af[mt][1] = __float_as_uint(Ws[(kr+q4  )*36 + mb+r8+8]);
                    af[mt][2] = __float_as_uint(Ws[(kr+q4+4)*36 + mb+r8]);
                    af[mt][3] = __float_as_uint(Ws[(kr+q4+4)*36 + mb+r8+8]);
                }
                #pragma unroll
                for (int nt=0; nt<4; nt++){
                    int nb = warp*32 + nt*8;
                    unsigned bf[2];
                    bf[0] = __float_as_uint(fb2[(ko+q4  )*264 + nb+r8]);
                    bf[1] = __float_as_uint(fb2[(ko+q4+4)*264 + nb+r8]);
                    #pragma unroll
                    for (int mt=0; mt<2; mt++)
                        mma8(acc[mt][nt], af[mt], bf);
                }
            }
            buf = (buf == 2) ? 0 : buf+1;
        }
        #pragma unroll
        for (int mt=0; mt<2; mt++){
            float b0 = (mt==0) ? bb0  : ((16+r8 < MFc) ? ccb[16+r8] : 0.f);
            float b1 = (mt==0) ? bb0b : 0.f;
            #pragma unroll
            for (int nt=0; nt<4; nt++){
                float* cc = acc[mt][nt];
                maxv[mt][0] = fmaxf(maxv[mt][0], fmaxf(cc[0], cc[1]) + b0);
                maxv[mt][1] = fmaxf(maxv[mt][1], fmaxf(cc[2], cc[3]) + b1);
            }
        }
    }
    #pragma unroll
    for (int mt=0; mt<2; mt++)
        #pragma unroll
        for (int h=0; h<2; h++){
            float v = maxv[mt][h];
            v = fmaxf(v, __shfl_xor_sync(0xFFFFFFFFu, v, 1));
            v = fmaxf(v, __shfl_xor_sync(0xFFFFFFFFu, v, 2));
            maxv[mt][h] = v;
        }
    if (q4 == 0){
        #pragma unroll
        for (int mt=0; mt<2; mt++)
            #pragma unroll
            for (int h=0; h<2; h++)
                red[mt*16 + h*8 + r8][warp] = maxv[mt][h];
    }
    __syncthreads();
    if (tid < 32){
        float m = red[tid][0];
        #pragma unroll
        for (int w = 1; w < 8; w++) m = fmaxf(m, red[tid][w]);
        part[tid] = (tid < MFc) ? m * outW[tid] : 0.f;
    }
    __syncthreads();
    if (tid == 0){
        float sc = outb[0];
        #pragma unroll
        for (int mf = 0; mf < MFc; mf++) sc += part[mf];
        out[img] = sc;
    }
}

// ---------------- launch ----------------
extern "C" void kernel_launch(void* const* d_in, const int* in_sizes, int n_in,
                              void* d_out, int out_size)
{
    const int* bqtok = nullptr; const int* bdtok = nullptr;
    for (int i = 0; i < 4; i++){
        if (in_sizes[i] == NTQ)      bqtok = (const int*)d_in[i];
        else if (in_sizes[i] == NTD) bdtok = (const int*)d_in[i];
    }
    const float* emb    = (const float*)d_in[4];
    const float* projW  = (const float*)d_in[5];
    const float* projb  = (const float*)d_in[6];
    const float* qWih   = (const float*)d_in[7];
    const float* qWhh   = (const float*)d_in[8];
    const float* qbih   = (const float*)d_in[9];
    const float* qbhh   = (const float*)d_in[10];
    const float* dWih   = (const float*)d_in[11];
    const float* dWhh   = (const float*)d_in[12];
    const float* dbih   = (const float*)d_in[13];
    const float* dbhh   = (const float*)d_in[14];
    const float* qpW    = (const float*)d_in[15];
    const float* qpb    = (const float*)d_in[16];
    const float* dpW    = (const float*)d_in[17];
    const float* dpb    = (const float*)d_in[18];
    const float* alpha  = (const float*)d_in[19];
    const float* c1W    = (const float*)d_in[20];
    const float* c1b    = (const float*)d_in[21];
    const float* c2W    = (const float*)d_in[22];
    const float* c2b    = (const float*)d_in[23];
    const float* c3W    = (const float*)d_in[24];
    const float* c3b    = (const float*)d_in[25];
    const float* ccW    = (const float*)d_in[26];
    const float* ccb    = (const float*)d_in[27];
    const float* outW   = (const float*)d_in[28];
    const float* outb   = (const float*)d_in[29];
    float* out = (float*)d_out;

    float *pXq,*pXd,*pxgq,*pxgd,*pencq,*pencd,*ppq,*ppdT,*ps3,*ps5,*ps7,*pqb,*pdb,*pWTq,*pWTd;
    cudaGetSymbolAddress((void**)&pXq,  g_Xq);
    cudaGetSymbolAddress((void**)&pXd,  g_Xd);
    cudaGetSymbolAddress((void**)&pxgq, g_xgq);
    cudaGetSymbolAddress((void**)&pxgd, g_xgd);
    cudaGetSymbolAddress((void**)&pencq,g_encq);
    cudaGetSymbolAddress((void**)&pencd,g_encd);
    cudaGetSymbolAddress((void**)&ppq,  g_pq);
    cudaGetSymbolAddress((void**)&ppdT, g_pdT);
    cudaGetSymbolAddress((void**)&ps3,  g_s3);
    cudaGetSymbolAddress((void**)&ps5,  g_s5);
    cudaGetSymbolAddress((void**)&ps7,  g_s7);
    cudaGetSymbolAddress((void**)&pqb,  g_qb);
    cudaGetSymbolAddress((void**)&pdb,  g_db);
    cudaGetSymbolAddress((void**)&pWTq, g_WTq);
    cudaGetSymbolAddress((void**)&pWTd, g_WTd);

    cudaFuncSetAttribute(lstm_persist, cudaFuncAttributeMaxDynamicSharedMemorySize, LSTM_SMEM);
    cudaFuncSetAttribute(gemm_dual<true,false,false>, cudaFuncAttributeMaxDynamicSharedMemorySize, GEMM_DSM);
    cudaFuncSetAttribute(gemm_dual<false,false,true>, cudaFuncAttributeMaxDynamicSharedMemorySize, GEMM_DSM);
    cudaFuncSetAttribute(gemm_dual<false,true,false>, cudaFuncAttributeMaxDynamicSharedMemorySize, GEMM_DSM);
    cudaFuncSetAttribute(convgemm_k, cudaFuncAttributeMaxDynamicSharedMemorySize, CONV_DSM);
    cudaFuncSetAttribute(score_k, cudaFuncAttributeMaxDynamicSharedMemorySize, SCORE_DSM);

    bias_sum_k<<<4,256>>>(qbih,qbhh,dbih,dbhh);
    wt_k<<<dim3(10,32,2),dim3(32,8)>>>(qWih, dWih);

    // embed + proj (dual): X = emb[tok] @ projW + projb
    { GS s1{emb, bqtok, projW, projb, pXq, NTQ, Ff, 0};
      GS s2{emb, bdtok, projW, projb, pXd, NTD, Ff, 0};
      gemm_dual<true,false,false><<<dim3(3,324),256,GEMM_DSM>>>(s1,s2,4, Ff,Ff, Ff,Ff); }

    // input gates (dual, packed WT): xg = X @ Wih^T + (bih+bhh)
    { GS s1{pXq, nullptr, pWTq, pqb, pxgq, NTQ, G4, 0};
      GS s2{pXd, nullptr, pWTd, pdb, pxgd, NTD, G4, 0};
      gemm_dual<false,false,true><<<dim3(8,324),256,GEMM_DSM>>>(s1,s2,4, Ff,G4, G4,Ff); }

    // persistent LSTMs (merged: 11 clusters x 8 blocks)
    lstm_persist<<<88,256,LSTM_SMEM>>>(pxgq, qWhh, pencq, pxgd, dWhh, pencd);

    // projections (dual, 8B-async B): pq [512,50]; pdT per image
    { GS s1{pencq, nullptr, qpW, qpb, ppq,  NTQ, Cc, 0};
      GS s2{pencd, nullptr, dpW, dpb, ppdT, NTD, 0,  1};
      gemm_dual<false,true,false><<<dim3(1,324),256,GEMM_DSM>>>(s1,s2,4, Hh,Cc, Cc,Hh); }

    // conv stage 1 (merged)
    {
        long t7 = (long)Bq*NFc*QLn*352;
        s_k<<<dim3((unsigned)((t7+255)/256),3),256>>>(c1W,c2W,c3W, ps3,ps5,ps7);
    }
    // conv stage 2 (k-step 32)
    convgemm_k<<<dim3(7,BD,3),256,CONV_DSM>>>(ps3,ps5,ps7, c1W,c1b, c2W,c2b, c3W,c3b,
                                              bqtok, bdtok, alpha);

    // 1x1 conv + maxpool + linear (tf32 mma, k-step 16)
    score_k<<<BD,256,SCORE_DSM>>>(ccW, ccb, outW, outb, out);
}

// round 17
// speedup vs baseline: 1.1992x; 1.0165x over previous
#include <cuda_runtime.h>
#include <math.h>

// ---------------- problem constants ----------------
#define Bq  32
#define Dn  10
#define QLn 16
#define DLn 128
#define BD  320
#define Ff  300
#define Hh  256
#define G4  1024
#define Cc  50
#define NFc 50
#define MFc 20
#define NTQ (Bq*QLn)      // 512
#define NTD (BD*DLn)      // 40960

// ---------------- device scratch ----------------
__device__ float g_Xq[NTQ*Ff];
__device__ float g_Xd[(size_t)NTD*Ff];
__device__ float g_xgq[(size_t)NTQ*G4];
__device__ float g_xgd[(size_t)NTD*G4];
__device__ float g_encq[NTQ*Hh];
__device__ float g_encd[(size_t)NTD*Hh];
__device__ float g_pq[NTQ*Cc];
__device__ float g_pdT[(size_t)BD*Cc*DLn];
__device__ float g_s3[(size_t)Bq*NFc*QLn*152 + 16];
__device__ float g_s5[(size_t)Bq*NFc*QLn*252 + 16];
__device__ float g_s7[(size_t)Bq*NFc*QLn*352 + 16];
__device__ float g_f[(size_t)BD*150*QLn*DLn];
__device__ float g_qb[G4];
__device__ float g_db[G4];
__device__ float g_WTq[Ff*G4];     // Wih^T, column-permuted for packed loads
__device__ float g_WTd[Ff*G4];

__device__ __forceinline__ float tha(float x){
    float y; asm("tanh.approx.f32 %0, %1;" : "=f"(y) : "f"(x)); return y;
}
__device__ __forceinline__ float sigf(float x){ return fmaf(tha(0.5f*x), 0.5f, 0.5f); }

__device__ __forceinline__ void mma8(float* c, const unsigned* a, const unsigned* b){
    asm volatile("mma.sync.aligned.m16n8k8.row.col.f32.tf32.tf32.f32 "
        "{%0,%1,%2,%3}, {%4,%5,%6,%7}, {%8,%9}, {%0,%1,%2,%3};"
        : "+f"(c[0]),"+f"(c[1]),"+f"(c[2]),"+f"(c[3])
        : "r"(a[0]),"r"(a[1]),"r"(a[2]),"r"(a[3]), "r"(b[0]),"r"(b[1]));
}
__device__ __forceinline__ unsigned sptr(const void* p){
    return (unsigned)__cvta_generic_to_shared(p);
}
__device__ __forceinline__ void cpa16(unsigned dst, const void* src, bool pred){
    int sz = pred ? 16 : 0;
    asm volatile("cp.async.cg.shared.global [%0], [%1], 16, %2;" :: "r"(dst), "l"(src), "r"(sz));
}
__device__ __forceinline__ void cpa8(unsigned dst, const void* src, bool pred){
    int sz = pred ? 8 : 0;
    asm volatile("cp.async.ca.shared.global [%0], [%1], 8, %2;" :: "r"(dst), "l"(src), "r"(sz));
}
#define CP_COMMIT() asm volatile("cp.async.commit_group;")
#define CP_WAIT0()  asm volatile("cp.async.wait_group 0;")
#define CP_WAIT1()  asm volatile("cp.async.wait_group 1;")
#define CLUSTER_ARRIVE() asm volatile("barrier.cluster.arrive.aligned;" ::: "memory")
#define CLUSTER_WAIT()   asm volatile("barrier.cluster.wait.aligned;" ::: "memory")

// ---------------- bias precombine ----------------
__global__ void bias_sum_k(const float* __restrict__ qb1, const float* __restrict__ qb2,
                           const float* __restrict__ db1, const float* __restrict__ db2)
{
    int t = blockIdx.x*blockDim.x + threadIdx.x;
    if (t < G4){ g_qb[t] = qb1[t]+qb2[t]; g_db[t] = db1[t]+db2[t]; }
}

// ---------------- Wih transpose: smem-tiled, coalesced both sides ----------
__global__ void wt_k(const float* __restrict__ qW, const float* __restrict__ dW)
{
    __shared__ float t[32][33];
    const float* src = blockIdx.z ? dW : qW;
    float* dst = blockIdx.z ? g_WTd : g_WTq;
    int k0 = blockIdx.x*32, n0 = blockIdx.y*32;
    int tx = threadIdx.x, ty = threadIdx.y;     // block (32,8)
    #pragma unroll
    for (int dy = 0; dy < 32; dy += 8){
        int n = n0 + ty + dy, k = k0 + tx;
        t[ty+dy][tx] = (k < Ff) ? src[(size_t)n*Ff + k] : 0.f;
    }
    __syncthreads();
    #pragma unroll
    for (int dy = 0; dy < 32; dy += 8){
        int k = k0 + ty + dy;
        int n = n0 + tx;
        int np = (n & ~31) | ((n & 7)*4 + ((n >> 3) & 3));
        if (k < Ff) dst[(size_t)k*G4 + np] = t[tx][ty+dy];
    }
}

// ---------------- dual-side 3-stage pipelined tf32 GEMM, k-step 32 ----------
struct GS {
    const float* A; const int* idx; const float* Bm; const float* bias;
    float* C; int M; int ldc; int store;   // store 0: C[m*ldc+n]; 1: pdT layout
};
#define ASTG 4608            // 128 x 36 floats per stage
#define BSTG 4352            // 32 x 136 floats per stage
#define GEMM_DSM ((3*ASTG + 3*BSTG)*4)
template<bool GATHER, bool B8, bool PACKB>
__global__ __launch_bounds__(256,2) void gemm_dual(
    GS s1, GS s2, int ysplit, int lda, int ldb, int N, int K)
{
    extern __shared__ float dsm[];
    float* Asm = dsm;            // 3 x [128][36]
    float* Bsm = dsm + 3*ASTG;   // 3 x [32][136]
    int tid = threadIdx.x;
    int lane = tid & 31, warp = tid >> 5;
    int wm = warp >> 2, wn = warp & 3;
    bool side2 = ((int)blockIdx.y >= ysplit);
    const float* A_   = side2 ? s2.A    : s1.A;
    const int*   idx_ = side2 ? s2.idx  : s1.idx;
    const float* Bm_  = side2 ? s2.Bm   : s1.Bm;
    const float* bias = side2 ? s2.bias : s1.bias;
    float*       C    = side2 ? s2.C    : s1.C;
    int M    = side2 ? s2.M    : s1.M;
    int ldc  = side2 ? s2.ldc  : s1.ldc;
    int store= side2 ? s2.store: s1.store;
    int by = (int)blockIdx.y - (side2 ? ysplit : 0);
    int m0 = by*128, n0 = blockIdx.x*128;
    int nk = (K + 31) >> 5;
    int r8 = lane>>2, q4 = lane&3;

    int arb = tid >> 3, aoff = (tid & 7)*4;
    const float* ArowP[4];
    bool mok[4];
    #pragma unroll
    for (int u = 0; u < 4; u++){
        int r = arb + 32*u;
        mok[u] = (m0 + r) < M;
        long g = GATHER ? (long)idx_[m0 + (mok[u] ? r : 0)] : (long)(m0 + (mok[u] ? r : 0));
        ArowP[u] = A_ + g*(long)lda;
    }
    int brb16 = tid >> 5, boff16 = (tid & 31)*4;
    int brb8  = tid >> 6, boff8  = (tid & 63)*2;

    auto issue = [&](int kt, int buf){
        int k0 = kt*32;
        float* Ab = Asm + buf*ASTG;
        #pragma unroll
        for (int u = 0; u < 4; u++){
            int r = arb + 32*u;
            cpa16(sptr(Ab + r*36 + aoff), ArowP[u] + k0 + aoff,
                  mok[u] && (k0 + aoff) < K);
        }
        float* Bb = Bsm + buf*BSTG;
        if (B8){
            #pragma unroll
            for (int u = 0; u < 8; u++){
                int r = brb8 + 4*u;
                cpa8(sptr(Bb + r*136 + boff8),
                     Bm_ + (size_t)(k0+r)*ldb + n0 + boff8,
                     (k0+r) < K && (n0+boff8) < N);
            }
        } else {
            #pragma unroll
            for (int u = 0; u < 4; u++){
                int r = brb16 + 8*u;
                cpa16(sptr(Bb + r*136 + boff16),
                      Bm_ + (size_t)(k0+r)*ldb + n0 + boff16,
                      (k0+r) < K && (n0+boff16) < N);
            }
        }
        CP_COMMIT();
    };

    float acc[4][4][4] = {};

    issue(0,0);
    if (nk > 1) issue(1,1);

    int buf = 0;
    for (int kt = 0; kt < nk; kt++){
        if (kt >= nk-1) CP_WAIT0(); else CP_WAIT1();
        __syncthreads();
        if (kt+2 < nk) issue(kt+2, buf == 0 ? 2 : buf-1);
        const float* Ab2 = Asm + buf*ASTG;
        const float* Bb2 = Bsm + buf*BSTG;
        #pragma unroll
        for (int kb=0; kb<4; kb++){
            int ko = kb*8;
            unsigned af[4][4], bf[4][2];
            #pragma unroll
            for (int mt=0; mt<4; mt++){
                int rb = wm*64 + mt*16;
                af[mt][0] = __float_as_uint(Ab2[(rb+r8  )*36 + ko+q4  ]);
                af[mt][1] = __float_as_uint(Ab2[(rb+r8+8)*36 + ko+q4  ]);
                af[mt][2] = __float_as_uint(Ab2[(rb+r8  )*36 + ko+q4+4]);
                af[mt][3] = __float_as_uint(Ab2[(rb+r8+8)*36 + ko+q4+4]);
            }
            if (PACKB){
                float4 b0 = *(const float4*)&Bb2[(ko+q4  )*136 + wn*32 + r8*4];
                float4 b1 = *(const float4*)&Bb2[(ko+q4+4)*136 + wn*32 + r8*4];
                bf[0][0]=__float_as_uint(b0.x); bf[1][0]=__float_as_uint(b0.y);
                bf[2][0]=__float_as_uint(b0.z); bf[3][0]=__float_as_uint(b0.w);
                bf[0][1]=__float_as_uint(b1.x); bf[1][1]=__float_as_uint(b1.y);
                bf[2][1]=__float_as_uint(b1.z); bf[3][1]=__float_as_uint(b1.w);
            } else {
                #pragma unroll
                for (int nt=0; nt<4; nt++){
                    int nb = wn*32 + nt*8;
                    bf[nt][0] = __float_as_uint(Bb2[(ko+q4  )*136 + nb+r8]);
                    bf[nt][1] = __float_as_uint(Bb2[(ko+q4+4)*136 + nb+r8]);
                }
            }
            #pragma unroll
            for (int mt=0;mt<4;mt++)
                #pragma unroll
                for (int nt=0;nt<4;nt++)
                    mma8(acc[mt][nt], af[mt], bf[nt]);
        }
        buf = (buf == 2) ? 0 : buf+1;
    }

    #pragma unroll
    for (int mt=0;mt<4;mt++){
        int row = m0 + wm*64 + mt*16 + r8;
        #pragma unroll
        for (int nt=0;nt<4;nt++){
            int col = n0 + wn*32 + nt*8 + q4*2;
            const float* cc = acc[mt][nt];
            #pragma unroll
            for (int j=0;j<2;j++){
                int n = col + j;
                if (n >= N) continue;
                float bb = bias ? bias[n] : 0.f;
                float v0 = cc[j] + bb, v1 = cc[2+j] + bb;
                if (store == 0){
                    if (row < M)   C[(size_t)row*ldc + n] = v0;
                    if (row+8 < M) C[(size_t)(row+8)*ldc + n] = v1;
                } else {
                    int img = row >> 7;
                    C[((size_t)img*Cc + n)*DLn + (row & 127)] = v0;
                    C[((size_t)img*Cc + n)*DLn + ((row+8) & 127)] = v1;
                }
            }
        }
    }
}

// ---------------- persistent LSTM: coalesced enc store via smem stage -------
#define LSTM_BS_W  (256*136)
#define LSTM_AS_W  (32*260)
#define LSTM_XS_W  (32*132)
#define LSTM_HS_W  (32*36)
#define LSTM_SMEM  ((LSTM_BS_W + LSTM_AS_W + LSTM_XS_W + LSTM_HS_W)*4)
__global__ __cluster_dims__(8,1,1) __launch_bounds__(256,1) void lstm_persist(
    const float* __restrict__ xgq, const float* __restrict__ Whq, float* __restrict__ encq,
    const float* __restrict__ xgd, const float* __restrict__ Whd, float* __restrict__ encd)
{
    extern __shared__ unsigned smbuf[];
    unsigned* Bs = smbuf;
    float* Bsf = (float*)Bs;
    float* As = (float*)(smbuf + LSTM_BS_W);
    float* xs = As + LSTM_AS_W;
    float* hs = xs + LSTM_XS_W;          // [32][36] h staging
    int tid = threadIdx.x;
    int lane = tid & 31, warp = tid >> 5;
    int r8 = lane >> 2, q4 = lane & 3;
    int wm = warp & 1, wn = warp >> 1;
    int cid = blockIdx.x >> 3, hb = blockIdx.x & 7;
    const float* xg; const float* Whh; float* enc; int T, n0;
    if (cid == 0){ xg = xgq; Whh = Whq; enc = encq; T = QLn; n0 = 0; }
    else        { xg = xgd; Whh = Whd; enc = encd; T = DLn; n0 = (cid-1)*32; }
    int h0 = hb * 32;

    for (int idx = tid; idx < 128*256; idx += 256){
        int p = idx >> 8, k = idx & 255;
        int p32 = p & 31;
        int j = (p & ~31) | (((p32 & 3) << 3) | (p32 >> 2));   // nt*8 + r8
        int r = ((j & 3) << 8) + h0 + (j >> 2);
        Bs[k*136 + p] = __float_as_uint(Whh[(size_t)r*Hh + k]);
    }

    auto issueXS = [&](int t){
        #pragma unroll
        for (int u = 0; u < 4; u++){
            int ch = tid + 256*u;
            int m  = ch >> 5;
            int g  = (ch >> 3) & 3;
            int o4 = (ch & 7) * 4;
            const float* src = xg + ((size_t)(n0+m)*T + t)*G4 + g*256 + h0 + o4;
            cpa16(sptr(xs + m*132 + g*32 + o4), src, true);
        }
        CP_COMMIT();
    };
    auto issueASh = [&](int t, int h){
        #pragma unroll
        for (int u = 0; u < 4; u++){
            int ch = tid + 256*u;
            int m  = ch >> 5;
            int k4 = (ch & 31)*4 + h*128;
            cpa16(sptr(As + m*260 + k4), enc + ((size_t)(n0+m)*T + (t-1))*Hh + k4, true);
        }
        CP_COMMIT();
    };

    issueXS(0);
    float creg[4] = {0.f, 0.f, 0.f, 0.f};
    int rb = wm*16;
    float acc[4][4];
    int srow = tid >> 3, soff = (tid & 7)*4;   // coalesced store map

    for (int t = 0; t < T; t++){
        #pragma unroll
        for (int nt = 0; nt < 4; nt++){
            acc[nt][0]=0.f; acc[nt][1]=0.f; acc[nt][2]=0.f; acc[nt][3]=0.f;
        }
        int kmid;
        if (t == 0){
            for (int idx = tid; idx < 32*256; idx += 256)
                As[(idx >> 8)*260 + (idx & 255)] = 0.f;
            CP_WAIT0();
            __syncthreads();
            kmid = 256;
        } else {
            issueASh(t, 0);
            issueASh(t, 1);
            CP_WAIT1();
            __syncthreads();
            kmid = 128;
        }
        for (int ko = 0; ko < kmid; ko += 8){
            unsigned af[4];
            af[0] = __float_as_uint(As[(rb+r8  )*260 + ko+q4  ]);
            af[1] = __float_as_uint(As[(rb+r8+8)*260 + ko+q4  ]);
            af[2] = __float_as_uint(As[(rb+r8  )*260 + ko+q4+4]);
            af[3] = __float_as_uint(As[(rb+r8+8)*260 + ko+q4+4]);
            float4 b0 = *(const float4*)&Bsf[(ko+q4  )*136 + wn*32 + r8*4];
            float4 b1 = *(const float4*)&Bsf[(ko+q4+4)*136 + wn*32 + r8*4];
            unsigned bf0[2] = {__float_as_uint(b0.x), __float_as_uint(b1.x)};
            unsigned bf1[2] = {__float_as_uint(b0.y), __float_as_uint(b1.y)};
            unsigned bf2[2] = {__float_as_uint(b0.z), __float_as_uint(b1.z)};
            unsigned bf3[2] = {__float_as_uint(b0.w), __float_as_uint(b1.w)};
            mma8(acc[0], af, bf0);
            mma8(acc[1], af, bf1);
            mma8(acc[2], af, bf2);
            mma8(acc[3], af, bf3);
        }
        if (kmid == 128){
            CP_WAIT0();
            __syncthreads();
            for (int ko = 128; ko < 256; ko += 8){
                unsigned af[4];
                af[0] = __float_as_uint(As[(rb+r8  )*260 + ko+q4  ]);
                af[1] = __float_as_uint(As[(rb+r8+8)*260 + ko+q4  ]);
                af[2] = __float_as_uint(As[(rb+r8  )*260 + ko+q4+4]);
                af[3] = __float_as_uint(As[(rb+r8+8)*260 + ko+q4+4]);
                float4 b0 = *(const float4*)&Bsf[(ko+q4  )*136 + wn*32 + r8*4];
                float4 b1 = *(const float4*)&Bsf[(ko+q4+4)*136 + wn*32 + r8*4];
                unsigned bf0[2] = {__float_as_uint(b0.x), __float_as_uint(b1.x)};
                unsigned bf1[2] = {__float_as_uint(b0.y), __float_as_uint(b1.y)};
                unsigned bf2[2] = {__float_as_uint(b0.z), __float_as_uint(b1.z)};
                unsigned bf3[2] = {__float_as_uint(b0.w), __float_as_uint(b1.w)};
                mma8(acc[0], af, bf0);
                mma8(acc[1], af, bf1);
                mma8(acc[2], af, bf2);
                mma8(acc[3], af, bf3);
            }
        }

        bool odd = (q4 & 1);
        int m  = rb + r8 + (odd ? 8 : 0);
        #pragma unroll
        for (int nt = 0; nt < 4; nt++){
            float a0 = acc[nt][0], a1 = acc[nt][1], a2 = acc[nt][2], a3 = acc[nt][3];
            float e0 = __shfl_xor_sync(0xFFFFFFFFu, a0, 1);
            float e1 = __shfl_xor_sync(0xFFFFFFFFu, a1, 1);
            float e2 = __shfl_xor_sync(0xFFFFFFFFu, a2, 1);
            float e3 = __shfl_xor_sync(0xFFFFFFFFu, a3, 1);
            float g0 = odd ? e2 : a0;
            float g1 = odd ? e3 : a1;
            float g2 = odd ? a2 : e0;
            float g3 = odd ? a3 : e1;
            int hp = wn*8 + nt*2 + (q4 >> 1);
            const float* xr = xs + m*132 + hp;
            float gi = g0 + xr[0];
            float gf = g1 + xr[32];
            float gg = g2 + xr[64];
            float go = g3 + xr[96];
            float cv = sigf(gf)*creg[nt] + sigf(gi)*tha(gg);
            creg[nt] = cv;
            hs[m*36 + hp] = sigf(go)*tha(cv);
        }
        __syncthreads();
        {
            float4 v = *(const float4*)&hs[srow*36 + soff];
            *(float4*)&enc[((size_t)(n0+srow)*T + t)*Hh + h0 + soff] = v;
        }
        CLUSTER_ARRIVE();
        if (t+1 < T) issueXS(t+1);
        CLUSTER_WAIT();
    }
}

// ---------------- conv stage 1 (merged 3 convs via blockIdx.y) ----------------
__global__ void s_k(const float* __restrict__ c1W, const float* __restrict__ c2W,
                    const float* __restrict__ c3W,
                    float* __restrict__ s3, float* __restrict__ s5, float* __restrict__ s7)
{
    int z = blockIdx.y;
    int KW = 3 + 2*z, KP = 152 + 100*z;
    const float* cW = (z==0) ? c1W : (z==1) ? c2W : c3W;
    float* s = (z==0) ? s3 : (z==1) ? s5 : s7;
    long total = (long)Bq*NFc*QLn*KP;
    long i = (long)blockIdx.x*blockDim.x + threadIdx.x;
    if (i >= total) return;
    int kk = (int)(i % KP);
    long r = i / KP;
    int q  = (int)(r % QLn); r /= QLn;
    int o  = (int)(r % NFc);
    int b  = (int)(r / NFc);
    float v = 0.f;
    if (kk < Cc*KW){
        int dd = kk / Cc, c = kk - dd*Cc;
        #pragma unroll
        for (int dq = 0; dq < 3; dq++){
            int qq = q + dq - 1;
            if (qq >= 0 && qq < QLn)
                v += cW[(((size_t)o*51 + c)*3 + dq)*KW + dd] * g_pq[((size_t)b*QLn + qq)*Cc + c];
        }
    }
    s[i] = v;
}

// ---------------- conv stage 2: k-step 32, z interleaved in grid.x ----------
#define CASTG 4608           // 128 x 36 floats per stage
#define CONV_DSM ((3*CASTG + 50*132)*4)
__global__ __launch_bounds__(256,2) void convgemm_k(
    const float* __restrict__ sA3, const float* __restrict__ sA5, const float* __restrict__ sA7,
    const float* __restrict__ c1W, const float* __restrict__ c1b,
    const float* __restrict__ c2W, const float* __restrict__ c2b,
    const float* __restrict__ c3W, const float* __restrict__ c3b,
    const int* __restrict__ bqtok, const int* __restrict__ bdtok,
    const float* __restrict__ alpha)
{
    int z  = (int)blockIdx.x % 3;          // interleave long/short blocks
    int xm = (int)blockIdx.x / 3;
    const int KW = 3 + 2*z, KP = 152 + 100*z, PW = KW >> 1, OCB = z*50;
    const int nk = (KP + 31) >> 5;
    const float* sA = (z==0) ? sA3 : (z==1) ? sA5 : sA7;
    const float* cW = (z==0) ? c1W : (z==1) ? c2W : c3W;
    const float* cb = (z==0) ? c1b : (z==1) ? c2b : c3b;
    extern __shared__ float dsm[];
    float* Asm = dsm;              // 3 stages x [128][36]
    float* pdt = dsm + 3*CASTG;    // [50][132]
    __shared__ float ems[18][136];
    __shared__ float wem[8][21];
    __shared__ int qt[16], dt[128], s_any;
    int tid = threadIdx.x;
    int lane = tid & 31, warp = tid >> 5;
    int wm = warp >> 2, wn = warp & 3;
    int img = blockIdx.y, b = img / Dn;
    int m0 = xm*128, obase = m0 >> 4;
    int r8 = lane>>2, q4 = lane&3;

    const float* Pd = &g_pdT[(size_t)img*Cc*DLn];
    int arb = tid >> 3, aoff = (tid & 7)*4;
    const float* ArowP[4];
    bool mok[4];
    #pragma unroll
    for (int u = 0; u < 4; u++){
        int r = arb + 32*u;
        mok[u] = (m0 + r) < 800;
        ArowP[u] = sA + ((size_t)b*800 + (mok[u] ? m0+r : 0))*KP;
    }

    auto issueA = [&](int kt, int buf){
        int k0 = kt*32;
        float* Ab = Asm + buf*CASTG;
        #pragma unroll
        for (int u = 0; u < 4; u++){
            int r = arb + 32*u;
            cpa16(sptr(Ab + r*36 + aoff), ArowP[u] + k0 + aoff,
                  mok[u] && (k0 + aoff) < KP);
        }
    };

    for (int ch = tid; ch < 1600; ch += 256){
        int row = ch >> 5, off = (ch & 31) * 4;
        cpa16(sptr(pdt + row*132 + off), Pd + row*128 + off, true);
    }
    issueA(0,0); CP_COMMIT();
    issueA(1,1); CP_COMMIT();

    if (tid == 0) s_any = 0;
    if (tid < 16) qt[tid] = bqtok[b*QLn + tid];
    if (tid < 128) dt[tid] = bdtok[(size_t)img*DLn + tid];
    if (tid < 8*3*KW){
        int ol = tid/(3*KW), rr = tid%(3*KW);
        int o = obase + ol;
        wem[ol][rr] = (o < NFc) ? cW[(((size_t)o*51 + 50)*3 + rr/KW)*KW + rr%KW] : 0.f;
    }
    __syncthreads();
    float al = alpha[0];
    for (int e = tid; e < 18*136; e += 256){
        int qi = e/136, dj = e%136;
        int q = qi-1, dl = dj-3;
        float v = 0.f;
        if (q >= 0 && q < QLn && dl >= 0 && dl < DLn && qt[q] == dt[dl]){ v = al; s_any = 1; }
        ems[qi][dj] = v;
    }

    float acc[4][4][4] = {};
    int buf = 0;
    for (int kt = 0; kt < nk; kt++){
        if (kt >= nk-1) CP_WAIT0(); else CP_WAIT1();
        __syncthreads();
        if (kt+2 < nk){ issueA(kt+2, buf == 0 ? 2 : buf-1); CP_COMMIT(); }
        const float* Ab2 = Asm + buf*CASTG;
        #pragma unroll
        for (int kb=0; kb<4; kb++){
            int ko = kb*8;
            int ka = kt*32 + ko + q4;
            int k2 = ka + 4;
            int dda = ka/Cc, ca = ka - dda*Cc;
            int ddb = k2/Cc, cbb = k2 - ddb*Cc;
            unsigned af[4][4], bf[4][2];
            #pragma unroll
            for (int mt=0; mt<4; mt++){
                int rb = wm*64 + mt*16;
                af[mt][0] = __float_as_uint(Ab2[(rb+r8  )*36 + ko+q4  ]);
                af[mt][1] = __float_as_uint(Ab2[(rb+r8+8)*36 + ko+q4  ]);
                af[mt][2] = __float_as_uint(Ab2[(rb+r8  )*36 + ko+q4+4]);
                af[mt][3] = __float_as_uint(Ab2[(rb+r8+8)*36 + ko+q4+4]);
            }
            #pragma unroll
            for (int nt=0; nt<4; nt++){
                int col = wn*32 + nt*8 + r8;
                int sa = col + dda - PW;
                int sb = col + ddb - PW;
                bf[nt][0] = ((unsigned)sa < 128u && ka < KP) ? __float_as_uint(pdt[ca*132 + sa]) : 0u;
                bf[nt][1] = ((unsigned)sb < 128u && k2 < KP) ? __float_as_uint(pdt[cbb*132 + sb]) : 0u;
            }
            #pragma unroll
            for (int mt=0;mt<4;mt++)
                #pragma unroll
                for (int nt=0;nt<4;nt++)
                    mma8(acc[mt][nt], af[mt], bf[nt]);
        }
        buf = (buf == 2) ? 0 : buf+1;
    }

    int any = s_any;
    #pragma unroll
    for (int mt=0;mt<4;mt++){
        int row = m0 + wm*64 + mt*16;
        if (row >= 800) continue;
        int o = row >> 4, ol = o - obase;
        float bias = cb[o];
        #pragma unroll
        for (int rr=0; rr<2; rr++){
            int q = r8 + rr*8;
            #pragma unroll
            for (int nt=0;nt<4;nt++){
                int col = wn*32 + nt*8 + q4*2;
                #pragma unroll
                for (int j=0;j<2;j++){
                    int dl = col + j;
                    float v = acc[mt][nt][rr*2 + j] + bias;
                    if (any){
                        for (int dq = 0; dq < 3; dq++)
                            for (int dd = 0; dd < KW; dd++)
                                v += wem[ol][dq*KW+dd] * ems[q+dq][dl+dd+3-PW];
                    }
                    v = fmaxf(v, 0.f);
                    g_f[(((size_t)img*150 + OCB + o)*QLn + q)*DLn + dl] = v;
                }
            }
        }
    }
}

// ---------------- 1x1 conv + maxpool + linear (tf32 mma, 3 blocks/SM) -------
#define FSTG (16*264)
#define SCORE_DSM ((3*FSTG + 160*36)*4)
__global__ __launch_bounds__(256,3) void score_k(
    const float* __restrict__ ccW, const float* __restrict__ ccb,
    const float* __restrict__ outW, const float* __restrict__ outb,
    float* __restrict__ out)
{
    extern __shared__ float dsm[];
    float* fs = dsm;               // 3 stages x [16][264]
    float* Ws = dsm + 3*FSTG;      // [160][36]: Ws[k*36+m]
    __shared__ float red[32][8];
    __shared__ float part[32];
    int img = blockIdx.x, tid = threadIdx.x;
    int lane = tid & 31, warp = tid >> 5;
    int r8 = lane >> 2, q4 = lane & 3;

    for (int idx = tid; idx < 160*32; idx += 256){
        int m = idx & 31, k = idx >> 5;
        Ws[k*36 + m] = (m < MFc && k < 150) ? ccW[m*150 + k] : 0.f;
    }

    const float* fimg = &g_f[(size_t)img*150*2048];
    auto issue = [&](int kt, int pch, int buf){
        #pragma unroll
        for (int h = 0; h < 4; h++){
            int ch = tid + 256*h;
            int row = ch >> 6, off = (ch & 63)*4;
            int kr = kt*16 + row;
            cpa16(sptr(fs + buf*FSTG + row*264 + off),
                  fimg + (size_t)kr*2048 + pch*256 + off, kr < 150);
        }
        CP_COMMIT();
    };

    float bb0 = (r8      < MFc) ? ccb[r8]      : 0.f;
    float bb0b= (r8+8    < MFc) ? ccb[r8+8]    : 0.f;
    float maxv[2][2] = {{-1e30f,-1e30f},{-1e30f,-1e30f}};
    __syncthreads();   // Ws ready

    for (int pch = 0; pch < 8; pch++){
        float acc[2][4][4] = {};
        if (pch) __syncthreads();
        issue(0, pch, 0);
        issue(1, pch, 1);
        int buf = 0;
        for (int kt = 0; kt < 10; kt++){
            if (kt >= 8) CP_WAIT0(); else CP_WAIT1();
            __syncthreads();
            if (kt+2 < 10) issue(kt+2, pch, buf == 0 ? 2 : buf-1);
            const float* fb2 = fs + buf*FSTG;
            #pragma unroll
            for (int kb = 0; kb < 2; kb++){
                int ko = kb*8;
                unsigned af[2][4];
                #pragma unroll
                for (int mt=0; mt<2; mt++){
                    int mb = mt*16;
                    int kr = kt*16 + ko;
                    af[mt][0] = __float_as_uint(Ws[(kr+q4  )*36 + mb+r8]);
                    af[mt][1] = __float_as_uint(Ws[(kr+q4  )*36 + mb+r8+8]);
                    af[mt][2] = __float_as_uint(Ws[(kr+q4+4)*36 + mb+r8]);
                    af[mt][3] = __float_as_uint(Ws[(kr+q4+4)*36 + mb+r8+8]);
                }
                #pragma unroll
                for (int nt=0; nt<4; nt++){
                    int nb = warp*32 + nt*8;
                    unsigned bf[2];
                    bf[0] = __float_as_uint(fb2[(ko+q4  )*264 + nb+r8]);
                    bf[1] = __float_as_uint(fb2[(ko+q4+4)*264 + nb+r8]);
                    #pragma unroll
                    for (int mt=0; mt<2; mt++)
                        mma8(acc[mt][nt], af[mt], bf);
                }
            }
            buf = (buf == 2) ? 0 : buf+1;
        }
        #pragma unroll
        for (int mt=0; mt<2; mt++){
            float b0 = (mt==0) ? bb0  : ((16+r8 < MFc) ? ccb[16+r8] : 0.f);
            float b1 = (mt==0) ? bb0b : 0.f;
            #pragma unroll
            for (int nt=0; nt<4; nt++){
                float* cc = acc[mt][nt];
                maxv[mt][0] = fmaxf(maxv[mt][0], fmaxf(cc[0], cc[1]) + b0);
                maxv[mt][1] = fmaxf(maxv[mt][1], fmaxf(cc[2], cc[3]) + b1);
            }
        }
    }
    #pragma unroll
    for (int mt=0; mt<2; mt++)
        #pragma unroll
        for (int h=0; h<2; h++){
            float v = maxv[mt][h];
            v = fmaxf(v, __shfl_xor_sync(0xFFFFFFFFu, v, 1));
            v = fmaxf(v, __shfl_xor_sync(0xFFFFFFFFu, v, 2));
            maxv[mt][h] = v;
        }
    if (q4 == 0){
        #pragma unroll
        for (int mt=0; mt<2; mt++)
            #pragma unroll
            for (int h=0; h<2; h++)
                red[mt*16 + h*8 + r8][warp] = maxv[mt][h];
    }
    __syncthreads();
    if (tid < 32){
        float m = red[tid][0];
        #pragma unroll
        for (int w = 1; w < 8; w++) m = fmaxf(m, red[tid][w]);
        part[tid] = (tid < MFc) ? m * outW[tid] : 0.f;
    }
    __syncthreads();
    if (tid == 0){
        float sc = outb[0];
        #pragma unroll
        for (int mf = 0; mf < MFc; mf++) sc += part[mf];
        out[img] = sc;
    }
}

// ---------------- launch ----------------
extern "C" void kernel_launch(void* const* d_in, const int* in_sizes, int n_in,
                              void* d_out, int out_size)
{
    const int* bqtok = nullptr; const int* bdtok = nullptr;
    for (int i = 0; i < 4; i++){
        if (in_sizes[i] == NTQ)      bqtok = (const int*)d_in[i];
        else if (in_sizes[i] == NTD) bdtok = (const int*)d_in[i];
    }
    const float* emb    = (const float*)d_in[4];
    const float* projW  = (const float*)d_in[5];
    const float* projb  = (const float*)d_in[6];
    const float* qWih   = (const float*)d_in[7];
    const float* qWhh   = (const float*)d_in[8];
    const float* qbih   = (const float*)d_in[9];
    const float* qbhh   = (const float*)d_in[10];
    const float* dWih   = (const float*)d_in[11];
    const float* dWhh   = (const float*)d_in[12];
    const float* dbih   = (const float*)d_in[13];
    const float* dbhh   = (const float*)d_in[14];
    const float* qpW    = (const float*)d_in[15];
    const float* qpb    = (const float*)d_in[16];
    const float* dpW    = (const float*)d_in[17];
    const float* dpb    = (const float*)d_in[18];
    const float* alpha  = (const float*)d_in[19];
    const float* c1W    = (const float*)d_in[20];
    const float* c1b    = (const float*)d_in[21];
    const float* c2W    = (const float*)d_in[22];
    const float* c2b    = (const float*)d_in[23];
    const float* c3W    = (const float*)d_in[24];
    const float* c3b    = (const float*)d_in[25];
    const float* ccW    = (const float*)d_in[26];
    const float* ccb    = (const float*)d_in[27];
    const float* outW   = (const float*)d_in[28];
    const float* outb   = (const float*)d_in[29];
    float* out = (float*)d_out;

    float *pXq,*pXd,*pxgq,*pxgd,*pencq,*pencd,*ppq,*ppdT,*ps3,*ps5,*ps7,*pqb,*pdb,*pWTq,*pWTd;
    cudaGetSymbolAddress((void**)&pXq,  g_Xq);
    cudaGetSymbolAddress((void**)&pXd,  g_Xd);
    cudaGetSymbolAddress((void**)&pxgq, g_xgq);
    cudaGetSymbolAddress((void**)&pxgd, g_xgd);
    cudaGetSymbolAddress((void**)&pencq,g_encq);
    cudaGetSymbolAddress((void**)&pencd,g_encd);
    cudaGetSymbolAddress((void**)&ppq,  g_pq);
    cudaGetSymbolAddress((void**)&ppdT, g_pdT);
    cudaGetSymbolAddress((void**)&ps3,  g_s3);
    cudaGetSymbolAddress((void**)&ps5,  g_s5);
    cudaGetSymbolAddress((void**)&ps7,  g_s7);
    cudaGetSymbolAddress((void**)&pqb,  g_qb);
    cudaGetSymbolAddress((void**)&pdb,  g_db);
    cudaGetSymbolAddress((void**)&pWTq, g_WTq);
    cudaGetSymbolAddress((void**)&pWTd, g_WTd);

    cudaFuncSetAttribute(lstm_persist, cudaFuncAttributeMaxDynamicSharedMemorySize, LSTM_SMEM);
    cudaFuncSetAttribute(gemm_dual<true,false,false>, cudaFuncAttributeMaxDynamicSharedMemorySize, GEMM_DSM);
    cudaFuncSetAttribute(gemm_dual<false,false,true>, cudaFuncAttributeMaxDynamicSharedMemorySize, GEMM_DSM);
    cudaFuncSetAttribute(gemm_dual<false,true,false>, cudaFuncAttributeMaxDynamicSharedMemorySize, GEMM_DSM);
    cudaFuncSetAttribute(convgemm_k, cudaFuncAttributeMaxDynamicSharedMemorySize, CONV_DSM);
    cudaFuncSetAttribute(score_k, cudaFuncAttributeMaxDynamicSharedMemorySize, SCORE_DSM);

    bias_sum_k<<<4,256>>>(qbih,qbhh,dbih,dbhh);
    wt_k<<<dim3(10,32,2),dim3(32,8)>>>(qWih, dWih);

    // embed + proj (dual): X = emb[tok] @ projW + projb
    { GS s1{emb, bqtok, projW, projb, pXq, NTQ, Ff, 0};
      GS s2{emb, bdtok, projW, projb, pXd, NTD, Ff, 0};
      gemm_dual<true,false,false><<<dim3(3,324),256,GEMM_DSM>>>(s1,s2,4, Ff,Ff, Ff,Ff); }

    // input gates (dual, packed WT): xg = X @ Wih^T + (bih+bhh)
    { GS s1{pXq, nullptr, pWTq, pqb, pxgq, NTQ, G4, 0};
      GS s2{pXd, nullptr, pWTd, pdb, pxgd, NTD, G4, 0};
      gemm_dual<false,false,true><<<dim3(8,324),256,GEMM_DSM>>>(s1,s2,4, Ff,G4, G4,Ff); }

    // persistent LSTMs (merged: 11 clusters x 8 blocks)
    lstm_persist<<<88,256,LSTM_SMEM>>>(pxgq, qWhh, pencq, pxgd, dWhh, pencd);

    // projections (dual, 8B-async B): pq [512,50]; pdT per image
    { GS s1{pencq, nullptr, qpW, qpb, ppq,  NTQ, Cc, 0};
      GS s2{pencd, nullptr, dpW, dpb, ppdT, NTD, 0,  1};
      gemm_dual<false,true,false><<<dim3(1,324),256,GEMM_DSM>>>(s1,s2,4, Hh,Cc, Cc,Hh); }

    // conv stage 1 (merged)
    {
        long t7 = (long)Bq*NFc*QLn*352;
        s_k<<<dim3((unsigned)((t7+255)/256),3),256>>>(c1W,c2W,c3W, ps3,ps5,ps7);
    }
    // conv stage 2 (k-step 32, z interleaved for wave balance)
    convgemm_k<<<dim3(21,BD),256,CONV_DSM>>>(ps3,ps5,ps7, c1W,c1b, c2W,c2b, c3W,c3b,
                                             bqtok, bdtok, alpha);

    // 1x1 conv + maxpool + linear (tf32 mma, single wave)
    score_k<<<BD,256,SCORE_DSM>>>(ccW, ccb, outW, outb, out);
}